// round 1
// baseline (speedup 1.0000x reference)
#include <cuda_runtime.h>
#include <math.h>

#define TSEQ 2048
#define NB   2
#define CDIM 768
#define NH   12
#define HDIM 64
#define DFF  3072
#define ROWS (NB * TSEQ)   // 4096

// ---------------- scratch (device globals: allocation-free) ----------------
__device__ float g_ln [ROWS * CDIM];       // 12.6 MB
__device__ float g_qkv[ROWS * 3 * CDIM];   // 37.7 MB
__device__ float g_att[ROWS * CDIM];       // 12.6 MB
__device__ float g_x1 [ROWS * CDIM];       // 12.6 MB
__device__ float g_h  [ROWS * DFF];        // 50.3 MB

__device__ __forceinline__ float gelu_f(float v) {
    return 0.5f * v * (1.0f + erff(v * 0.70710678118654752f));
}

// ---------------- LayerNorm: one block (256 thr) per row of 768 ------------
__global__ __launch_bounds__(256) void ln_k(const float* __restrict__ xin,
                                            const float* __restrict__ g,
                                            const float* __restrict__ b,
                                            float* __restrict__ out) {
    int row = blockIdx.x;
    int tid = threadIdx.x;
    const float* xr = xin + (size_t)row * CDIM;

    float v0 = xr[tid], v1 = xr[tid + 256], v2 = xr[tid + 512];
    float s  = v0 + v1 + v2;
    float ss = v0 * v0 + v1 * v1 + v2 * v2;

    #pragma unroll
    for (int off = 16; off > 0; off >>= 1) {
        s  += __shfl_xor_sync(0xffffffffu, s,  off);
        ss += __shfl_xor_sync(0xffffffffu, ss, off);
    }
    __shared__ float sh_s[8], sh_ss[8];
    int wid = tid >> 5, lane = tid & 31;
    if (lane == 0) { sh_s[wid] = s; sh_ss[wid] = ss; }
    __syncthreads();
    float ts = 0.f, tss = 0.f;
    #pragma unroll
    for (int i = 0; i < 8; ++i) { ts += sh_s[i]; tss += sh_ss[i]; }

    const float inv = 1.0f / (float)CDIM;
    float mu   = ts * inv;
    float var  = tss * inv - mu * mu;
    float rstd = rsqrtf(var + 1e-5f);

    float* orow = out + (size_t)row * CDIM;
    orow[tid      ] = (v0 - mu) * rstd * g[tid      ] + b[tid      ];
    orow[tid + 256] = (v1 - mu) * rstd * g[tid + 256] + b[tid + 256];
    orow[tid + 512] = (v2 - mu) * rstd * g[tid + 512] + b[tid + 512];
}

// ---------------- GEMM: C[M,N] = A[M,K] @ B[K,N] (+epilogue) ---------------
// 128x128 tile, BK=8, 256 threads, 8x8 per thread as 2x2 of 4x4 sub-tiles.
// EPI: 0 = none, 1 = +res, 2 = +bias then exact GELU, 3 = +bias +res
#define BM 128
#define BN 128
#define BK 8

template <int EPI>
__global__ __launch_bounds__(256, 2) void gemm_k(const float* __restrict__ A,
                                                 const float* __restrict__ Bm,
                                                 const float* __restrict__ bias,
                                                 const float* __restrict__ res,
                                                 float* __restrict__ C,
                                                 int M, int N, int K) {
    __shared__ float As[BK][BM];   // A tile, transposed
    __shared__ float Bs[BK][BN];

    int tid = threadIdx.x;
    int bm  = blockIdx.y * BM;
    int bn  = blockIdx.x * BN;

    // global->smem load mapping
    int arow  = tid >> 1;           // 0..127
    int acol4 = (tid & 1) * 4;      // 0 / 4
    int brow  = tid >> 5;           // 0..7
    int bcol4 = (tid & 31) * 4;     // 0..124

    const float* Aptr = A  + (size_t)(bm + arow) * K + acol4;
    const float* Bptr = Bm + (size_t)brow * N + bn + bcol4;

    int tx = tid & 15, ty = tid >> 4;

    float acc[8][8];
    #pragma unroll
    for (int i = 0; i < 8; ++i)
        #pragma unroll
        for (int j = 0; j < 8; ++j) acc[i][j] = 0.f;

    float4 a_ld = *(const float4*)Aptr;
    float4 b_ld = *(const float4*)Bptr;

    int ntiles = K / BK;
    for (int t = 0; t < ntiles; ++t) {
        As[acol4 + 0][arow] = a_ld.x;
        As[acol4 + 1][arow] = a_ld.y;
        As[acol4 + 2][arow] = a_ld.z;
        As[acol4 + 3][arow] = a_ld.w;
        *(float4*)&Bs[brow][bcol4] = b_ld;
        __syncthreads();

        if (t + 1 < ntiles) {
            a_ld = *(const float4*)(Aptr + (t + 1) * BK);
            b_ld = *(const float4*)(Bptr + (size_t)(t + 1) * BK * N);
        }

        #pragma unroll
        for (int k = 0; k < BK; ++k) {
            float ar[8], br[8];
            *(float4*)&ar[0] = *(const float4*)&As[k][ty * 4];
            *(float4*)&ar[4] = *(const float4*)&As[k][64 + ty * 4];
            *(float4*)&br[0] = *(const float4*)&Bs[k][tx * 4];
            *(float4*)&br[4] = *(const float4*)&Bs[k][64 + tx * 4];
            #pragma unroll
            for (int i = 0; i < 8; ++i)
                #pragma unroll
                for (int j = 0; j < 8; ++j)
                    acc[i][j] += ar[i] * br[j];
        }
        __syncthreads();
    }

    // epilogue
    #pragma unroll
    for (int ig = 0; ig < 2; ++ig) {
        #pragma unroll
        for (int ii = 0; ii < 4; ++ii) {
            int ai = ig * 4 + ii;
            int r  = bm + ig * 64 + ty * 4 + ii;
            #pragma unroll
            for (int jg = 0; jg < 2; ++jg) {
                int c = bn + jg * 64 + tx * 4;
                float4 o4;
                float vv[4];
                #pragma unroll
                for (int j = 0; j < 4; ++j) {
                    float tv = acc[ai][jg * 4 + j];
                    if (EPI == 2 || EPI == 3) tv += bias[c + j];
                    if (EPI == 2)             tv  = gelu_f(tv);
                    if (EPI == 1 || EPI == 3) tv += res[(size_t)r * N + c + j];
                    vv[j] = tv;
                }
                o4.x = vv[0]; o4.y = vv[1]; o4.z = vv[2]; o4.w = vv[3];
                *(float4*)(C + (size_t)r * N + c) = o4;
            }
        }
    }
}

// ---------------- Causal flash attention: 1 warp per query row -------------
// qkv layout per row: [q(768) | k(768) | v(768)], head h at offset h*64.
__global__ __launch_bounds__(128) void attn_k(const float* __restrict__ qkv,
                                              float* __restrict__ y) {
    int bh   = blockIdx.y;            // 0..23
    int b    = bh / NH;
    int h    = bh % NH;
    int qbase = blockIdx.x * 4;
    int warp = threadIdx.x >> 5;
    int lane = threadIdx.x & 31;
    int q    = qbase + warp;

    __shared__ float Kt[HDIM][33];    // transposed K tile (32 keys)
    __shared__ float Vt[HDIM][33];

    const float* base = qkv + (size_t)b * TSEQ * (3 * CDIM);

    // whole q row in registers (all lanes identical -> broadcast loads)
    float qreg[HDIM];
    {
        const float* qp = base + (size_t)q * (3 * CDIM) + h * HDIM;
        #pragma unroll
        for (int d4 = 0; d4 < 16; ++d4) {
            float4 v = *(const float4*)(qp + d4 * 4);
            qreg[d4 * 4 + 0] = v.x; qreg[d4 * 4 + 1] = v.y;
            qreg[d4 * 4 + 2] = v.z; qreg[d4 * 4 + 3] = v.w;
        }
    }

    float o[HDIM];
    #pragma unroll
    for (int d = 0; d < HDIM; ++d) o[d] = 0.f;
    float m_run = -1e30f, l_run = 0.f;

    int ntiles = ((qbase + 3) >> 5) + 1;
    for (int kt = 0; kt < ntiles; ++kt) {
        int k0 = kt * 32;
        __syncthreads();
        // 128 threads load 32 keys x 64 dims of K and V (float4 each)
        #pragma unroll
        for (int i = 0; i < 4; ++i) {
            int idx = i * 128 + threadIdx.x;   // 0..511
            int j   = idx >> 4;                // key 0..31
            int d4  = idx & 15;
            const float* rowp = base + (size_t)(k0 + j) * (3 * CDIM) + h * HDIM;
            float4 kv = *(const float4*)(rowp + CDIM + d4 * 4);
            Kt[d4 * 4 + 0][j] = kv.x; Kt[d4 * 4 + 1][j] = kv.y;
            Kt[d4 * 4 + 2][j] = kv.z; Kt[d4 * 4 + 3][j] = kv.w;
            float4 vv = *(const float4*)(rowp + 2 * CDIM + d4 * 4);
            Vt[d4 * 4 + 0][j] = vv.x; Vt[d4 * 4 + 1][j] = vv.y;
            Vt[d4 * 4 + 2][j] = vv.z; Vt[d4 * 4 + 3][j] = vv.w;
        }
        __syncthreads();

        int kg = k0 + lane;
        float s = 0.f;
        #pragma unroll
        for (int d = 0; d < HDIM; ++d) s += qreg[d] * Kt[d][lane];
        s = (kg <= q) ? s * 0.125f : -1e30f;

        float mt = s;
        #pragma unroll
        for (int off = 16; off > 0; off >>= 1)
            mt = fmaxf(mt, __shfl_xor_sync(0xffffffffu, mt, off));
        float m_new = fmaxf(m_run, mt);
        float corr  = __expf(m_run - m_new);
        float p     = __expf(s - m_new);     // masked s=-1e30 -> 0
        float ps = p;
        #pragma unroll
        for (int off = 16; off > 0; off >>= 1)
            ps += __shfl_xor_sync(0xffffffffu, ps, off);
        l_run = l_run * corr + ps;
        m_run = m_new;

        #pragma unroll
        for (int d = 0; d < HDIM; ++d)
            o[d] = o[d] * corr + p * Vt[d][lane];
    }

    // reduce per-lane partial O across the warp
    #pragma unroll
    for (int d = 0; d < HDIM; ++d)
        #pragma unroll
        for (int off = 16; off > 0; off >>= 1)
            o[d] += __shfl_xor_sync(0xffffffffu, o[d], off);

    float inv_l = 1.f / l_run;
    float* yp = y + (size_t)(b * TSEQ + q) * CDIM + h * HDIM;
    yp[lane]      = o[lane]      * inv_l;
    yp[lane + 32] = o[lane + 32] * inv_l;
}

// ---------------- launch --------------------------------------------------
extern "C" void kernel_launch(void* const* d_in, const int* in_sizes, int n_in,
                              void* d_out, int out_size) {
    const float* x      = (const float*)d_in[0];
    const float* ln1_g  = (const float*)d_in[1];
    const float* ln1_b  = (const float*)d_in[2];
    const float* w_qkv  = (const float*)d_in[3];
    const float* w_o    = (const float*)d_in[4];
    const float* ln2_g  = (const float*)d_in[5];
    const float* ln2_b  = (const float*)d_in[6];
    const float* w_fc   = (const float*)d_in[7];
    const float* b_fc   = (const float*)d_in[8];
    const float* w_proj = (const float*)d_in[9];
    const float* b_proj = (const float*)d_in[10];
    float* out = (float*)d_out;

    float *ln, *qkv, *att, *x1, *hb;
    cudaGetSymbolAddress((void**)&ln,  g_ln);
    cudaGetSymbolAddress((void**)&qkv, g_qkv);
    cudaGetSymbolAddress((void**)&att, g_att);
    cudaGetSymbolAddress((void**)&x1,  g_x1);
    cudaGetSymbolAddress((void**)&hb,  g_h);

    // 1) ln1(x)
    ln_k<<<ROWS, 256>>>(x, ln1_g, ln1_b, ln);
    // 2) qkv = ln1 @ w_qkv
    gemm_k<0><<<dim3(3 * CDIM / BN, ROWS / BM), 256>>>(ln, w_qkv, nullptr, nullptr,
                                                       qkv, ROWS, 3 * CDIM, CDIM);
    // 3) causal attention
    attn_k<<<dim3(TSEQ / 4, NB * NH), 128>>>(qkv, att);
    // 4) x1 = x + att @ w_o
    gemm_k<1><<<dim3(CDIM / BN, ROWS / BM), 256>>>(att, w_o, nullptr, x,
                                                   x1, ROWS, CDIM, CDIM);
    // 5) ln2(x1)
    ln_k<<<ROWS, 256>>>(x1, ln2_g, ln2_b, ln);
    // 6) h = gelu(ln2 @ w_fc + b_fc)
    gemm_k<2><<<dim3(DFF / BN, ROWS / BM), 256>>>(ln, w_fc, b_fc, nullptr,
                                                  hb, ROWS, DFF, CDIM);
    // 7) out = x1 + h @ w_proj + b_proj
    gemm_k<3><<<dim3(CDIM / BN, ROWS / BM), 256>>>(hb, w_proj, b_proj, x1,
                                                   out, ROWS, CDIM, DFF);
}

// round 2
// speedup vs baseline: 2.5810x; 2.5810x over previous
#include <cuda_runtime.h>
#include <math.h>

#define TSEQ 2048
#define NB   2
#define CDIM 768
#define NH   12
#define HDIM 64
#define DFF  3072
#define ROWS (NB * TSEQ)   // 4096

// ---------------- scratch (device globals: allocation-free) ----------------
__device__ float g_ln [ROWS * CDIM];       // 12.6 MB
__device__ float g_qkv[ROWS * 3 * CDIM];   // 37.7 MB
__device__ float g_att[ROWS * CDIM];       // 12.6 MB
__device__ float g_x1 [ROWS * CDIM];       // 12.6 MB
__device__ float g_h  [ROWS * DFF];        // 50.3 MB

__device__ __forceinline__ float gelu_f(float v) {
    return 0.5f * v * (1.0f + erff(v * 0.70710678118654752f));
}

// ---------------- LayerNorm: one block (256 thr) per row of 768 ------------
__global__ __launch_bounds__(256) void ln_k(const float* __restrict__ xin,
                                            const float* __restrict__ g,
                                            const float* __restrict__ b,
                                            float* __restrict__ out) {
    int row = blockIdx.x;
    int tid = threadIdx.x;
    const float* xr = xin + (size_t)row * CDIM;

    float v0 = xr[tid], v1 = xr[tid + 256], v2 = xr[tid + 512];
    float s  = v0 + v1 + v2;
    float ss = v0 * v0 + v1 * v1 + v2 * v2;

    #pragma unroll
    for (int off = 16; off > 0; off >>= 1) {
        s  += __shfl_xor_sync(0xffffffffu, s,  off);
        ss += __shfl_xor_sync(0xffffffffu, ss, off);
    }
    __shared__ float sh_s[8], sh_ss[8];
    int wid = tid >> 5, lane = tid & 31;
    if (lane == 0) { sh_s[wid] = s; sh_ss[wid] = ss; }
    __syncthreads();
    float ts = 0.f, tss = 0.f;
    #pragma unroll
    for (int i = 0; i < 8; ++i) { ts += sh_s[i]; tss += sh_ss[i]; }

    const float inv = 1.0f / (float)CDIM;
    float mu   = ts * inv;
    float var  = tss * inv - mu * mu;
    float rstd = rsqrtf(var + 1e-5f);

    float* orow = out + (size_t)row * CDIM;
    orow[tid      ] = (v0 - mu) * rstd * g[tid      ] + b[tid      ];
    orow[tid + 256] = (v1 - mu) * rstd * g[tid + 256] + b[tid + 256];
    orow[tid + 512] = (v2 - mu) * rstd * g[tid + 512] + b[tid + 512];
}

// ---------------- GEMM: C[M,N] = A[M,K] @ B[K,N] (+epilogue) ---------------
#define BM 128
#define BN 128
#define BK 8

template <int EPI>
__global__ __launch_bounds__(256, 2) void gemm_k(const float* __restrict__ A,
                                                 const float* __restrict__ Bm,
                                                 const float* __restrict__ bias,
                                                 const float* __restrict__ res,
                                                 float* __restrict__ C,
                                                 int M, int N, int K) {
    __shared__ float As[BK][BM];   // A tile, transposed
    __shared__ float Bs[BK][BN];

    int tid = threadIdx.x;
    int bm  = blockIdx.y * BM;
    int bn  = blockIdx.x * BN;

    int arow  = tid >> 1;
    int acol4 = (tid & 1) * 4;
    int brow  = tid >> 5;
    int bcol4 = (tid & 31) * 4;

    const float* Aptr = A  + (size_t)(bm + arow) * K + acol4;
    const float* Bptr = Bm + (size_t)brow * N + bn + bcol4;

    int tx = tid & 15, ty = tid >> 4;

    float acc[8][8];
    #pragma unroll
    for (int i = 0; i < 8; ++i)
        #pragma unroll
        for (int j = 0; j < 8; ++j) acc[i][j] = 0.f;

    float4 a_ld = *(const float4*)Aptr;
    float4 b_ld = *(const float4*)Bptr;

    int ntiles = K / BK;
    for (int t = 0; t < ntiles; ++t) {
        As[acol4 + 0][arow] = a_ld.x;
        As[acol4 + 1][arow] = a_ld.y;
        As[acol4 + 2][arow] = a_ld.z;
        As[acol4 + 3][arow] = a_ld.w;
        *(float4*)&Bs[brow][bcol4] = b_ld;
        __syncthreads();

        if (t + 1 < ntiles) {
            a_ld = *(const float4*)(Aptr + (t + 1) * BK);
            b_ld = *(const float4*)(Bptr + (size_t)(t + 1) * BK * N);
        }

        #pragma unroll
        for (int k = 0; k < BK; ++k) {
            float ar[8], br[8];
            *(float4*)&ar[0] = *(const float4*)&As[k][ty * 4];
            *(float4*)&ar[4] = *(const float4*)&As[k][64 + ty * 4];
            *(float4*)&br[0] = *(const float4*)&Bs[k][tx * 4];
            *(float4*)&br[4] = *(const float4*)&Bs[k][64 + tx * 4];
            #pragma unroll
            for (int i = 0; i < 8; ++i)
                #pragma unroll
                for (int j = 0; j < 8; ++j)
                    acc[i][j] += ar[i] * br[j];
        }
        __syncthreads();
    }

    #pragma unroll
    for (int ig = 0; ig < 2; ++ig) {
        #pragma unroll
        for (int ii = 0; ii < 4; ++ii) {
            int ai = ig * 4 + ii;
            int r  = bm + ig * 64 + ty * 4 + ii;
            #pragma unroll
            for (int jg = 0; jg < 2; ++jg) {
                int c = bn + jg * 64 + tx * 4;
                float4 o4;
                float vv[4];
                #pragma unroll
                for (int j = 0; j < 4; ++j) {
                    float tv = acc[ai][jg * 4 + j];
                    if (EPI == 2 || EPI == 3) tv += bias[c + j];
                    if (EPI == 2)             tv  = gelu_f(tv);
                    if (EPI == 1 || EPI == 3) tv += res[(size_t)r * N + c + j];
                    vv[j] = tv;
                }
                o4.x = vv[0]; o4.y = vv[1]; o4.z = vv[2]; o4.w = vv[3];
                *(float4*)(C + (size_t)r * N + c) = o4;
            }
        }
    }
}

// ---------------- Flash attention: 64q x 64k tiles, 256 threads ------------
// qkv layout per row: [q(768) | k(768) | v(768)], head h at offset h*64.
// Thread (ty,tx) of a 16x16 grid owns a 4x4 S tile and a 4x4 O tile.
#define APAD 68   // row stride (floats); 68*4B = 272B, multiple of 16 -> float4 ok

__global__ __launch_bounds__(256, 3) void attn_k(const float* __restrict__ qkv,
                                                 float* __restrict__ y) {
    extern __shared__ float sm[];
    float* Qs = sm;                  // [64][APAD], transposed: Qs[d][q]
    float* Ks = Qs + 64 * APAD;      // [64][APAD], transposed: Ks[d][k]
    float* Vs = Ks + 64 * APAD;      // [64][APAD], natural:    Vs[k][d]
    float* Ps = Vs + 64 * APAD;      // [64][APAD], transposed: Ps[k][q]

    int bh = blockIdx.y;             // 0..23
    int b  = bh / NH;
    int h  = bh % NH;
    int qt = gridDim.x - 1 - blockIdx.x;   // big (late-diagonal) tiles first
    int q0 = qt * 64;

    int tid = threadIdx.x;
    int tx = tid & 15, ty = tid >> 4;

    const float* base = qkv + (size_t)b * TSEQ * (3 * CDIM) + h * HDIM;

    // load Q tile, transposed, with 1/sqrt(64) folded in
    for (int idx = tid; idx < 64 * 16; idx += 256) {
        int qq = idx >> 4, d4 = idx & 15;
        float4 v = *(const float4*)(base + (size_t)(q0 + qq) * (3 * CDIM) + d4 * 4);
        Qs[(d4 * 4 + 0) * APAD + qq] = v.x * 0.125f;
        Qs[(d4 * 4 + 1) * APAD + qq] = v.y * 0.125f;
        Qs[(d4 * 4 + 2) * APAD + qq] = v.z * 0.125f;
        Qs[(d4 * 4 + 3) * APAD + qq] = v.w * 0.125f;
    }

    float m_i[4], l_i[4], o[4][4];
    #pragma unroll
    for (int i = 0; i < 4; ++i) {
        m_i[i] = -1e30f; l_i[i] = 0.f;
        #pragma unroll
        for (int j = 0; j < 4; ++j) o[i][j] = 0.f;
    }

    int ntiles = qt + 1;
    for (int kt = 0; kt < ntiles; ++kt) {
        int k0 = kt * 64;
        __syncthreads();   // prev tile's P.V reads of Vs/Ps done; Qs visible (1st iter)

        // load K (transposed) and V (natural)
        for (int idx = tid; idx < 64 * 16; idx += 256) {
            int kk = idx >> 4, d4 = idx & 15;
            const float* rp = base + (size_t)(k0 + kk) * (3 * CDIM);
            float4 kv = *(const float4*)(rp + CDIM + d4 * 4);
            Ks[(d4 * 4 + 0) * APAD + kk] = kv.x;
            Ks[(d4 * 4 + 1) * APAD + kk] = kv.y;
            Ks[(d4 * 4 + 2) * APAD + kk] = kv.z;
            Ks[(d4 * 4 + 3) * APAD + kk] = kv.w;
            float4 vv = *(const float4*)(rp + 2 * CDIM + d4 * 4);
            *(float4*)&Vs[kk * APAD + d4 * 4] = vv;
        }
        __syncthreads();

        // S = Q @ K^T (scaled), 4x4 per thread
        float s[4][4];
        #pragma unroll
        for (int i = 0; i < 4; ++i)
            #pragma unroll
            for (int j = 0; j < 4; ++j) s[i][j] = 0.f;

        #pragma unroll 8
        for (int d = 0; d < HDIM; ++d) {
            float4 aq = *(const float4*)&Qs[d * APAD + ty * 4];
            float4 bk = *(const float4*)&Ks[d * APAD + tx * 4];
            float ar[4] = {aq.x, aq.y, aq.z, aq.w};
            float br[4] = {bk.x, bk.y, bk.z, bk.w};
            #pragma unroll
            for (int i = 0; i < 4; ++i)
                #pragma unroll
                for (int j = 0; j < 4; ++j)
                    s[i][j] += ar[i] * br[j];
        }

        // causal mask (only the diagonal tile needs it)
        if (kt == qt) {
            #pragma unroll
            for (int i = 0; i < 4; ++i) {
                int qg = q0 + ty * 4 + i;
                #pragma unroll
                for (int j = 0; j < 4; ++j)
                    if (k0 + tx * 4 + j > qg) s[i][j] = -1e30f;
            }
        }

        // online softmax per row (reduce across the 16 tx lanes)
        #pragma unroll
        for (int i = 0; i < 4; ++i) {
            float mt = fmaxf(fmaxf(s[i][0], s[i][1]), fmaxf(s[i][2], s[i][3]));
            #pragma unroll
            for (int off = 1; off < 16; off <<= 1)
                mt = fmaxf(mt, __shfl_xor_sync(0xffffffffu, mt, off));
            float mn   = fmaxf(m_i[i], mt);
            float corr = __expf(m_i[i] - mn);
            m_i[i] = mn;
            float rs = 0.f;
            #pragma unroll
            for (int j = 0; j < 4; ++j) {
                s[i][j] = __expf(s[i][j] - mn);
                rs += s[i][j];
            }
            #pragma unroll
            for (int off = 1; off < 16; off <<= 1)
                rs += __shfl_xor_sync(0xffffffffu, rs, off);
            l_i[i] = l_i[i] * corr + rs;
            #pragma unroll
            for (int j = 0; j < 4; ++j) o[i][j] *= corr;
        }

        // stage P transposed: Ps[k][q]
        #pragma unroll
        for (int i = 0; i < 4; ++i)
            #pragma unroll
            for (int j = 0; j < 4; ++j)
                Ps[(tx * 4 + j) * APAD + ty * 4 + i] = s[i][j];
        __syncthreads();

        // O += P @ V
        #pragma unroll 8
        for (int k = 0; k < 64; ++k) {
            float4 ap = *(const float4*)&Ps[k * APAD + ty * 4];
            float4 bv = *(const float4*)&Vs[k * APAD + tx * 4];
            float ar[4] = {ap.x, ap.y, ap.z, ap.w};
            float br[4] = {bv.x, bv.y, bv.z, bv.w};
            #pragma unroll
            for (int i = 0; i < 4; ++i)
                #pragma unroll
                for (int j = 0; j < 4; ++j)
                    o[i][j] += ar[i] * br[j];
        }
    }

    // write O / l
    #pragma unroll
    for (int i = 0; i < 4; ++i) {
        float inv_l = 1.f / l_i[i];
        int qg = q0 + ty * 4 + i;
        float4 o4;
        o4.x = o[i][0] * inv_l; o4.y = o[i][1] * inv_l;
        o4.z = o[i][2] * inv_l; o4.w = o[i][3] * inv_l;
        *(float4*)(y + (size_t)(b * TSEQ + qg) * CDIM + h * HDIM + tx * 4) = o4;
    }
}

// ---------------- launch --------------------------------------------------
extern "C" void kernel_launch(void* const* d_in, const int* in_sizes, int n_in,
                              void* d_out, int out_size) {
    const float* x      = (const float*)d_in[0];
    const float* ln1_g  = (const float*)d_in[1];
    const float* ln1_b  = (const float*)d_in[2];
    const float* w_qkv  = (const float*)d_in[3];
    const float* w_o    = (const float*)d_in[4];
    const float* ln2_g  = (const float*)d_in[5];
    const float* ln2_b  = (const float*)d_in[6];
    const float* w_fc   = (const float*)d_in[7];
    const float* b_fc   = (const float*)d_in[8];
    const float* w_proj = (const float*)d_in[9];
    const float* b_proj = (const float*)d_in[10];
    float* out = (float*)d_out;

    float *ln, *qkv, *att, *x1, *hb;
    cudaGetSymbolAddress((void**)&ln,  g_ln);
    cudaGetSymbolAddress((void**)&qkv, g_qkv);
    cudaGetSymbolAddress((void**)&att, g_att);
    cudaGetSymbolAddress((void**)&x1,  g_x1);
    cudaGetSymbolAddress((void**)&hb,  g_h);

    static int smem_set = 0;
    const int ATT_SMEM = 4 * 64 * APAD * 4;   // 69,632 B
    if (!smem_set) {
        cudaFuncSetAttribute(attn_k, cudaFuncAttributeMaxDynamicSharedMemorySize,
                             ATT_SMEM);
        smem_set = 1;
    }

    // 1) ln1(x)
    ln_k<<<ROWS, 256>>>(x, ln1_g, ln1_b, ln);
    // 2) qkv = ln1 @ w_qkv
    gemm_k<0><<<dim3(3 * CDIM / BN, ROWS / BM), 256>>>(ln, w_qkv, nullptr, nullptr,
                                                       qkv, ROWS, 3 * CDIM, CDIM);
    // 3) causal attention
    attn_k<<<dim3(TSEQ / 64, NB * NH), 256, ATT_SMEM>>>(qkv, att);
    // 4) x1 = x + att @ w_o
    gemm_k<1><<<dim3(CDIM / BN, ROWS / BM), 256>>>(att, w_o, nullptr, x,
                                                   x1, ROWS, CDIM, CDIM);
    // 5) ln2(x1)
    ln_k<<<ROWS, 256>>>(x1, ln2_g, ln2_b, ln);
    // 6) h = gelu(ln2 @ w_fc + b_fc)
    gemm_k<2><<<dim3(DFF / BN, ROWS / BM), 256>>>(ln, w_fc, b_fc, nullptr,
                                                  hb, ROWS, DFF, CDIM);
    // 7) out = x1 + h @ w_proj + b_proj
    gemm_k<3><<<dim3(CDIM / BN, ROWS / BM), 256>>>(hb, w_proj, b_proj, x1,
                                                   out, ROWS, CDIM, DFF);
}

// round 3
// speedup vs baseline: 4.3159x; 1.6722x over previous
#include <cuda_runtime.h>
#include <math.h>

#define TSEQ 2048
#define NB   2
#define CDIM 768
#define NH   12
#define HDIM 64
#define DFF  3072
#define ROWS (NB * TSEQ)   // 4096

// ---------------- scratch (device globals: allocation-free) ----------------
__device__ float g_ln [ROWS * CDIM];
__device__ float g_qkv[ROWS * 3 * CDIM];
__device__ float g_att[ROWS * CDIM];
__device__ float g_x1 [ROWS * CDIM];
__device__ float g_h  [ROWS * DFF];

__device__ __forceinline__ float gelu_f(float v) {
    return 0.5f * v * (1.0f + erff(v * 0.70710678118654752f));
}

__device__ __forceinline__ unsigned f2tf32(float f) {
    unsigned o;
    asm("cvt.rna.tf32.f32 %0, %1;" : "=r"(o) : "f"(f));
    return o;
}

// ---------------- LayerNorm ------------------------------------------------
__global__ __launch_bounds__(256) void ln_k(const float* __restrict__ xin,
                                            const float* __restrict__ g,
                                            const float* __restrict__ b,
                                            float* __restrict__ out) {
    int row = blockIdx.x;
    int tid = threadIdx.x;
    const float* xr = xin + (size_t)row * CDIM;

    float v0 = xr[tid], v1 = xr[tid + 256], v2 = xr[tid + 512];
    float s  = v0 + v1 + v2;
    float ss = v0 * v0 + v1 * v1 + v2 * v2;

    #pragma unroll
    for (int off = 16; off > 0; off >>= 1) {
        s  += __shfl_xor_sync(0xffffffffu, s,  off);
        ss += __shfl_xor_sync(0xffffffffu, ss, off);
    }
    __shared__ float sh_s[8], sh_ss[8];
    int wid = tid >> 5, lane = tid & 31;
    if (lane == 0) { sh_s[wid] = s; sh_ss[wid] = ss; }
    __syncthreads();
    float ts = 0.f, tss = 0.f;
    #pragma unroll
    for (int i = 0; i < 8; ++i) { ts += sh_s[i]; tss += sh_ss[i]; }

    const float inv = 1.0f / (float)CDIM;
    float mu   = ts * inv;
    float var  = tss * inv - mu * mu;
    float rstd = rsqrtf(var + 1e-5f);

    float* orow = out + (size_t)row * CDIM;
    orow[tid      ] = (v0 - mu) * rstd * g[tid      ] + b[tid      ];
    orow[tid + 256] = (v1 - mu) * rstd * g[tid + 256] + b[tid + 256];
    orow[tid + 512] = (v2 - mu) * rstd * g[tid + 512] + b[tid + 512];
}

// ---------------- tf32 tensor-core GEMM -----------------------------------
// C[M,N] = A[M,K] @ B[K,N] (+epilogue), tf32 mma.sync m16n8k8.
// CTA tile 128x128x16, 8 warps (2 along M x 4 along N), warp tile 64x32.
// EPI: 0 none, 1 +res, 2 +bias+GELU, 3 +bias+res
#define BM 128
#define BN 128
#define BK 16
#define ASTRIDE 20    // 16 + 4 pad (words) -> conflict-free frag loads
#define BSTRIDE 136   // 128 + 8 pad

template <int EPI>
__global__ __launch_bounds__(256, 2) void gemm_k(const float* __restrict__ A,
                                                 const float* __restrict__ Bm,
                                                 const float* __restrict__ bias,
                                                 const float* __restrict__ res,
                                                 float* __restrict__ C,
                                                 int M, int N, int K) {
    __shared__ unsigned As[2][BM * ASTRIDE];
    __shared__ unsigned Bs[2][BK * BSTRIDE];

    int tid  = threadIdx.x;
    int lane = tid & 31;
    int wid  = tid >> 5;
    int warp_m = wid & 1;        // 0..1
    int warp_n = wid >> 1;       // 0..3
    int bm = blockIdx.y * BM;
    int bn = blockIdx.x * BN;

    int grp = lane >> 2;         // 0..7
    int tig = lane & 3;          // 0..3

    // staging index maps
    int a_m  = tid >> 1;               // wait: 512 float4 over 2 loads below
    // A tile: 128 rows x 16 cols = 512 float4; idx = l*256+tid; m=idx>>2, kq=idx&3
    // B tile: 16 rows x 128 cols = 512 float4; idx = l*256+tid; k=idx>>5, n4=idx&31
    (void)a_m;

    float acc[4][4][4];
    #pragma unroll
    for (int i = 0; i < 4; ++i)
        #pragma unroll
        for (int j = 0; j < 4; ++j)
            #pragma unroll
            for (int r = 0; r < 4; ++r) acc[i][j][r] = 0.f;

    int ntiles = K / BK;

    float4 a_ld[2], b_ld[2];
    // prologue load tile 0
    #pragma unroll
    for (int l = 0; l < 2; ++l) {
        int idx = l * 256 + tid;
        int m = idx >> 2, kq = idx & 3;
        a_ld[l] = *(const float4*)(A + (size_t)(bm + m) * K + kq * 4);
        int k = idx >> 5, n4 = idx & 31;
        b_ld[l] = *(const float4*)(Bm + (size_t)k * N + bn + n4 * 4);
    }
    #pragma unroll
    for (int l = 0; l < 2; ++l) {
        int idx = l * 256 + tid;
        int m = idx >> 2, kq = idx & 3;
        unsigned* ap = &As[0][m * ASTRIDE + kq * 4];
        ap[0] = f2tf32(a_ld[l].x); ap[1] = f2tf32(a_ld[l].y);
        ap[2] = f2tf32(a_ld[l].z); ap[3] = f2tf32(a_ld[l].w);
        int k = idx >> 5, n4 = idx & 31;
        unsigned* bp = &Bs[0][k * BSTRIDE + n4 * 4];
        bp[0] = f2tf32(b_ld[l].x); bp[1] = f2tf32(b_ld[l].y);
        bp[2] = f2tf32(b_ld[l].z); bp[3] = f2tf32(b_ld[l].w);
    }
    __syncthreads();

    for (int t = 0; t < ntiles; ++t) {
        int cur = t & 1, nxt = cur ^ 1;
        bool has_next = (t + 1 < ntiles);
        if (has_next) {
            #pragma unroll
            for (int l = 0; l < 2; ++l) {
                int idx = l * 256 + tid;
                int m = idx >> 2, kq = idx & 3;
                a_ld[l] = *(const float4*)(A + (size_t)(bm + m) * K + (t + 1) * BK + kq * 4);
                int k = idx >> 5, n4 = idx & 31;
                b_ld[l] = *(const float4*)(Bm + (size_t)((t + 1) * BK + k) * N + bn + n4 * 4);
            }
        }

        const unsigned* Asc = As[cur];
        const unsigned* Bsc = Bs[cur];
        #pragma unroll
        for (int ks = 0; ks < BK; ks += 8) {
            unsigned af[4][4], bf[4][2];
            #pragma unroll
            for (int mi = 0; mi < 4; ++mi) {
                int m0 = warp_m * 64 + mi * 16;
                const unsigned* p = &Asc[(m0 + grp) * ASTRIDE + ks + tig];
                af[mi][0] = p[0];
                af[mi][1] = p[8 * ASTRIDE];
                af[mi][2] = p[4];
                af[mi][3] = p[8 * ASTRIDE + 4];
            }
            #pragma unroll
            for (int ni = 0; ni < 4; ++ni) {
                int n0 = warp_n * 32 + ni * 8;
                const unsigned* p = &Bsc[(ks + tig) * BSTRIDE + n0 + grp];
                bf[ni][0] = p[0];
                bf[ni][1] = p[4 * BSTRIDE];
            }
            #pragma unroll
            for (int mi = 0; mi < 4; ++mi)
                #pragma unroll
                for (int ni = 0; ni < 4; ++ni) {
                    asm volatile(
                        "mma.sync.aligned.m16n8k8.row.col.f32.tf32.tf32.f32 "
                        "{%0,%1,%2,%3}, {%4,%5,%6,%7}, {%8,%9}, {%0,%1,%2,%3};"
                        : "+f"(acc[mi][ni][0]), "+f"(acc[mi][ni][1]),
                          "+f"(acc[mi][ni][2]), "+f"(acc[mi][ni][3])
                        : "r"(af[mi][0]), "r"(af[mi][1]),
                          "r"(af[mi][2]), "r"(af[mi][3]),
                          "r"(bf[ni][0]), "r"(bf[ni][1]));
                }
        }

        if (has_next) {
            #pragma unroll
            for (int l = 0; l < 2; ++l) {
                int idx = l * 256 + tid;
                int m = idx >> 2, kq = idx & 3;
                unsigned* ap = &As[nxt][m * ASTRIDE + kq * 4];
                ap[0] = f2tf32(a_ld[l].x); ap[1] = f2tf32(a_ld[l].y);
                ap[2] = f2tf32(a_ld[l].z); ap[3] = f2tf32(a_ld[l].w);
                int k = idx >> 5, n4 = idx & 31;
                unsigned* bp = &Bs[nxt][k * BSTRIDE + n4 * 4];
                bp[0] = f2tf32(b_ld[l].x); bp[1] = f2tf32(b_ld[l].y);
                bp[2] = f2tf32(b_ld[l].z); bp[3] = f2tf32(b_ld[l].w);
            }
        }
        __syncthreads();
    }

    // epilogue: each frag row pair, float2 stores
    #pragma unroll
    for (int mi = 0; mi < 4; ++mi) {
        #pragma unroll
        for (int rr = 0; rr < 2; ++rr) {
            int r = bm + warp_m * 64 + mi * 16 + grp + rr * 8;
            #pragma unroll
            for (int ni = 0; ni < 4; ++ni) {
                int c = bn + warp_n * 32 + ni * 8 + 2 * tig;
                float v0 = acc[mi][ni][rr * 2 + 0];
                float v1 = acc[mi][ni][rr * 2 + 1];
                if (EPI == 2 || EPI == 3) { v0 += bias[c]; v1 += bias[c + 1]; }
                if (EPI == 2)             { v0 = gelu_f(v0); v1 = gelu_f(v1); }
                if (EPI == 1 || EPI == 3) {
                    const float* rp = res + (size_t)r * N + c;
                    v0 += rp[0]; v1 += rp[1];
                }
                float2 o2; o2.x = v0; o2.y = v1;
                *(float2*)(C + (size_t)r * N + c) = o2;
            }
        }
    }
}

// ---------------- Flash attention: 64q x 64k tiles, 256 threads ------------
#define APAD 68

__global__ __launch_bounds__(256, 3) void attn_k(const float* __restrict__ qkv,
                                                 float* __restrict__ y) {
    extern __shared__ float sm[];
    float* Qs = sm;
    float* Ks = Qs + 64 * APAD;
    float* Vs = Ks + 64 * APAD;
    float* Ps = Vs + 64 * APAD;

    int bh = blockIdx.y;
    int b  = bh / NH;
    int h  = bh % NH;
    int qt = gridDim.x - 1 - blockIdx.x;
    int q0 = qt * 64;

    int tid = threadIdx.x;
    int tx = tid & 15, ty = tid >> 4;

    const float* base = qkv + (size_t)b * TSEQ * (3 * CDIM) + h * HDIM;

    for (int idx = tid; idx < 64 * 16; idx += 256) {
        int qq = idx >> 4, d4 = idx & 15;
        float4 v = *(const float4*)(base + (size_t)(q0 + qq) * (3 * CDIM) + d4 * 4);
        Qs[(d4 * 4 + 0) * APAD + qq] = v.x * 0.125f;
        Qs[(d4 * 4 + 1) * APAD + qq] = v.y * 0.125f;
        Qs[(d4 * 4 + 2) * APAD + qq] = v.z * 0.125f;
        Qs[(d4 * 4 + 3) * APAD + qq] = v.w * 0.125f;
    }

    float m_i[4], l_i[4], o[4][4];
    #pragma unroll
    for (int i = 0; i < 4; ++i) {
        m_i[i] = -1e30f; l_i[i] = 0.f;
        #pragma unroll
        for (int j = 0; j < 4; ++j) o[i][j] = 0.f;
    }

    int ntiles = qt + 1;
    for (int kt = 0; kt < ntiles; ++kt) {
        int k0 = kt * 64;
        __syncthreads();

        for (int idx = tid; idx < 64 * 16; idx += 256) {
            int kk = idx >> 4, d4 = idx & 15;
            const float* rp = base + (size_t)(k0 + kk) * (3 * CDIM);
            float4 kv = *(const float4*)(rp + CDIM + d4 * 4);
            Ks[(d4 * 4 + 0) * APAD + kk] = kv.x;
            Ks[(d4 * 4 + 1) * APAD + kk] = kv.y;
            Ks[(d4 * 4 + 2) * APAD + kk] = kv.z;
            Ks[(d4 * 4 + 3) * APAD + kk] = kv.w;
            float4 vv = *(const float4*)(rp + 2 * CDIM + d4 * 4);
            *(float4*)&Vs[kk * APAD + d4 * 4] = vv;
        }
        __syncthreads();

        float s[4][4];
        #pragma unroll
        for (int i = 0; i < 4; ++i)
            #pragma unroll
            for (int j = 0; j < 4; ++j) s[i][j] = 0.f;

        #pragma unroll 8
        for (int d = 0; d < HDIM; ++d) {
            float4 aq = *(const float4*)&Qs[d * APAD + ty * 4];
            float4 bk = *(const float4*)&Ks[d * APAD + tx * 4];
            float ar[4] = {aq.x, aq.y, aq.z, aq.w};
            float br[4] = {bk.x, bk.y, bk.z, bk.w};
            #pragma unroll
            for (int i = 0; i < 4; ++i)
                #pragma unroll
                for (int j = 0; j < 4; ++j)
                    s[i][j] += ar[i] * br[j];
        }

        if (kt == qt) {
            #pragma unroll
            for (int i = 0; i < 4; ++i) {
                int qg = q0 + ty * 4 + i;
                #pragma unroll
                for (int j = 0; j < 4; ++j)
                    if (k0 + tx * 4 + j > qg) s[i][j] = -1e30f;
            }
        }

        #pragma unroll
        for (int i = 0; i < 4; ++i) {
            float mt = fmaxf(fmaxf(s[i][0], s[i][1]), fmaxf(s[i][2], s[i][3]));
            #pragma unroll
            for (int off = 1; off < 16; off <<= 1)
                mt = fmaxf(mt, __shfl_xor_sync(0xffffffffu, mt, off));
            float mn   = fmaxf(m_i[i], mt);
            float corr = __expf(m_i[i] - mn);
            m_i[i] = mn;
            float rs = 0.f;
            #pragma unroll
            for (int j = 0; j < 4; ++j) {
                s[i][j] = __expf(s[i][j] - mn);
                rs += s[i][j];
            }
            #pragma unroll
            for (int off = 1; off < 16; off <<= 1)
                rs += __shfl_xor_sync(0xffffffffu, rs, off);
            l_i[i] = l_i[i] * corr + rs;
            #pragma unroll
            for (int j = 0; j < 4; ++j) o[i][j] *= corr;
        }

        #pragma unroll
        for (int i = 0; i < 4; ++i)
            #pragma unroll
            for (int j = 0; j < 4; ++j)
                Ps[(tx * 4 + j) * APAD + ty * 4 + i] = s[i][j];
        __syncthreads();

        #pragma unroll 8
        for (int k = 0; k < 64; ++k) {
            float4 ap = *(const float4*)&Ps[k * APAD + ty * 4];
            float4 bv = *(const float4*)&Vs[k * APAD + tx * 4];
            float ar[4] = {ap.x, ap.y, ap.z, ap.w};
            float br[4] = {bv.x, bv.y, bv.z, bv.w};
            #pragma unroll
            for (int i = 0; i < 4; ++i)
                #pragma unroll
                for (int j = 0; j < 4; ++j)
                    o[i][j] += ar[i] * br[j];
        }
    }

    #pragma unroll
    for (int i = 0; i < 4; ++i) {
        float inv_l = 1.f / l_i[i];
        int qg = q0 + ty * 4 + i;
        float4 o4;
        o4.x = o[i][0] * inv_l; o4.y = o[i][1] * inv_l;
        o4.z = o[i][2] * inv_l; o4.w = o[i][3] * inv_l;
        *(float4*)(y + (size_t)(b * TSEQ + qg) * CDIM + h * HDIM + tx * 4) = o4;
    }
}

// ---------------- launch --------------------------------------------------
extern "C" void kernel_launch(void* const* d_in, const int* in_sizes, int n_in,
                              void* d_out, int out_size) {
    const float* x      = (const float*)d_in[0];
    const float* ln1_g  = (const float*)d_in[1];
    const float* ln1_b  = (const float*)d_in[2];
    const float* w_qkv  = (const float*)d_in[3];
    const float* w_o    = (const float*)d_in[4];
    const float* ln2_g  = (const float*)d_in[5];
    const float* ln2_b  = (const float*)d_in[6];
    const float* w_fc   = (const float*)d_in[7];
    const float* b_fc   = (const float*)d_in[8];
    const float* w_proj = (const float*)d_in[9];
    const float* b_proj = (const float*)d_in[10];
    float* out = (float*)d_out;

    float *ln, *qkv, *att, *x1, *hb;
    cudaGetSymbolAddress((void**)&ln,  g_ln);
    cudaGetSymbolAddress((void**)&qkv, g_qkv);
    cudaGetSymbolAddress((void**)&att, g_att);
    cudaGetSymbolAddress((void**)&x1,  g_x1);
    cudaGetSymbolAddress((void**)&hb,  g_h);

    static int smem_set = 0;
    const int ATT_SMEM = 4 * 64 * APAD * 4;
    if (!smem_set) {
        cudaFuncSetAttribute(attn_k, cudaFuncAttributeMaxDynamicSharedMemorySize,
                             ATT_SMEM);
        smem_set = 1;
    }

    ln_k<<<ROWS, 256>>>(x, ln1_g, ln1_b, ln);
    gemm_k<0><<<dim3(3 * CDIM / BN, ROWS / BM), 256>>>(ln, w_qkv, nullptr, nullptr,
                                                       qkv, ROWS, 3 * CDIM, CDIM);
    attn_k<<<dim3(TSEQ / 64, NB * NH), 256, ATT_SMEM>>>(qkv, att);
    gemm_k<1><<<dim3(CDIM / BN, ROWS / BM), 256>>>(att, w_o, nullptr, x,
                                                   x1, ROWS, CDIM, CDIM);
    ln_k<<<ROWS, 256>>>(x1, ln2_g, ln2_b, ln);
    gemm_k<2><<<dim3(DFF / BN, ROWS / BM), 256>>>(ln, w_fc, b_fc, nullptr,
                                                  hb, ROWS, DFF, CDIM);
    gemm_k<3><<<dim3(CDIM / BN, ROWS / BM), 256>>>(hb, w_proj, b_proj, x1,
                                                   out, ROWS, CDIM, DFF);
}

// round 4
// speedup vs baseline: 4.4988x; 1.0424x over previous
#include <cuda_runtime.h>
#include <math.h>

#define TSEQ 2048
#define NB   2
#define CDIM 768
#define NH   12
#define HDIM 64
#define DFF  3072
#define ROWS (NB * TSEQ)   // 4096

// ---------------- scratch (device globals: allocation-free) ----------------
__device__ float g_ln [ROWS * CDIM];
__device__ float g_qkv[ROWS * 3 * CDIM];
__device__ float g_att[ROWS * CDIM];
__device__ float g_x1 [ROWS * CDIM];
__device__ float g_h  [ROWS * DFF];
// tf32-pre-rounded weights
__device__ float g_wqkv_r [CDIM * 3 * CDIM];
__device__ float g_wo_r   [CDIM * CDIM];
__device__ float g_wfc_r  [CDIM * DFF];
__device__ float g_wproj_r[DFF * CDIM];

__device__ __forceinline__ float gelu_f(float v) {
    return 0.5f * v * (1.0f + erff(v * 0.70710678118654752f));
}

__device__ __forceinline__ float tf32r(float f) {
    unsigned u;
    asm("cvt.rna.tf32.f32 %0, %1;" : "=r"(u) : "f"(f));
    return __uint_as_float(u);
}

// ---------------- weight pre-round (once per launch) -----------------------
__global__ __launch_bounds__(256) void round_k(const float* __restrict__ in,
                                               float* __restrict__ out, int n4) {
    int i = blockIdx.x * 256 + threadIdx.x;
    if (i < n4) {
        float4 v = ((const float4*)in)[i];
        v.x = tf32r(v.x); v.y = tf32r(v.y);
        v.z = tf32r(v.z); v.w = tf32r(v.w);
        ((float4*)out)[i] = v;
    }
}

// ---------------- LayerNorm (output rounded to tf32) -----------------------
__global__ __launch_bounds__(256) void ln_k(const float* __restrict__ xin,
                                            const float* __restrict__ g,
                                            const float* __restrict__ b,
                                            float* __restrict__ out) {
    int row = blockIdx.x;
    int tid = threadIdx.x;
    const float* xr = xin + (size_t)row * CDIM;

    float v0 = xr[tid], v1 = xr[tid + 256], v2 = xr[tid + 512];
    float s  = v0 + v1 + v2;
    float ss = v0 * v0 + v1 * v1 + v2 * v2;

    #pragma unroll
    for (int off = 16; off > 0; off >>= 1) {
        s  += __shfl_xor_sync(0xffffffffu, s,  off);
        ss += __shfl_xor_sync(0xffffffffu, ss, off);
    }
    __shared__ float sh_s[8], sh_ss[8];
    int wid = tid >> 5, lane = tid & 31;
    if (lane == 0) { sh_s[wid] = s; sh_ss[wid] = ss; }
    __syncthreads();
    float ts = 0.f, tss = 0.f;
    #pragma unroll
    for (int i = 0; i < 8; ++i) { ts += sh_s[i]; tss += sh_ss[i]; }

    const float inv = 1.0f / (float)CDIM;
    float mu   = ts * inv;
    float var  = tss * inv - mu * mu;
    float rstd = rsqrtf(var + 1e-5f);

    float* orow = out + (size_t)row * CDIM;
    orow[tid      ] = tf32r((v0 - mu) * rstd * g[tid      ] + b[tid      ]);
    orow[tid + 256] = tf32r((v1 - mu) * rstd * g[tid + 256] + b[tid + 256]);
    orow[tid + 512] = tf32r((v2 - mu) * rstd * g[tid + 512] + b[tid + 512]);
}

// ---------------- tf32 tensor-core GEMM with cp.async 3-stage pipeline -----
// C[M,N] = A[M,K] @ B[K,N] (+epilogue). A,B must be tf32-pre-rounded fp32.
// CTA tile 128x128x16, 8 warps (2M x 4N), warp tile 64x32 (4x4 m16n8k8 frags).
// EPI: 0 none, 1 +res, 2 +bias+GELU(out rounded), 3 +bias+res
#define BM 128
#define BN 128
#define BK 16
#define ASTRIDE 20    // words; 80B row stride (16B-aligned, conflict-free frags)
#define BSTRIDE 136   // words; 544B
#define ASZ (BM * ASTRIDE)   // 2560 words
#define BSZ (BK * BSTRIDE)   // 2176 words
#define NSTAGE 3
#define GEMM_SMEM (NSTAGE * (ASZ + BSZ) * 4)   // 56,832 B

__device__ __forceinline__ void cp16(unsigned dst, const void* src) {
    asm volatile("cp.async.cg.shared.global [%0], [%1], 16;\n"
                 :: "r"(dst), "l"(src) : "memory");
}
__device__ __forceinline__ void cp_commit() {
    asm volatile("cp.async.commit_group;\n" ::: "memory");
}

template <int EPI>
__global__ __launch_bounds__(256, 2) void gemm_k(const float* __restrict__ A,
                                                 const float* __restrict__ Bm,
                                                 const float* __restrict__ bias,
                                                 const float* __restrict__ res,
                                                 float* __restrict__ C,
                                                 int M, int N, int K) {
    extern __shared__ unsigned sm_u[];
    unsigned* AsB = sm_u;             // [NSTAGE][ASZ]
    unsigned* BsB = sm_u + NSTAGE * ASZ;

    int tid  = threadIdx.x;
    int lane = tid & 31;
    int wid  = tid >> 5;
    int warp_m = wid & 1;
    int warp_n = wid >> 1;
    int bm = blockIdx.y * BM;
    int bn = blockIdx.x * BN;
    int grp = lane >> 2;
    int tig = lane & 3;

    // per-thread staging coords (2 x 16B for A, 2 x 16B for B per tile)
    const float* aSrc[2]; const float* bSrc[2];
    unsigned aOff[2], bOff[2];
    #pragma unroll
    for (int l = 0; l < 2; ++l) {
        int idx = l * 256 + tid;
        int m = idx >> 2, kq = idx & 3;
        aSrc[l] = A + (size_t)(bm + m) * K + kq * 4;
        aOff[l] = (unsigned)(m * ASTRIDE + kq * 4) * 4u;
        int k = idx >> 5, n4 = idx & 31;
        bSrc[l] = Bm + (size_t)k * N + bn + n4 * 4;
        bOff[l] = (unsigned)(k * BSTRIDE + n4 * 4) * 4u;
    }
    unsigned smem_base = (unsigned)__cvta_generic_to_shared(sm_u);
    unsigned bs_base   = smem_base + NSTAGE * ASZ * 4;

    int ntiles = K / BK;

    auto issue = [&](int t) {
        int buf = t % NSTAGE;
        unsigned aB = smem_base + buf * (ASZ * 4);
        unsigned bB = bs_base   + buf * (BSZ * 4);
        #pragma unroll
        for (int l = 0; l < 2; ++l) {
            cp16(aB + aOff[l], aSrc[l] + t * BK);
            cp16(bB + bOff[l], bSrc[l] + (size_t)t * BK * N);
        }
        cp_commit();
    };

    float acc[4][4][4];
    #pragma unroll
    for (int i = 0; i < 4; ++i)
        #pragma unroll
        for (int j = 0; j < 4; ++j)
            #pragma unroll
            for (int r = 0; r < 4; ++r) acc[i][j][r] = 0.f;

    issue(0);
    issue(1);

    for (int t = 0; t < ntiles; ++t) {
        if (t + 2 < ntiles) {
            issue(t + 2);
            asm volatile("cp.async.wait_group %0;\n" :: "n"(2));
        } else if (t + 1 < ntiles) {
            asm volatile("cp.async.wait_group %0;\n" :: "n"(1));
        } else {
            asm volatile("cp.async.wait_group %0;\n" :: "n"(0));
        }
        __syncthreads();

        const unsigned* Asc = AsB + (t % NSTAGE) * ASZ;
        const unsigned* Bsc = BsB + (t % NSTAGE) * BSZ;
        #pragma unroll
        for (int ks = 0; ks < BK; ks += 8) {
            unsigned af[4][4], bf[4][2];
            #pragma unroll
            for (int mi = 0; mi < 4; ++mi) {
                int m0 = warp_m * 64 + mi * 16;
                const unsigned* p = &Asc[(m0 + grp) * ASTRIDE + ks + tig];
                af[mi][0] = p[0];
                af[mi][1] = p[8 * ASTRIDE];
                af[mi][2] = p[4];
                af[mi][3] = p[8 * ASTRIDE + 4];
            }
            #pragma unroll
            for (int ni = 0; ni < 4; ++ni) {
                int n0 = warp_n * 32 + ni * 8;
                const unsigned* p = &Bsc[(ks + tig) * BSTRIDE + n0 + grp];
                bf[ni][0] = p[0];
                bf[ni][1] = p[4 * BSTRIDE];
            }
            #pragma unroll
            for (int mi = 0; mi < 4; ++mi)
                #pragma unroll
                for (int ni = 0; ni < 4; ++ni) {
                    asm volatile(
                        "mma.sync.aligned.m16n8k8.row.col.f32.tf32.tf32.f32 "
                        "{%0,%1,%2,%3}, {%4,%5,%6,%7}, {%8,%9}, {%0,%1,%2,%3};"
                        : "+f"(acc[mi][ni][0]), "+f"(acc[mi][ni][1]),
                          "+f"(acc[mi][ni][2]), "+f"(acc[mi][ni][3])
                        : "r"(af[mi][0]), "r"(af[mi][1]),
                          "r"(af[mi][2]), "r"(af[mi][3]),
                          "r"(bf[ni][0]), "r"(bf[ni][1]));
                }
        }
        __syncthreads();
    }

    // epilogue
    #pragma unroll
    for (int mi = 0; mi < 4; ++mi) {
        #pragma unroll
        for (int rr = 0; rr < 2; ++rr) {
            int r = bm + warp_m * 64 + mi * 16 + grp + rr * 8;
            #pragma unroll
            for (int ni = 0; ni < 4; ++ni) {
                int c = bn + warp_n * 32 + ni * 8 + 2 * tig;
                float v0 = acc[mi][ni][rr * 2 + 0];
                float v1 = acc[mi][ni][rr * 2 + 1];
                if (EPI == 2 || EPI == 3) { v0 += bias[c]; v1 += bias[c + 1]; }
                if (EPI == 2) { v0 = tf32r(gelu_f(v0)); v1 = tf32r(gelu_f(v1)); }
                if (EPI == 1 || EPI == 3) {
                    const float* rp = res + (size_t)r * N + c;
                    v0 += rp[0]; v1 += rp[1];
                }
                float2 o2; o2.x = v0; o2.y = v1;
                *(float2*)(C + (size_t)r * N + c) = o2;
            }
        }
    }
}

// ---------------- Flash attention: 64q x 64k tiles, 256 threads ------------
// Output rounded to tf32 (feeds gemm<1> as A).
#define APAD 68

__global__ __launch_bounds__(256, 3) void attn_k(const float* __restrict__ qkv,
                                                 float* __restrict__ y) {
    extern __shared__ float sm[];
    float* Qs = sm;
    float* Ks = Qs + 64 * APAD;
    float* Vs = Ks + 64 * APAD;
    float* Ps = Vs + 64 * APAD;

    int bh = blockIdx.y;
    int b  = bh / NH;
    int h  = bh % NH;
    int qt = gridDim.x - 1 - blockIdx.x;
    int q0 = qt * 64;

    int tid = threadIdx.x;
    int tx = tid & 15, ty = tid >> 4;

    const float* base = qkv + (size_t)b * TSEQ * (3 * CDIM) + h * HDIM;

    for (int idx = tid; idx < 64 * 16; idx += 256) {
        int qq = idx >> 4, d4 = idx & 15;
        float4 v = *(const float4*)(base + (size_t)(q0 + qq) * (3 * CDIM) + d4 * 4);
        Qs[(d4 * 4 + 0) * APAD + qq] = v.x * 0.125f;
        Qs[(d4 * 4 + 1) * APAD + qq] = v.y * 0.125f;
        Qs[(d4 * 4 + 2) * APAD + qq] = v.z * 0.125f;
        Qs[(d4 * 4 + 3) * APAD + qq] = v.w * 0.125f;
    }

    float m_i[4], l_i[4], o[4][4];
    #pragma unroll
    for (int i = 0; i < 4; ++i) {
        m_i[i] = -1e30f; l_i[i] = 0.f;
        #pragma unroll
        for (int j = 0; j < 4; ++j) o[i][j] = 0.f;
    }

    int ntiles = qt + 1;
    for (int kt = 0; kt < ntiles; ++kt) {
        int k0 = kt * 64;
        __syncthreads();

        for (int idx = tid; idx < 64 * 16; idx += 256) {
            int kk = idx >> 4, d4 = idx & 15;
            const float* rp = base + (size_t)(k0 + kk) * (3 * CDIM);
            float4 kv = *(const float4*)(rp + CDIM + d4 * 4);
            Ks[(d4 * 4 + 0) * APAD + kk] = kv.x;
            Ks[(d4 * 4 + 1) * APAD + kk] = kv.y;
            Ks[(d4 * 4 + 2) * APAD + kk] = kv.z;
            Ks[(d4 * 4 + 3) * APAD + kk] = kv.w;
            float4 vv = *(const float4*)(rp + 2 * CDIM + d4 * 4);
            *(float4*)&Vs[kk * APAD + d4 * 4] = vv;
        }
        __syncthreads();

        float s[4][4];
        #pragma unroll
        for (int i = 0; i < 4; ++i)
            #pragma unroll
            for (int j = 0; j < 4; ++j) s[i][j] = 0.f;

        #pragma unroll 8
        for (int d = 0; d < HDIM; ++d) {
            float4 aq = *(const float4*)&Qs[d * APAD + ty * 4];
            float4 bk = *(const float4*)&Ks[d * APAD + tx * 4];
            float ar[4] = {aq.x, aq.y, aq.z, aq.w};
            float br[4] = {bk.x, bk.y, bk.z, bk.w};
            #pragma unroll
            for (int i = 0; i < 4; ++i)
                #pragma unroll
                for (int j = 0; j < 4; ++j)
                    s[i][j] += ar[i] * br[j];
        }

        if (kt == qt) {
            #pragma unroll
            for (int i = 0; i < 4; ++i) {
                int qg = q0 + ty * 4 + i;
                #pragma unroll
                for (int j = 0; j < 4; ++j)
                    if (k0 + tx * 4 + j > qg) s[i][j] = -1e30f;
            }
        }

        #pragma unroll
        for (int i = 0; i < 4; ++i) {
            float mt = fmaxf(fmaxf(s[i][0], s[i][1]), fmaxf(s[i][2], s[i][3]));
            #pragma unroll
            for (int off = 1; off < 16; off <<= 1)
                mt = fmaxf(mt, __shfl_xor_sync(0xffffffffu, mt, off));
            float mn   = fmaxf(m_i[i], mt);
            float corr = __expf(m_i[i] - mn);
            m_i[i] = mn;
            float rs = 0.f;
            #pragma unroll
            for (int j = 0; j < 4; ++j) {
                s[i][j] = __expf(s[i][j] - mn);
                rs += s[i][j];
            }
            #pragma unroll
            for (int off = 1; off < 16; off <<= 1)
                rs += __shfl_xor_sync(0xffffffffu, rs, off);
            l_i[i] = l_i[i] * corr + rs;
            #pragma unroll
            for (int j = 0; j < 4; ++j) o[i][j] *= corr;
        }

        #pragma unroll
        for (int i = 0; i < 4; ++i)
            #pragma unroll
            for (int j = 0; j < 4; ++j)
                Ps[(tx * 4 + j) * APAD + ty * 4 + i] = s[i][j];
        __syncthreads();

        #pragma unroll 8
        for (int k = 0; k < 64; ++k) {
            float4 ap = *(const float4*)&Ps[k * APAD + ty * 4];
            float4 bv = *(const float4*)&Vs[k * APAD + tx * 4];
            float ar[4] = {ap.x, ap.y, ap.z, ap.w};
            float br[4] = {bv.x, bv.y, bv.z, bv.w};
            #pragma unroll
            for (int i = 0; i < 4; ++i)
                #pragma unroll
                for (int j = 0; j < 4; ++j)
                    o[i][j] += ar[i] * br[j];
        }
    }

    #pragma unroll
    for (int i = 0; i < 4; ++i) {
        float inv_l = 1.f / l_i[i];
        int qg = q0 + ty * 4 + i;
        float4 o4;
        o4.x = tf32r(o[i][0] * inv_l); o4.y = tf32r(o[i][1] * inv_l);
        o4.z = tf32r(o[i][2] * inv_l); o4.w = tf32r(o[i][3] * inv_l);
        *(float4*)(y + (size_t)(b * TSEQ + qg) * CDIM + h * HDIM + tx * 4) = o4;
    }
}

// ---------------- launch --------------------------------------------------
extern "C" void kernel_launch(void* const* d_in, const int* in_sizes, int n_in,
                              void* d_out, int out_size) {
    const float* x      = (const float*)d_in[0];
    const float* ln1_g  = (const float*)d_in[1];
    const float* ln1_b  = (const float*)d_in[2];
    const float* w_qkv  = (const float*)d_in[3];
    const float* w_o    = (const float*)d_in[4];
    const float* ln2_g  = (const float*)d_in[5];
    const float* ln2_b  = (const float*)d_in[6];
    const float* w_fc   = (const float*)d_in[7];
    const float* b_fc   = (const float*)d_in[8];
    const float* w_proj = (const float*)d_in[9];
    const float* b_proj = (const float*)d_in[10];
    float* out = (float*)d_out;

    float *ln, *qkv, *att, *x1, *hb;
    float *wqkv_r, *wo_r, *wfc_r, *wproj_r;
    cudaGetSymbolAddress((void**)&ln,  g_ln);
    cudaGetSymbolAddress((void**)&qkv, g_qkv);
    cudaGetSymbolAddress((void**)&att, g_att);
    cudaGetSymbolAddress((void**)&x1,  g_x1);
    cudaGetSymbolAddress((void**)&hb,  g_h);
    cudaGetSymbolAddress((void**)&wqkv_r,  g_wqkv_r);
    cudaGetSymbolAddress((void**)&wo_r,    g_wo_r);
    cudaGetSymbolAddress((void**)&wfc_r,   g_wfc_r);
    cudaGetSymbolAddress((void**)&wproj_r, g_wproj_r);

    static int smem_set = 0;
    const int ATT_SMEM = 4 * 64 * APAD * 4;
    if (!smem_set) {
        cudaFuncSetAttribute(attn_k, cudaFuncAttributeMaxDynamicSharedMemorySize,
                             ATT_SMEM);
        cudaFuncSetAttribute(gemm_k<0>, cudaFuncAttributeMaxDynamicSharedMemorySize, GEMM_SMEM);
        cudaFuncSetAttribute(gemm_k<1>, cudaFuncAttributeMaxDynamicSharedMemorySize, GEMM_SMEM);
        cudaFuncSetAttribute(gemm_k<2>, cudaFuncAttributeMaxDynamicSharedMemorySize, GEMM_SMEM);
        cudaFuncSetAttribute(gemm_k<3>, cudaFuncAttributeMaxDynamicSharedMemorySize, GEMM_SMEM);
        smem_set = 1;
    }

    // pre-round weights to tf32
    round_k<<<(CDIM * 3 * CDIM / 4 + 255) / 256, 256>>>(w_qkv,  wqkv_r,  CDIM * 3 * CDIM / 4);
    round_k<<<(CDIM * CDIM / 4 + 255) / 256, 256>>>(w_o,    wo_r,    CDIM * CDIM / 4);
    round_k<<<(CDIM * DFF / 4 + 255) / 256, 256>>>(w_fc,   wfc_r,   CDIM * DFF / 4);
    round_k<<<(DFF * CDIM / 4 + 255) / 256, 256>>>(w_proj, wproj_r, DFF * CDIM / 4);

    ln_k<<<ROWS, 256>>>(x, ln1_g, ln1_b, ln);
    gemm_k<0><<<dim3(3 * CDIM / BN, ROWS / BM), 256, GEMM_SMEM>>>(ln, wqkv_r, nullptr, nullptr,
                                                       qkv, ROWS, 3 * CDIM, CDIM);
    attn_k<<<dim3(TSEQ / 64, NB * NH), 256, ATT_SMEM>>>(qkv, att);
    gemm_k<1><<<dim3(CDIM / BN, ROWS / BM), 256, GEMM_SMEM>>>(att, wo_r, nullptr, x,
                                                   x1, ROWS, CDIM, CDIM);
    ln_k<<<ROWS, 256>>>(x1, ln2_g, ln2_b, ln);
    gemm_k<2><<<dim3(DFF / BN, ROWS / BM), 256, GEMM_SMEM>>>(ln, wfc_r, b_fc, nullptr,
                                                  hb, ROWS, DFF, CDIM);
    gemm_k<3><<<dim3(CDIM / BN, ROWS / BM), 256, GEMM_SMEM>>>(hb, wproj_r, b_proj, x1,
                                                   out, ROWS, CDIM, DFF);
}

// round 6
// speedup vs baseline: 5.7470x; 1.2775x over previous
#include <cuda_runtime.h>
#include <cuda_fp16.h>
#include <math.h>

#define TSEQ 2048
#define NB   2
#define CDIM 768
#define NH   12
#define HDIM 64
#define DFF  3072
#define ROWS (NB * TSEQ)   // 4096

// ---------------- scratch (device globals: allocation-free) ----------------
__device__ __half g_lnh [ROWS * CDIM];      // ln output (GEMM A)
__device__ float  g_qkv [ROWS * 3 * CDIM];  // fp32 (attention precision)
__device__ __half g_atth[ROWS * CDIM];      // attn output (GEMM A)
__device__ float  g_x1  [ROWS * CDIM];      // residual stream fp32
__device__ __half g_hh  [ROWS * DFF];       // gelu output (GEMM A)
// fp16 weights
__device__ __half g_wqkv_h [CDIM * 3 * CDIM];
__device__ __half g_wo_h   [CDIM * CDIM];
__device__ __half g_wfc_h  [CDIM * DFF];
__device__ __half g_wproj_h[DFF * CDIM];

__device__ __forceinline__ float gelu_f(float v) {
    return 0.5f * v * (1.0f + erff(v * 0.70710678118654752f));
}

union Pack4 { __half h[4]; uint2 u; };

// ---------------- weight fp32 -> fp16 (once per launch) --------------------
__global__ __launch_bounds__(256) void roundh_k(const float* __restrict__ in,
                                                __half* __restrict__ out,
                                                int n4) {
    int i = blockIdx.x * 256 + threadIdx.x;
    if (i < n4) {
        float4 v = ((const float4*)in)[i];
        Pack4 p;
        p.h[0] = __float2half_rn(v.x); p.h[1] = __float2half_rn(v.y);
        p.h[2] = __float2half_rn(v.z); p.h[3] = __float2half_rn(v.w);
        ((uint2*)out)[i] = p.u;
    }
}

// ---------------- LayerNorm (fp32 in, fp16 out) ----------------------------
__global__ __launch_bounds__(256) void ln_k(const float* __restrict__ xin,
                                            const float* __restrict__ g,
                                            const float* __restrict__ b,
                                            __half* __restrict__ out) {
    int row = blockIdx.x;
    int tid = threadIdx.x;
    const float* xr = xin + (size_t)row * CDIM;

    float v0 = xr[tid], v1 = xr[tid + 256], v2 = xr[tid + 512];
    float s  = v0 + v1 + v2;
    float ss = v0 * v0 + v1 * v1 + v2 * v2;

    #pragma unroll
    for (int off = 16; off > 0; off >>= 1) {
        s  += __shfl_xor_sync(0xffffffffu, s,  off);
        ss += __shfl_xor_sync(0xffffffffu, ss, off);
    }
    __shared__ float sh_s[8], sh_ss[8];
    int wid = tid >> 5, lane = tid & 31;
    if (lane == 0) { sh_s[wid] = s; sh_ss[wid] = ss; }
    __syncthreads();
    float ts = 0.f, tss = 0.f;
    #pragma unroll
    for (int i = 0; i < 8; ++i) { ts += sh_s[i]; tss += sh_ss[i]; }

    const float inv = 1.0f / (float)CDIM;
    float mu   = ts * inv;
    float var  = tss * inv - mu * mu;
    float rstd = rsqrtf(var + 1e-5f);

    __half* orow = out + (size_t)row * CDIM;
    orow[tid      ] = __float2half_rn((v0 - mu) * rstd * g[tid      ] + b[tid      ]);
    orow[tid + 256] = __float2half_rn((v1 - mu) * rstd * g[tid + 256] + b[tid + 256]);
    orow[tid + 512] = __float2half_rn((v2 - mu) * rstd * g[tid + 512] + b[tid + 512]);
}

// ---------------- fp16 tensor-core GEMM, cp.async 4-stage, ldmatrix --------
// C[M,N] = A[M,K] @ B[K,N] (+epilogue). A,B fp16, accum fp32.
// CTA 128x128x16, 8 warps (2M x 4N), warp tile 64x32, m16n8k16.
// EPI: 0 none(f32 out), 1 +res(f32), 2 +bias+GELU(fp16 out), 3 +bias+res(f32)
#define BM 128
#define BN 128
#define BK 16
#define AROW 24            // fp16 units per A smem row (16 + 8 pad) = 48B
#define BROW 136           // fp16 units per B smem row (128 + 8 pad) = 272B
#define ASZB (BM * AROW * 2)        // 6144 B
#define BSZB (BK * BROW * 2)        // 4352 B
#define STG  (ASZB + BSZB)          // 10496 B
#define NSTAGE 4
#define GEMM_SMEM (NSTAGE * STG)    // 41984 B

__device__ __forceinline__ void cp16(unsigned dst, const void* src) {
    asm volatile("cp.async.cg.shared.global [%0], [%1], 16;\n"
                 :: "r"(dst), "l"(src) : "memory");
}
__device__ __forceinline__ void cp_commit() {
    asm volatile("cp.async.commit_group;\n" ::: "memory");
}
__device__ __forceinline__ void ldsm4(unsigned* r, unsigned addr) {
    asm volatile("ldmatrix.sync.aligned.m8n8.x4.shared.b16 {%0,%1,%2,%3}, [%4];"
                 : "=r"(r[0]), "=r"(r[1]), "=r"(r[2]), "=r"(r[3]) : "r"(addr));
}
__device__ __forceinline__ void ldsm4t(unsigned* r, unsigned addr) {
    asm volatile("ldmatrix.sync.aligned.m8n8.x4.trans.shared.b16 {%0,%1,%2,%3}, [%4];"
                 : "=r"(r[0]), "=r"(r[1]), "=r"(r[2]), "=r"(r[3]) : "r"(addr));
}

template <int EPI>
__global__ __launch_bounds__(256, 2) void gemm_k(const __half* __restrict__ A,
                                                 const __half* __restrict__ Bm,
                                                 const float* __restrict__ bias,
                                                 const float* __restrict__ res,
                                                 void* __restrict__ Cv,
                                                 int M, int N, int K) {
    extern __shared__ char smc[];
    unsigned smem_base = (unsigned)__cvta_generic_to_shared(smc);

    int tid  = threadIdx.x;
    int lane = tid & 31;
    int wid  = tid >> 5;
    int warp_m = wid & 1;
    int warp_n = wid >> 1;
    int bm = blockIdx.y * BM;
    int bn = blockIdx.x * BN;
    int grp = lane >> 2;
    int tig = lane & 3;

    int am = tid >> 1, ah = tid & 1;
    const __half* aS = A + (size_t)(bm + am) * K + ah * 8;
    unsigned aO = (unsigned)(am * AROW + ah * 8) * 2u;
    int bk = tid >> 4, bn8 = tid & 15;
    const __half* bS = Bm + (size_t)bk * N + bn + bn8 * 8;
    unsigned bO = (unsigned)ASZB + (unsigned)(bk * BROW + bn8 * 8) * 2u;

    auto issue = [&](int t) {
        unsigned s = smem_base + (unsigned)(t % NSTAGE) * STG;
        cp16(s + aO, aS + (size_t)t * BK);
        cp16(s + bO, bS + (size_t)t * BK * N);
        cp_commit();
    };

    unsigned aL = (unsigned)(((warp_m * 64 + (lane & 15)) * AROW + (lane >> 4) * 8) * 2);
    unsigned bL = (unsigned)ASZB +
                  (unsigned)(((lane & 15) * BROW + warp_n * 32 + (lane >> 4) * 8) * 2);

    float acc[4][4][4];
    #pragma unroll
    for (int i = 0; i < 4; ++i)
        #pragma unroll
        for (int j = 0; j < 4; ++j)
            #pragma unroll
            for (int r = 0; r < 4; ++r) acc[i][j][r] = 0.f;

    int ntiles = K / BK;
    issue(0); issue(1); issue(2);

    for (int t = 0; t < ntiles; ++t) {
        if (t + 3 < ntiles) {
            issue(t + 3);
            asm volatile("cp.async.wait_group %0;\n" :: "n"(3));
        } else if (t + 2 < ntiles) {
            asm volatile("cp.async.wait_group %0;\n" :: "n"(2));
        } else if (t + 1 < ntiles) {
            asm volatile("cp.async.wait_group %0;\n" :: "n"(1));
        } else {
            asm volatile("cp.async.wait_group %0;\n" :: "n"(0));
        }
        __syncthreads();

        unsigned base = smem_base + (unsigned)(t % NSTAGE) * STG;

        unsigned af[4][4], bfr[2][4];
        #pragma unroll
        for (int mi = 0; mi < 4; ++mi)
            ldsm4(af[mi], base + aL + mi * 16 * AROW * 2);
        #pragma unroll
        for (int nb = 0; nb < 2; ++nb)
            ldsm4t(bfr[nb], base + bL + nb * 16 * 2);

        #pragma unroll
        for (int mi = 0; mi < 4; ++mi)
            #pragma unroll
            for (int ni = 0; ni < 4; ++ni) {
                unsigned b0 = bfr[ni >> 1][(ni & 1) * 2 + 0];
                unsigned b1 = bfr[ni >> 1][(ni & 1) * 2 + 1];
                asm volatile(
                    "mma.sync.aligned.m16n8k16.row.col.f32.f16.f16.f32 "
                    "{%0,%1,%2,%3}, {%4,%5,%6,%7}, {%8,%9}, {%0,%1,%2,%3};"
                    : "+f"(acc[mi][ni][0]), "+f"(acc[mi][ni][1]),
                      "+f"(acc[mi][ni][2]), "+f"(acc[mi][ni][3])
                    : "r"(af[mi][0]), "r"(af[mi][1]),
                      "r"(af[mi][2]), "r"(af[mi][3]),
                      "r"(b0), "r"(b1));
            }
        __syncthreads();
    }

    // epilogue
    #pragma unroll
    for (int mi = 0; mi < 4; ++mi) {
        #pragma unroll
        for (int rr = 0; rr < 2; ++rr) {
            int r = bm + warp_m * 64 + mi * 16 + grp + rr * 8;
            #pragma unroll
            for (int ni = 0; ni < 4; ++ni) {
                int c = bn + warp_n * 32 + ni * 8 + 2 * tig;
                float v0 = acc[mi][ni][rr * 2 + 0];
                float v1 = acc[mi][ni][rr * 2 + 1];
                if (EPI == 2 || EPI == 3) { v0 += bias[c]; v1 += bias[c + 1]; }
                if (EPI == 2)             { v0 = gelu_f(v0); v1 = gelu_f(v1); }
                if (EPI == 1 || EPI == 3) {
                    const float* rp = res + (size_t)r * N + c;
                    v0 += rp[0]; v1 += rp[1];
                }
                if (EPI == 2) {
                    __half2 o;
                    o.x = __float2half_rn(v0);
                    o.y = __float2half_rn(v1);
                    *(__half2*)((__half*)Cv + (size_t)r * N + c) = o;
                } else {
                    float2 o2; o2.x = v0; o2.y = v1;
                    *(float2*)((float*)Cv + (size_t)r * N + c) = o2;
                }
            }
        }
    }
}

// ---------------- Flash attention: 64q x 64k tiles, fp32, fp16 out ---------
#define APAD 68

__global__ __launch_bounds__(256, 3) void attn_k(const float* __restrict__ qkv,
                                                 __half* __restrict__ y) {
    extern __shared__ float sm[];
    float* Qs = sm;
    float* Ks = Qs + 64 * APAD;
    float* Vs = Ks + 64 * APAD;
    float* Ps = Vs + 64 * APAD;

    int bh = blockIdx.y;
    int b  = bh / NH;
    int h  = bh % NH;
    int qt = gridDim.x - 1 - blockIdx.x;
    int q0 = qt * 64;

    int tid = threadIdx.x;
    int tx = tid & 15, ty = tid >> 4;

    const float* base = qkv + (size_t)b * TSEQ * (3 * CDIM) + h * HDIM;

    for (int idx = tid; idx < 64 * 16; idx += 256) {
        int qq = idx >> 4, d4 = idx & 15;
        float4 v = *(const float4*)(base + (size_t)(q0 + qq) * (3 * CDIM) + d4 * 4);
        Qs[(d4 * 4 + 0) * APAD + qq] = v.x * 0.125f;
        Qs[(d4 * 4 + 1) * APAD + qq] = v.y * 0.125f;
        Qs[(d4 * 4 + 2) * APAD + qq] = v.z * 0.125f;
        Qs[(d4 * 4 + 3) * APAD + qq] = v.w * 0.125f;
    }

    float m_i[4], l_i[4], o[4][4];
    #pragma unroll
    for (int i = 0; i < 4; ++i) {
        m_i[i] = -1e30f; l_i[i] = 0.f;
        #pragma unroll
        for (int j = 0; j < 4; ++j) o[i][j] = 0.f;
    }

    int ntiles = qt + 1;
    for (int kt = 0; kt < ntiles; ++kt) {
        int k0 = kt * 64;
        __syncthreads();

        for (int idx = tid; idx < 64 * 16; idx += 256) {
            int kk = idx >> 4, d4 = idx & 15;
            const float* rp = base + (size_t)(k0 + kk) * (3 * CDIM);
            float4 kv = *(const float4*)(rp + CDIM + d4 * 4);
            Ks[(d4 * 4 + 0) * APAD + kk] = kv.x;
            Ks[(d4 * 4 + 1) * APAD + kk] = kv.y;
            Ks[(d4 * 4 + 2) * APAD + kk] = kv.z;
            Ks[(d4 * 4 + 3) * APAD + kk] = kv.w;
            float4 vv = *(const float4*)(rp + 2 * CDIM + d4 * 4);
            *(float4*)&Vs[kk * APAD + d4 * 4] = vv;
        }
        __syncthreads();

        float s[4][4];
        #pragma unroll
        for (int i = 0; i < 4; ++i)
            #pragma unroll
            for (int j = 0; j < 4; ++j) s[i][j] = 0.f;

        #pragma unroll 8
        for (int d = 0; d < HDIM; ++d) {
            float4 aq = *(const float4*)&Qs[d * APAD + ty * 4];
            float4 bk = *(const float4*)&Ks[d * APAD + tx * 4];
            float ar[4] = {aq.x, aq.y, aq.z, aq.w};
            float br[4] = {bk.x, bk.y, bk.z, bk.w};
            #pragma unroll
            for (int i = 0; i < 4; ++i)
                #pragma unroll
                for (int j = 0; j < 4; ++j)
                    s[i][j] += ar[i] * br[j];
        }

        if (kt == qt) {
            #pragma unroll
            for (int i = 0; i < 4; ++i) {
                int qg = q0 + ty * 4 + i;
                #pragma unroll
                for (int j = 0; j < 4; ++j)
                    if (k0 + tx * 4 + j > qg) s[i][j] = -1e30f;
            }
        }

        #pragma unroll
        for (int i = 0; i < 4; ++i) {
            float mt = fmaxf(fmaxf(s[i][0], s[i][1]), fmaxf(s[i][2], s[i][3]));
            #pragma unroll
            for (int off = 1; off < 16; off <<= 1)
                mt = fmaxf(mt, __shfl_xor_sync(0xffffffffu, mt, off));
            float mn   = fmaxf(m_i[i], mt);
            float corr = __expf(m_i[i] - mn);
            m_i[i] = mn;
            float rs = 0.f;
            #pragma unroll
            for (int j = 0; j < 4; ++j) {
                s[i][j] = __expf(s[i][j] - mn);
                rs += s[i][j];
            }
            #pragma unroll
            for (int off = 1; off < 16; off <<= 1)
                rs += __shfl_xor_sync(0xffffffffu, rs, off);
            l_i[i] = l_i[i] * corr + rs;
            #pragma unroll
            for (int j = 0; j < 4; ++j) o[i][j] *= corr;
        }

        #pragma unroll
        for (int i = 0; i < 4; ++i)
            #pragma unroll
            for (int j = 0; j < 4; ++j)
                Ps[(tx * 4 + j) * APAD + ty * 4 + i] = s[i][j];
        __syncthreads();

        #pragma unroll 8
        for (int k = 0; k < 64; ++k) {
            float4 ap = *(const float4*)&Ps[k * APAD + ty * 4];
            float4 bv = *(const float4*)&Vs[k * APAD + tx * 4];
            float ar[4] = {ap.x, ap.y, ap.z, ap.w};
            float br[4] = {bv.x, bv.y, bv.z, bv.w};
            #pragma unroll
            for (int i = 0; i < 4; ++i)
                #pragma unroll
                for (int j = 0; j < 4; ++j)
                    o[i][j] += ar[i] * br[j];
        }
    }

    #pragma unroll
    for (int i = 0; i < 4; ++i) {
        float inv_l = 1.f / l_i[i];
        int qg = q0 + ty * 4 + i;
        Pack4 p;
        p.h[0] = __float2half_rn(o[i][0] * inv_l);
        p.h[1] = __float2half_rn(o[i][1] * inv_l);
        p.h[2] = __float2half_rn(o[i][2] * inv_l);
        p.h[3] = __float2half_rn(o[i][3] * inv_l);
        *(uint2*)(y + (size_t)(b * TSEQ + qg) * CDIM + h * HDIM + tx * 4) = p.u;
    }
}

// ---------------- launch --------------------------------------------------
extern "C" void kernel_launch(void* const* d_in, const int* in_sizes, int n_in,
                              void* d_out, int out_size) {
    const float* x      = (const float*)d_in[0];
    const float* ln1_g  = (const float*)d_in[1];
    const float* ln1_b  = (const float*)d_in[2];
    const float* w_qkv  = (const float*)d_in[3];
    const float* w_o    = (const float*)d_in[4];
    const float* ln2_g  = (const float*)d_in[5];
    const float* ln2_b  = (const float*)d_in[6];
    const float* w_fc   = (const float*)d_in[7];
    const float* b_fc   = (const float*)d_in[8];
    const float* w_proj = (const float*)d_in[9];
    const float* b_proj = (const float*)d_in[10];
    float* out = (float*)d_out;

    __half *lnh, *atth, *hh, *wqkv_h, *wo_h, *wfc_h, *wproj_h;
    float *qkv, *x1;
    cudaGetSymbolAddress((void**)&lnh,  g_lnh);
    cudaGetSymbolAddress((void**)&qkv,  g_qkv);
    cudaGetSymbolAddress((void**)&atth, g_atth);
    cudaGetSymbolAddress((void**)&x1,   g_x1);
    cudaGetSymbolAddress((void**)&hh,   g_hh);
    cudaGetSymbolAddress((void**)&wqkv_h,  g_wqkv_h);
    cudaGetSymbolAddress((void**)&wo_h,    g_wo_h);
    cudaGetSymbolAddress((void**)&wfc_h,   g_wfc_h);
    cudaGetSymbolAddress((void**)&wproj_h, g_wproj_h);

    static int smem_set = 0;
    const int ATT_SMEM = 4 * 64 * APAD * 4;
    if (!smem_set) {
        cudaFuncSetAttribute(attn_k, cudaFuncAttributeMaxDynamicSharedMemorySize, ATT_SMEM);
        cudaFuncSetAttribute(gemm_k<0>, cudaFuncAttributeMaxDynamicSharedMemorySize, GEMM_SMEM);
        cudaFuncSetAttribute(gemm_k<1>, cudaFuncAttributeMaxDynamicSharedMemorySize, GEMM_SMEM);
        cudaFuncSetAttribute(gemm_k<2>, cudaFuncAttributeMaxDynamicSharedMemorySize, GEMM_SMEM);
        cudaFuncSetAttribute(gemm_k<3>, cudaFuncAttributeMaxDynamicSharedMemorySize, GEMM_SMEM);
        smem_set = 1;
    }

    // weights -> fp16
    roundh_k<<<(CDIM * 3 * CDIM / 4 + 255) / 256, 256>>>(w_qkv,  wqkv_h,  CDIM * 3 * CDIM / 4);
    roundh_k<<<(CDIM * CDIM / 4 + 255) / 256, 256>>>(w_o,    wo_h,    CDIM * CDIM / 4);
    roundh_k<<<(CDIM * DFF / 4 + 255) / 256, 256>>>(w_fc,   wfc_h,   CDIM * DFF / 4);
    roundh_k<<<(DFF * CDIM / 4 + 255) / 256, 256>>>(w_proj, wproj_h, DFF * CDIM / 4);

    ln_k<<<ROWS, 256>>>(x, ln1_g, ln1_b, lnh);
    gemm_k<0><<<dim3(3 * CDIM / BN, ROWS / BM), 256, GEMM_SMEM>>>(lnh, wqkv_h, nullptr, nullptr,
                                                                  qkv, ROWS, 3 * CDIM, CDIM);
    attn_k<<<dim3(TSEQ / 64, NB * NH), 256, ATT_SMEM>>>(qkv, atth);
    gemm_k<1><<<dim3(CDIM / BN, ROWS / BM), 256, GEMM_SMEM>>>(atth, wo_h, nullptr, x,
                                                              x1, ROWS, CDIM, CDIM);
    ln_k<<<ROWS, 256>>>(x1, ln2_g, ln2_b, lnh);
    gemm_k<2><<<dim3(DFF / BN, ROWS / BM), 256, GEMM_SMEM>>>(lnh, wfc_h, b_fc, nullptr,
                                                             hh, ROWS, DFF, CDIM);
    gemm_k<3><<<dim3(CDIM / BN, ROWS / BM), 256, GEMM_SMEM>>>(hh, wproj_h, b_proj, x1,
                                                              out, ROWS, CDIM, DFF);
}

// round 7
// speedup vs baseline: 12.3518x; 2.1493x over previous
#include <cuda_runtime.h>
#include <cuda_fp16.h>
#include <math.h>

#define TSEQ 2048
#define NB   2
#define CDIM 768
#define NH   12
#define HDIM 64
#define DFF  3072
#define ROWS (NB * TSEQ)   // 4096

// ---------------- scratch (device globals: allocation-free) ----------------
__device__ __half g_lnh [ROWS * CDIM];        // ln output (GEMM A)
__device__ __half g_qkvh[ROWS * 3 * CDIM];    // qkv fp16
__device__ __half g_atth[ROWS * CDIM];        // attn output (GEMM A)
__device__ float  g_x1  [ROWS * CDIM];        // residual stream fp32
__device__ __half g_hh  [ROWS * DFF];         // gelu output (GEMM A)
// fp16 weights
__device__ __half g_wqkv_h [CDIM * 3 * CDIM];
__device__ __half g_wo_h   [CDIM * CDIM];
__device__ __half g_wfc_h  [CDIM * DFF];
__device__ __half g_wproj_h[DFF * CDIM];

__device__ __forceinline__ float gelu_f(float v) {
    return 0.5f * v * (1.0f + erff(v * 0.70710678118654752f));
}

union Pack4 { __half h[4]; uint2 u; };

__device__ __forceinline__ void cp16(unsigned dst, const void* src) {
    asm volatile("cp.async.cg.shared.global [%0], [%1], 16;\n"
                 :: "r"(dst), "l"(src) : "memory");
}
__device__ __forceinline__ void cp_commit() {
    asm volatile("cp.async.commit_group;\n" ::: "memory");
}
__device__ __forceinline__ void ldsm4(unsigned* r, unsigned addr) {
    asm volatile("ldmatrix.sync.aligned.m8n8.x4.shared.b16 {%0,%1,%2,%3}, [%4];"
                 : "=r"(r[0]), "=r"(r[1]), "=r"(r[2]), "=r"(r[3]) : "r"(addr));
}
__device__ __forceinline__ void ldsm4t(unsigned* r, unsigned addr) {
    asm volatile("ldmatrix.sync.aligned.m8n8.x4.trans.shared.b16 {%0,%1,%2,%3}, [%4];"
                 : "=r"(r[0]), "=r"(r[1]), "=r"(r[2]), "=r"(r[3]) : "r"(addr));
}
__device__ __forceinline__ void mma16816(float* c, const unsigned* a,
                                         unsigned b0, unsigned b1) {
    asm volatile(
        "mma.sync.aligned.m16n8k16.row.col.f32.f16.f16.f32 "
        "{%0,%1,%2,%3}, {%4,%5,%6,%7}, {%8,%9}, {%0,%1,%2,%3};"
        : "+f"(c[0]), "+f"(c[1]), "+f"(c[2]), "+f"(c[3])
        : "r"(a[0]), "r"(a[1]), "r"(a[2]), "r"(a[3]), "r"(b0), "r"(b1));
}
__device__ __forceinline__ unsigned f22h2(float x, float y) {
    __half2 h = __floats2half2_rn(x, y);
    return *(unsigned*)&h;
}

// ---------------- weight fp32 -> fp16 (once per launch) --------------------
__global__ __launch_bounds__(256) void roundh_k(const float* __restrict__ in,
                                                __half* __restrict__ out,
                                                int n4) {
    int i = blockIdx.x * 256 + threadIdx.x;
    if (i < n4) {
        float4 v = ((const float4*)in)[i];
        Pack4 p;
        p.h[0] = __float2half_rn(v.x); p.h[1] = __float2half_rn(v.y);
        p.h[2] = __float2half_rn(v.z); p.h[3] = __float2half_rn(v.w);
        ((uint2*)out)[i] = p.u;
    }
}

// ---------------- LayerNorm (fp32 in, fp16 out) ----------------------------
__global__ __launch_bounds__(256) void ln_k(const float* __restrict__ xin,
                                            const float* __restrict__ g,
                                            const float* __restrict__ b,
                                            __half* __restrict__ out) {
    int row = blockIdx.x;
    int tid = threadIdx.x;
    const float* xr = xin + (size_t)row * CDIM;

    float v0 = xr[tid], v1 = xr[tid + 256], v2 = xr[tid + 512];
    float s  = v0 + v1 + v2;
    float ss = v0 * v0 + v1 * v1 + v2 * v2;

    #pragma unroll
    for (int off = 16; off > 0; off >>= 1) {
        s  += __shfl_xor_sync(0xffffffffu, s,  off);
        ss += __shfl_xor_sync(0xffffffffu, ss, off);
    }
    __shared__ float sh_s[8], sh_ss[8];
    int wid = tid >> 5, lane = tid & 31;
    if (lane == 0) { sh_s[wid] = s; sh_ss[wid] = ss; }
    __syncthreads();
    float ts = 0.f, tss = 0.f;
    #pragma unroll
    for (int i = 0; i < 8; ++i) { ts += sh_s[i]; tss += sh_ss[i]; }

    const float inv = 1.0f / (float)CDIM;
    float mu   = ts * inv;
    float var  = tss * inv - mu * mu;
    float rstd = rsqrtf(var + 1e-5f);

    __half* orow = out + (size_t)row * CDIM;
    orow[tid      ] = __float2half_rn((v0 - mu) * rstd * g[tid      ] + b[tid      ]);
    orow[tid + 256] = __float2half_rn((v1 - mu) * rstd * g[tid + 256] + b[tid + 256]);
    orow[tid + 512] = __float2half_rn((v2 - mu) * rstd * g[tid + 512] + b[tid + 512]);
}

// ---------------- fp16 tensor-core GEMM, cp.async 4-stage, ldmatrix --------
// EPI: 0 none(f32), 1 +res(f32), 2 +bias+GELU(fp16), 3 +bias+res(f32), 4 none(fp16)
#define BM 128
#define BN 128
#define BK 16
#define AROW 24
#define BROW 136
#define ASZB (BM * AROW * 2)
#define BSZB (BK * BROW * 2)
#define STG  (ASZB + BSZB)
#define NSTAGE 4
#define GEMM_SMEM (NSTAGE * STG)

template <int EPI>
__global__ __launch_bounds__(256, 2) void gemm_k(const __half* __restrict__ A,
                                                 const __half* __restrict__ Bm,
                                                 const float* __restrict__ bias,
                                                 const float* __restrict__ res,
                                                 void* __restrict__ Cv,
                                                 int M, int N, int K) {
    extern __shared__ char smc[];
    unsigned smem_base = (unsigned)__cvta_generic_to_shared(smc);

    int tid  = threadIdx.x;
    int lane = tid & 31;
    int wid  = tid >> 5;
    int warp_m = wid & 1;
    int warp_n = wid >> 1;
    int bm = blockIdx.y * BM;
    int bn = blockIdx.x * BN;
    int grp = lane >> 2;
    int tig = lane & 3;

    int am = tid >> 1, ah = tid & 1;
    const __half* aS = A + (size_t)(bm + am) * K + ah * 8;
    unsigned aO = (unsigned)(am * AROW + ah * 8) * 2u;
    int bk = tid >> 4, bn8 = tid & 15;
    const __half* bS = Bm + (size_t)bk * N + bn + bn8 * 8;
    unsigned bO = (unsigned)ASZB + (unsigned)(bk * BROW + bn8 * 8) * 2u;

    auto issue = [&](int t) {
        unsigned s = smem_base + (unsigned)(t % NSTAGE) * STG;
        cp16(s + aO, aS + (size_t)t * BK);
        cp16(s + bO, bS + (size_t)t * BK * N);
        cp_commit();
    };

    unsigned aL = (unsigned)(((warp_m * 64 + (lane & 15)) * AROW + (lane >> 4) * 8) * 2);
    unsigned bL = (unsigned)ASZB +
                  (unsigned)(((lane & 15) * BROW + warp_n * 32 + (lane >> 4) * 8) * 2);

    float acc[4][4][4];
    #pragma unroll
    for (int i = 0; i < 4; ++i)
        #pragma unroll
        for (int j = 0; j < 4; ++j)
            #pragma unroll
            for (int r = 0; r < 4; ++r) acc[i][j][r] = 0.f;

    int ntiles = K / BK;
    issue(0); issue(1); issue(2);

    for (int t = 0; t < ntiles; ++t) {
        if (t + 3 < ntiles) {
            issue(t + 3);
            asm volatile("cp.async.wait_group %0;\n" :: "n"(3));
        } else if (t + 2 < ntiles) {
            asm volatile("cp.async.wait_group %0;\n" :: "n"(2));
        } else if (t + 1 < ntiles) {
            asm volatile("cp.async.wait_group %0;\n" :: "n"(1));
        } else {
            asm volatile("cp.async.wait_group %0;\n" :: "n"(0));
        }
        __syncthreads();

        unsigned base = smem_base + (unsigned)(t % NSTAGE) * STG;

        unsigned af[4][4], bfr[2][4];
        #pragma unroll
        for (int mi = 0; mi < 4; ++mi)
            ldsm4(af[mi], base + aL + mi * 16 * AROW * 2);
        #pragma unroll
        for (int nb = 0; nb < 2; ++nb)
            ldsm4t(bfr[nb], base + bL + nb * 16 * 2);

        #pragma unroll
        for (int mi = 0; mi < 4; ++mi)
            #pragma unroll
            for (int ni = 0; ni < 4; ++ni)
                mma16816(acc[mi][ni], af[mi],
                         bfr[ni >> 1][(ni & 1) * 2 + 0],
                         bfr[ni >> 1][(ni & 1) * 2 + 1]);
        __syncthreads();
    }

    #pragma unroll
    for (int mi = 0; mi < 4; ++mi) {
        #pragma unroll
        for (int rr = 0; rr < 2; ++rr) {
            int r = bm + warp_m * 64 + mi * 16 + grp + rr * 8;
            #pragma unroll
            for (int ni = 0; ni < 4; ++ni) {
                int c = bn + warp_n * 32 + ni * 8 + 2 * tig;
                float v0 = acc[mi][ni][rr * 2 + 0];
                float v1 = acc[mi][ni][rr * 2 + 1];
                if (EPI == 2 || EPI == 3) { v0 += bias[c]; v1 += bias[c + 1]; }
                if (EPI == 2)             { v0 = gelu_f(v0); v1 = gelu_f(v1); }
                if (EPI == 1 || EPI == 3) {
                    const float* rp = res + (size_t)r * N + c;
                    v0 += rp[0]; v1 += rp[1];
                }
                if (EPI == 2 || EPI == 4) {
                    __half2 o;
                    o.x = __float2half_rn(v0);
                    o.y = __float2half_rn(v1);
                    *(__half2*)((__half*)Cv + (size_t)r * N + c) = o;
                } else {
                    float2 o2; o2.x = v0; o2.y = v1;
                    *(float2*)((float*)Cv + (size_t)r * N + c) = o2;
                }
            }
        }
    }
}

// ---------------- Flash attention: fp16 tensor cores -----------------------
// 8 warps, 128 queries/CTA (16 per warp), 64-key tiles, double-buffered K/V.
// Q in registers as A-frags (pre-scaled 1/8); S fp32 accum; P->fp16 in regs.
#define KVP 72                      // halves per smem row (144 B)
#define Q_HALVES   (128 * KVP)      // 9216
#define KV_STAGE_H (2 * 64 * KVP)   // 9216 halves per stage (K + V)
#define ATT_SMEM   ((Q_HALVES + 2 * KV_STAGE_H) * 2)   // 55296 B

__global__ __launch_bounds__(256, 2) void attn_k(const __half* __restrict__ qkvh,
                                                 __half* __restrict__ y) {
    extern __shared__ __half smh[];
    unsigned smem_b = (unsigned)__cvta_generic_to_shared(smh);
    unsigned kvb    = smem_b + Q_HALVES * 2;

    int bh = blockIdx.y;
    int b  = bh / NH;
    int h  = bh % NH;
    int qt = gridDim.x - 1 - blockIdx.x;   // big tiles first
    int q0 = qt * 128;
    size_t bT = (size_t)b * TSEQ;

    int tid  = threadIdx.x;
    int lane = tid & 31;
    int wid  = tid >> 5;
    int grp  = lane >> 2;
    int tig  = lane & 3;

    // ---- stage Q (128 x 64 halves) ----
    #pragma unroll
    for (int i = 0; i < 4; ++i) {
        int c = i * 256 + tid;          // 0..1023
        int row = c >> 3, col8 = c & 7;
        const __half* src = qkvh + (bT + q0 + row) * (3 * CDIM) + h * HDIM + col8 * 8;
        cp16(smem_b + (unsigned)(row * KVP + col8 * 8) * 2, src);
    }
    cp_commit();

    auto kvissue = [&](int t) {
        int k0 = t * 64;
        unsigned sb = kvb + (unsigned)(t & 1) * (KV_STAGE_H * 2);
        #pragma unroll
        for (int i = 0; i < 4; ++i) {
            int c = i * 256 + tid;      // 0..1023
            int isV = c >> 9;
            int cc = c & 511;
            int row = cc >> 3, col8 = cc & 7;
            const __half* src = qkvh + (bT + k0 + row) * (3 * CDIM)
                                + (1 + isV) * CDIM + h * HDIM + col8 * 8;
            cp16(sb + (unsigned)(isV * (64 * KVP) + row * KVP + col8 * 8) * 2, src);
        }
        cp_commit();
    };

    kvissue(0);
    asm volatile("cp.async.wait_group 0;\n" ::: "memory");
    __syncthreads();

    // ---- Q fragments (4 d-chunks of 16), pre-scaled by 1/8 ----
    unsigned qf[4][4];
    {
        unsigned rowb = smem_b + (unsigned)((wid * 16 + (lane & 15)) * KVP) * 2;
        #pragma unroll
        for (int ch = 0; ch < 4; ++ch) {
            ldsm4(qf[ch], rowb + (unsigned)(ch * 16 + (lane >> 4) * 8) * 2);
            __half2 sc = __floats2half2_rn(0.125f, 0.125f);
            #pragma unroll
            for (int r = 0; r < 4; ++r) {
                __half2 v = *(__half2*)&qf[ch][r];
                v = __hmul2(v, sc);
                qf[ch][r] = *(unsigned*)&v;
            }
        }
    }

    float o[8][4];
    #pragma unroll
    for (int i = 0; i < 8; ++i)
        #pragma unroll
        for (int j = 0; j < 4; ++j) o[i][j] = 0.f;
    float m0 = -1e30f, m1 = -1e30f, l0 = 0.f, l1 = 0.f;

    int r0g = q0 + wid * 16 + grp;     // global row of this thread (low)
    int ntiles = 2 * (qt + 1);

    for (int t = 0; t < ntiles; ++t) {
        if (t + 1 < ntiles) {
            kvissue(t + 1);
            asm volatile("cp.async.wait_group 1;\n" ::: "memory");
        } else {
            asm volatile("cp.async.wait_group 0;\n" ::: "memory");
        }
        __syncthreads();

        int k0 = t * 64;
        unsigned Ksb = kvb + (unsigned)(t & 1) * (KV_STAGE_H * 2);
        unsigned Vsb = Ksb + (unsigned)(64 * KVP) * 2;

        // ---- S = Q K^T ----
        float s[8][4];
        #pragma unroll
        for (int i = 0; i < 8; ++i)
            #pragma unroll
            for (int j = 0; j < 4; ++j) s[i][j] = 0.f;

        int krow = (lane & 7) + ((lane >> 4) << 3);
        int kcol = ((lane >> 3) & 1) << 3;
        #pragma unroll
        for (int ch = 0; ch < 4; ++ch) {
            unsigned kf[4][4];
            #pragma unroll
            for (int p = 0; p < 4; ++p)
                ldsm4(kf[p], Ksb + (unsigned)((p * 16 + krow) * KVP + ch * 16 + kcol) * 2);
            #pragma unroll
            for (int nt = 0; nt < 8; ++nt)
                mma16816(s[nt], qf[ch],
                         kf[nt >> 1][(nt & 1) * 2 + 0],
                         kf[nt >> 1][(nt & 1) * 2 + 1]);
        }

        // ---- causal mask (only near-diagonal tiles) ----
        if (k0 + 63 > r0g + 8) {
            #pragma unroll
            for (int nt = 0; nt < 8; ++nt) {
                int c0 = k0 + nt * 8 + 2 * tig;
                if (c0     > r0g)     s[nt][0] = -1e30f;
                if (c0 + 1 > r0g)     s[nt][1] = -1e30f;
                if (c0     > r0g + 8) s[nt][2] = -1e30f;
                if (c0 + 1 > r0g + 8) s[nt][3] = -1e30f;
            }
        }

        // ---- online softmax ----
        float mx0 = -1e30f, mx1 = -1e30f;
        #pragma unroll
        for (int nt = 0; nt < 8; ++nt) {
            mx0 = fmaxf(mx0, fmaxf(s[nt][0], s[nt][1]));
            mx1 = fmaxf(mx1, fmaxf(s[nt][2], s[nt][3]));
        }
        mx0 = fmaxf(mx0, __shfl_xor_sync(0xffffffffu, mx0, 1));
        mx0 = fmaxf(mx0, __shfl_xor_sync(0xffffffffu, mx0, 2));
        mx1 = fmaxf(mx1, __shfl_xor_sync(0xffffffffu, mx1, 1));
        mx1 = fmaxf(mx1, __shfl_xor_sync(0xffffffffu, mx1, 2));

        float mn0 = fmaxf(m0, mx0), mn1 = fmaxf(m1, mx1);
        float cr0 = __expf(m0 - mn0), cr1 = __expf(m1 - mn1);
        m0 = mn0; m1 = mn1;

        float sum0 = 0.f, sum1 = 0.f;
        #pragma unroll
        for (int nt = 0; nt < 8; ++nt) {
            s[nt][0] = __expf(s[nt][0] - mn0); sum0 += s[nt][0];
            s[nt][1] = __expf(s[nt][1] - mn0); sum0 += s[nt][1];
            s[nt][2] = __expf(s[nt][2] - mn1); sum1 += s[nt][2];
            s[nt][3] = __expf(s[nt][3] - mn1); sum1 += s[nt][3];
        }
        sum0 += __shfl_xor_sync(0xffffffffu, sum0, 1);
        sum0 += __shfl_xor_sync(0xffffffffu, sum0, 2);
        sum1 += __shfl_xor_sync(0xffffffffu, sum1, 1);
        sum1 += __shfl_xor_sync(0xffffffffu, sum1, 2);
        l0 = l0 * cr0 + sum0;
        l1 = l1 * cr1 + sum1;

        #pragma unroll
        for (int nt = 0; nt < 8; ++nt) {
            o[nt][0] *= cr0; o[nt][1] *= cr0;
            o[nt][2] *= cr1; o[nt][3] *= cr1;
        }

        // ---- O += P V ----
        int vrow = (lane & 7) + (((lane >> 3) & 1) << 3);
        int vcol = (lane >> 4) << 3;
        #pragma unroll
        for (int c = 0; c < 4; ++c) {
            unsigned pa[4];
            pa[0] = f22h2(s[2 * c][0],     s[2 * c][1]);
            pa[1] = f22h2(s[2 * c][2],     s[2 * c][3]);
            pa[2] = f22h2(s[2 * c + 1][0], s[2 * c + 1][1]);
            pa[3] = f22h2(s[2 * c + 1][2], s[2 * c + 1][3]);

            unsigned vf[4][4];
            #pragma unroll
            for (int p = 0; p < 4; ++p)
                ldsm4t(vf[p], Vsb + (unsigned)((c * 16 + vrow) * KVP + p * 16 + vcol) * 2);

            #pragma unroll
            for (int dt = 0; dt < 8; ++dt)
                mma16816(o[dt], pa,
                         vf[dt >> 1][(dt & 1) * 2 + 0],
                         vf[dt >> 1][(dt & 1) * 2 + 1]);
        }
        __syncthreads();
    }

    // ---- write O / l (fp16) ----
    float i0 = 1.f / l0, i1 = 1.f / l1;
    __half* y0 = y + (bT + r0g) * CDIM + h * HDIM;
    __half* y1 = y0 + 8 * CDIM;
    #pragma unroll
    for (int dt = 0; dt < 8; ++dt) {
        __half2 a, bb;
        a.x  = __float2half_rn(o[dt][0] * i0);
        a.y  = __float2half_rn(o[dt][1] * i0);
        bb.x = __float2half_rn(o[dt][2] * i1);
        bb.y = __float2half_rn(o[dt][3] * i1);
        *(__half2*)(y0 + dt * 8 + 2 * tig) = a;
        *(__half2*)(y1 + dt * 8 + 2 * tig) = bb;
    }
}

// ---------------- launch --------------------------------------------------
extern "C" void kernel_launch(void* const* d_in, const int* in_sizes, int n_in,
                              void* d_out, int out_size) {
    const float* x      = (const float*)d_in[0];
    const float* ln1_g  = (const float*)d_in[1];
    const float* ln1_b  = (const float*)d_in[2];
    const float* w_qkv  = (const float*)d_in[3];
    const float* w_o    = (const float*)d_in[4];
    const float* ln2_g  = (const float*)d_in[5];
    const float* ln2_b  = (const float*)d_in[6];
    const float* w_fc   = (const float*)d_in[7];
    const float* b_fc   = (const float*)d_in[8];
    const float* w_proj = (const float*)d_in[9];
    const float* b_proj = (const float*)d_in[10];
    float* out = (float*)d_out;

    __half *lnh, *qkvh, *atth, *hh, *wqkv_h, *wo_h, *wfc_h, *wproj_h;
    float *x1;
    cudaGetSymbolAddress((void**)&lnh,  g_lnh);
    cudaGetSymbolAddress((void**)&qkvh, g_qkvh);
    cudaGetSymbolAddress((void**)&atth, g_atth);
    cudaGetSymbolAddress((void**)&x1,   g_x1);
    cudaGetSymbolAddress((void**)&hh,   g_hh);
    cudaGetSymbolAddress((void**)&wqkv_h,  g_wqkv_h);
    cudaGetSymbolAddress((void**)&wo_h,    g_wo_h);
    cudaGetSymbolAddress((void**)&wfc_h,   g_wfc_h);
    cudaGetSymbolAddress((void**)&wproj_h, g_wproj_h);

    static int smem_set = 0;
    if (!smem_set) {
        cudaFuncSetAttribute(attn_k, cudaFuncAttributeMaxDynamicSharedMemorySize, ATT_SMEM);
        cudaFuncSetAttribute(gemm_k<1>, cudaFuncAttributeMaxDynamicSharedMemorySize, GEMM_SMEM);
        cudaFuncSetAttribute(gemm_k<2>, cudaFuncAttributeMaxDynamicSharedMemorySize, GEMM_SMEM);
        cudaFuncSetAttribute(gemm_k<3>, cudaFuncAttributeMaxDynamicSharedMemorySize, GEMM_SMEM);
        cudaFuncSetAttribute(gemm_k<4>, cudaFuncAttributeMaxDynamicSharedMemorySize, GEMM_SMEM);
        smem_set = 1;
    }

    // weights -> fp16
    roundh_k<<<(CDIM * 3 * CDIM / 4 + 255) / 256, 256>>>(w_qkv,  wqkv_h,  CDIM * 3 * CDIM / 4);
    roundh_k<<<(CDIM * CDIM / 4 + 255) / 256, 256>>>(w_o,    wo_h,    CDIM * CDIM / 4);
    roundh_k<<<(CDIM * DFF / 4 + 255) / 256, 256>>>(w_fc,   wfc_h,   CDIM * DFF / 4);
    roundh_k<<<(DFF * CDIM / 4 + 255) / 256, 256>>>(w_proj, wproj_h, DFF * CDIM / 4);

    ln_k<<<ROWS, 256>>>(x, ln1_g, ln1_b, lnh);
    gemm_k<4><<<dim3(3 * CDIM / BN, ROWS / BM), 256, GEMM_SMEM>>>(lnh, wqkv_h, nullptr, nullptr,
                                                                  qkvh, ROWS, 3 * CDIM, CDIM);
    attn_k<<<dim3(TSEQ / 128, NB * NH), 256, ATT_SMEM>>>(qkvh, atth);
    gemm_k<1><<<dim3(CDIM / BN, ROWS / BM), 256, GEMM_SMEM>>>(atth, wo_h, nullptr, x,
                                                              x1, ROWS, CDIM, CDIM);
    ln_k<<<ROWS, 256>>>(x1, ln2_g, ln2_b, lnh);
    gemm_k<2><<<dim3(DFF / BN, ROWS / BM), 256, GEMM_SMEM>>>(lnh, wfc_h, b_fc, nullptr,
                                                             hh, ROWS, DFF, CDIM);
    gemm_k<3><<<dim3(CDIM / BN, ROWS / BM), 256, GEMM_SMEM>>>(hh, wproj_h, b_proj, x1,
                                                              out, ROWS, CDIM, DFF);
}

// round 9
// speedup vs baseline: 14.3918x; 1.1652x over previous
#include <cuda_runtime.h>
#include <cuda_fp16.h>
#include <math.h>

#define TSEQ 2048
#define NB   2
#define CDIM 768
#define NH   12
#define HDIM 64
#define DFF  3072
#define ROWS (NB * TSEQ)   // 4096

// ---------------- scratch (device globals: allocation-free) ----------------
__device__ __half g_lnh [ROWS * CDIM];
__device__ __half g_qkvh[ROWS * 3 * CDIM];
__device__ __half g_atth[ROWS * CDIM];
__device__ float  g_x1  [ROWS * CDIM];
__device__ __half g_hh  [ROWS * DFF];
// fp16 weights [K][N] (original layout)
__device__ __half g_wqkv_h [CDIM * 3 * CDIM];
__device__ __half g_wo_h   [CDIM * CDIM];
__device__ __half g_wfc_h  [CDIM * DFF];
__device__ __half g_wproj_h[DFF * CDIM];

__device__ __forceinline__ float gelu_f(float v) {
    return 0.5f * v * (1.0f + erff(v * 0.70710678118654752f));
}

union Pack4 { __half h[4]; uint2 u; };

__device__ __forceinline__ void cp16(unsigned dst, const void* src) {
    asm volatile("cp.async.cg.shared.global [%0], [%1], 16;\n"
                 :: "r"(dst), "l"(src) : "memory");
}
__device__ __forceinline__ void cp_commit() {
    asm volatile("cp.async.commit_group;\n" ::: "memory");
}
__device__ __forceinline__ void ldsm4(unsigned* r, unsigned addr) {
    asm volatile("ldmatrix.sync.aligned.m8n8.x4.shared.b16 {%0,%1,%2,%3}, [%4];"
                 : "=r"(r[0]), "=r"(r[1]), "=r"(r[2]), "=r"(r[3]) : "r"(addr));
}
__device__ __forceinline__ void ldsm4t(unsigned* r, unsigned addr) {
    asm volatile("ldmatrix.sync.aligned.m8n8.x4.trans.shared.b16 {%0,%1,%2,%3}, [%4];"
                 : "=r"(r[0]), "=r"(r[1]), "=r"(r[2]), "=r"(r[3]) : "r"(addr));
}
__device__ __forceinline__ void mma16816(float* c, const unsigned* a,
                                         unsigned b0, unsigned b1) {
    asm volatile(
        "mma.sync.aligned.m16n8k16.row.col.f32.f16.f16.f32 "
        "{%0,%1,%2,%3}, {%4,%5,%6,%7}, {%8,%9}, {%0,%1,%2,%3};"
        : "+f"(c[0]), "+f"(c[1]), "+f"(c[2]), "+f"(c[3])
        : "r"(a[0]), "r"(a[1]), "r"(a[2]), "r"(a[3]), "r"(b0), "r"(b1));
}
__device__ __forceinline__ unsigned f22h2(float x, float y) {
    __half2 h = __floats2half2_rn(x, y);
    return *(unsigned*)&h;
}

// ---------------- weight fp32 -> fp16 (once per launch) --------------------
__global__ __launch_bounds__(256) void roundh_k(const float* __restrict__ in,
                                                __half* __restrict__ out,
                                                int n4) {
    int i = blockIdx.x * 256 + threadIdx.x;
    if (i < n4) {
        float4 v = ((const float4*)in)[i];
        Pack4 p;
        p.h[0] = __float2half_rn(v.x); p.h[1] = __float2half_rn(v.y);
        p.h[2] = __float2half_rn(v.z); p.h[3] = __float2half_rn(v.w);
        ((uint2*)out)[i] = p.u;
    }
}

// ---------------- LayerNorm (fp32 in, fp16 out) ----------------------------
__global__ __launch_bounds__(256) void ln_k(const float* __restrict__ xin,
                                            const float* __restrict__ g,
                                            const float* __restrict__ b,
                                            __half* __restrict__ out) {
    int row = blockIdx.x;
    int tid = threadIdx.x;
    const float* xr = xin + (size_t)row * CDIM;

    float v0 = xr[tid], v1 = xr[tid + 256], v2 = xr[tid + 512];
    float s  = v0 + v1 + v2;
    float ss = v0 * v0 + v1 * v1 + v2 * v2;

    #pragma unroll
    for (int off = 16; off > 0; off >>= 1) {
        s  += __shfl_xor_sync(0xffffffffu, s,  off);
        ss += __shfl_xor_sync(0xffffffffu, ss, off);
    }
    __shared__ float sh_s[8], sh_ss[8];
    int wid = tid >> 5, lane = tid & 31;
    if (lane == 0) { sh_s[wid] = s; sh_ss[wid] = ss; }
    __syncthreads();
    float ts = 0.f, tss = 0.f;
    #pragma unroll
    for (int i = 0; i < 8; ++i) { ts += sh_s[i]; tss += sh_ss[i]; }

    const float inv = 1.0f / (float)CDIM;
    float mu   = ts * inv;
    float var  = tss * inv - mu * mu;
    float rstd = rsqrtf(var + 1e-5f);

    __half* orow = out + (size_t)row * CDIM;
    orow[tid      ] = __float2half_rn((v0 - mu) * rstd * g[tid      ] + b[tid      ]);
    orow[tid + 256] = __float2half_rn((v1 - mu) * rstd * g[tid + 256] + b[tid + 256]);
    orow[tid + 512] = __float2half_rn((v2 - mu) * rstd * g[tid + 512] + b[tid + 512]);
}

// ---------------- fp16 GEMM: 4 warps, 64x64 warp tiles, BK=32 --------------
// C[M,N] = A[M,K] @ B[K,N] (+epilogue). A,B fp16, accum fp32.
// CTA 128x128x32, 128 threads (2Mx2N warps), warp tile 64x64, m16n8k16.
// EPI: 1 +res(f32), 2 +bias+GELU(fp16), 3 +bias+res(f32), 4 none(fp16)
#define BM 128
#define BN 128
#define BK 32
#define AROW2 40     // halves per A smem row (32 + 8 pad) = 80 B
#define BROW2 136    // halves per B smem row (128 + 8 pad) = 272 B
#define ASZ2 (BM * AROW2 * 2)     // 10240 B
#define BSZ2 (BK * BROW2 * 2)     // 8704 B
#define STG2 (ASZ2 + BSZ2)        // 18944 B
#define NSTG 3
#define GEMM_SMEM (NSTG * STG2)   // 56832 B

template <int EPI>
__global__ __launch_bounds__(128, 2) void gemm_k(const __half* __restrict__ A,
                                                 const __half* __restrict__ Bm,
                                                 const float* __restrict__ bias,
                                                 const float* __restrict__ res,
                                                 void* __restrict__ Cv,
                                                 int M, int N, int K) {
    extern __shared__ char smc[];
    unsigned smem_base = (unsigned)__cvta_generic_to_shared(smc);

    int tid  = threadIdx.x;
    int lane = tid & 31;
    int wid  = tid >> 5;          // 0..3
    int warp_m = wid & 1;
    int warp_n = wid >> 1;
    int bm = blockIdx.y * BM;
    int bn = blockIdx.x * BN;
    int grp = lane >> 2;
    int tig = lane & 3;

    // staging coords: per thread 4x16B for A, 4x16B for B
    const __half* aP[4]; unsigned aO[4];
    const __half* bP[4]; unsigned bO[4];
    #pragma unroll
    for (int l = 0; l < 4; ++l) {
        int idx = l * 128 + tid;           // 0..511
        int ar = idx >> 2, ac = idx & 3;   // row 0..127, 16B chunk 0..3
        aP[l] = A + (size_t)(bm + ar) * K + ac * 8;
        aO[l] = (unsigned)(ar * AROW2 + ac * 8) * 2u;
        int br = idx >> 4, bc = idx & 15;  // row 0..31, chunk 0..15
        bP[l] = Bm + (size_t)br * N + bn + bc * 8;
        bO[l] = (unsigned)ASZ2 + (unsigned)(br * BROW2 + bc * 8) * 2u;
    }

    auto stage = [&](int t) {
        unsigned s = smem_base + (unsigned)(t % NSTG) * STG2;
        #pragma unroll
        for (int l = 0; l < 4; ++l) {
            cp16(s + aO[l], aP[l] + (size_t)t * BK);
            cp16(s + bO[l], bP[l] + (size_t)t * BK * N);
        }
        cp_commit();
    };

    float acc[4][8][4];
    #pragma unroll
    for (int i = 0; i < 4; ++i)
        #pragma unroll
        for (int j = 0; j < 8; ++j)
            #pragma unroll
            for (int r = 0; r < 4; ++r) acc[i][j][r] = 0.f;

    int ntiles = K / BK;
    stage(0); stage(1);

    // ldmatrix lane bases
    unsigned aLrow = (unsigned)(warp_m * 64 + (lane & 15));
    unsigned aLcol = (unsigned)((lane >> 4) * 8);
    unsigned bLrow = (unsigned)(lane & 15);
    unsigned bLcol = (unsigned)(warp_n * 64 + (lane >> 4) * 8);

    for (int t = 0; t < ntiles; ++t) {
        if (t + 2 < ntiles) {
            stage(t + 2);
            asm volatile("cp.async.wait_group %0;\n" :: "n"(2));
        } else if (t + 1 < ntiles) {
            asm volatile("cp.async.wait_group %0;\n" :: "n"(1));
        } else {
            asm volatile("cp.async.wait_group %0;\n" :: "n"(0));
        }
        __syncthreads();

        unsigned base = smem_base + (unsigned)(t % NSTG) * STG2;

        #pragma unroll
        for (int ks = 0; ks < 2; ++ks) {      // two k16 steps per BK=32
            unsigned af[4][4], bf[4][4];
            #pragma unroll
            for (int mi = 0; mi < 4; ++mi)
                ldsm4(af[mi], base +
                      (unsigned)(((aLrow + mi * 16) * AROW2) + ks * 16 + aLcol) * 2);
            #pragma unroll
            for (int j = 0; j < 4; ++j)
                ldsm4t(bf[j], base + (unsigned)ASZ2 +
                       (unsigned)(((ks * 16 + bLrow) * BROW2) + bLcol + j * 16) * 2);

            #pragma unroll
            for (int mi = 0; mi < 4; ++mi)
                #pragma unroll
                for (int ni = 0; ni < 8; ++ni)
                    mma16816(acc[mi][ni], af[mi],
                             bf[ni >> 1][(ni & 1) * 2 + 0],
                             bf[ni >> 1][(ni & 1) * 2 + 1]);
        }
        __syncthreads();
    }

    // epilogue
    #pragma unroll
    for (int mi = 0; mi < 4; ++mi) {
        #pragma unroll
        for (int rr = 0; rr < 2; ++rr) {
            int r = bm + warp_m * 64 + mi * 16 + grp + rr * 8;
            #pragma unroll
            for (int ni = 0; ni < 8; ++ni) {
                int c = bn + warp_n * 64 + ni * 8 + 2 * tig;
                float v0 = acc[mi][ni][rr * 2 + 0];
                float v1 = acc[mi][ni][rr * 2 + 1];
                if (EPI == 2 || EPI == 3) { v0 += bias[c]; v1 += bias[c + 1]; }
                if (EPI == 2)             { v0 = gelu_f(v0); v1 = gelu_f(v1); }
                if (EPI == 1 || EPI == 3) {
                    const float* rp = res + (size_t)r * N + c;
                    v0 += rp[0]; v1 += rp[1];
                }
                if (EPI == 2 || EPI == 4) {
                    __half2 o;
                    o.x = __float2half_rn(v0);
                    o.y = __float2half_rn(v1);
                    *(__half2*)((__half*)Cv + (size_t)r * N + c) = o;
                } else {
                    float2 o2; o2.x = v0; o2.y = v1;
                    *(float2*)((float*)Cv + (size_t)r * N + c) = o2;
                }
            }
        }
    }
}

// ---------------- Flash attention: fp16 tensor cores (unchanged R6) --------
#define KVP 72
#define Q_HALVES   (128 * KVP)
#define KV_STAGE_H (2 * 64 * KVP)
#define ATT_SMEM   ((Q_HALVES + 2 * KV_STAGE_H) * 2)

__global__ __launch_bounds__(256, 2) void attn_k(const __half* __restrict__ qkvh,
                                                 __half* __restrict__ y) {
    extern __shared__ __half smh[];
    unsigned smem_b = (unsigned)__cvta_generic_to_shared(smh);
    unsigned kvb    = smem_b + Q_HALVES * 2;

    int bh = blockIdx.y;
    int b  = bh / NH;
    int h  = bh % NH;
    int qt = gridDim.x - 1 - blockIdx.x;
    int q0 = qt * 128;
    size_t bT = (size_t)b * TSEQ;

    int tid  = threadIdx.x;
    int lane = tid & 31;
    int wid  = tid >> 5;
    int grp  = lane >> 2;
    int tig  = lane & 3;

    #pragma unroll
    for (int i = 0; i < 4; ++i) {
        int c = i * 256 + tid;
        int row = c >> 3, col8 = c & 7;
        const __half* src = qkvh + (bT + q0 + row) * (3 * CDIM) + h * HDIM + col8 * 8;
        cp16(smem_b + (unsigned)(row * KVP + col8 * 8) * 2, src);
    }
    cp_commit();

    auto kvissue = [&](int t) {
        int k0 = t * 64;
        unsigned sb = kvb + (unsigned)(t & 1) * (KV_STAGE_H * 2);
        #pragma unroll
        for (int i = 0; i < 4; ++i) {
            int c = i * 256 + tid;
            int isV = c >> 9;
            int cc = c & 511;
            int row = cc >> 3, col8 = cc & 7;
            const __half* src = qkvh + (bT + k0 + row) * (3 * CDIM)
                                + (1 + isV) * CDIM + h * HDIM + col8 * 8;
            cp16(sb + (unsigned)(isV * (64 * KVP) + row * KVP + col8 * 8) * 2, src);
        }
        cp_commit();
    };

    kvissue(0);
    asm volatile("cp.async.wait_group 0;\n" ::: "memory");
    __syncthreads();

    unsigned qf[4][4];
    {
        unsigned rowb = smem_b + (unsigned)((wid * 16 + (lane & 15)) * KVP) * 2;
        #pragma unroll
        for (int ch = 0; ch < 4; ++ch) {
            ldsm4(qf[ch], rowb + (unsigned)(ch * 16 + (lane >> 4) * 8) * 2);
            __half2 sc = __floats2half2_rn(0.125f, 0.125f);
            #pragma unroll
            for (int r = 0; r < 4; ++r) {
                __half2 v = *(__half2*)&qf[ch][r];
                v = __hmul2(v, sc);
                qf[ch][r] = *(unsigned*)&v;
            }
        }
    }

    float o[8][4];
    #pragma unroll
    for (int i = 0; i < 8; ++i)
        #pragma unroll
        for (int j = 0; j < 4; ++j) o[i][j] = 0.f;
    float m0 = -1e30f, m1 = -1e30f, l0 = 0.f, l1 = 0.f;

    int r0g = q0 + wid * 16 + grp;
    int ntiles = 2 * (qt + 1);

    for (int t = 0; t < ntiles; ++t) {
        if (t + 1 < ntiles) {
            kvissue(t + 1);
            asm volatile("cp.async.wait_group 1;\n" ::: "memory");
        } else {
            asm volatile("cp.async.wait_group 0;\n" ::: "memory");
        }
        __syncthreads();

        int k0 = t * 64;
        unsigned Ksb = kvb + (unsigned)(t & 1) * (KV_STAGE_H * 2);
        unsigned Vsb = Ksb + (unsigned)(64 * KVP) * 2;

        float s[8][4];
        #pragma unroll
        for (int i = 0; i < 8; ++i)
            #pragma unroll
            for (int j = 0; j < 4; ++j) s[i][j] = 0.f;

        int krow = (lane & 7) + ((lane >> 4) << 3);
        int kcol = ((lane >> 3) & 1) << 3;
        #pragma unroll
        for (int ch = 0; ch < 4; ++ch) {
            unsigned kf[4][4];
            #pragma unroll
            for (int p = 0; p < 4; ++p)
                ldsm4(kf[p], Ksb + (unsigned)((p * 16 + krow) * KVP + ch * 16 + kcol) * 2);
            #pragma unroll
            for (int nt = 0; nt < 8; ++nt)
                mma16816(s[nt], qf[ch],
                         kf[nt >> 1][(nt & 1) * 2 + 0],
                         kf[nt >> 1][(nt & 1) * 2 + 1]);
        }

        if (k0 + 63 > r0g + 8) {
            #pragma unroll
            for (int nt = 0; nt < 8; ++nt) {
                int c0 = k0 + nt * 8 + 2 * tig;
                if (c0     > r0g)     s[nt][0] = -1e30f;
                if (c0 + 1 > r0g)     s[nt][1] = -1e30f;
                if (c0     > r0g + 8) s[nt][2] = -1e30f;
                if (c0 + 1 > r0g + 8) s[nt][3] = -1e30f;
            }
        }

        float mx0 = -1e30f, mx1 = -1e30f;
        #pragma unroll
        for (int nt = 0; nt < 8; ++nt) {
            mx0 = fmaxf(mx0, fmaxf(s[nt][0], s[nt][1]));
            mx1 = fmaxf(mx1, fmaxf(s[nt][2], s[nt][3]));
        }
        mx0 = fmaxf(mx0, __shfl_xor_sync(0xffffffffu, mx0, 1));
        mx0 = fmaxf(mx0, __shfl_xor_sync(0xffffffffu, mx0, 2));
        mx1 = fmaxf(mx1, __shfl_xor_sync(0xffffffffu, mx1, 1));
        mx1 = fmaxf(mx1, __shfl_xor_sync(0xffffffffu, mx1, 2));

        float mn0 = fmaxf(m0, mx0), mn1 = fmaxf(m1, mx1);
        float cr0 = __expf(m0 - mn0), cr1 = __expf(m1 - mn1);
        m0 = mn0; m1 = mn1;

        float sum0 = 0.f, sum1 = 0.f;
        #pragma unroll
        for (int nt = 0; nt < 8; ++nt) {
            s[nt][0] = __expf(s[nt][0] - mn0); sum0 += s[nt][0];
            s[nt][1] = __expf(s[nt][1] - mn0); sum0 += s[nt][1];
            s[nt][2] = __expf(s[nt][2] - mn1); sum1 += s[nt][2];
            s[nt][3] = __expf(s[nt][3] - mn1); sum1 += s[nt][3];
        }
        sum0 += __shfl_xor_sync(0xffffffffu, sum0, 1);
        sum0 += __shfl_xor_sync(0xffffffffu, sum0, 2);
        sum1 += __shfl_xor_sync(0xffffffffu, sum1, 1);
        sum1 += __shfl_xor_sync(0xffffffffu, sum1, 2);
        l0 = l0 * cr0 + sum0;
        l1 = l1 * cr1 + sum1;

        #pragma unroll
        for (int nt = 0; nt < 8; ++nt) {
            o[nt][0] *= cr0; o[nt][1] *= cr0;
            o[nt][2] *= cr1; o[nt][3] *= cr1;
        }

        int vrow = (lane & 7) + (((lane >> 3) & 1) << 3);
        int vcol = (lane >> 4) << 3;
        #pragma unroll
        for (int c = 0; c < 4; ++c) {
            unsigned pa[4];
            pa[0] = f22h2(s[2 * c][0],     s[2 * c][1]);
            pa[1] = f22h2(s[2 * c][2],     s[2 * c][3]);
            pa[2] = f22h2(s[2 * c + 1][0], s[2 * c + 1][1]);
            pa[3] = f22h2(s[2 * c + 1][2], s[2 * c + 1][3]);

            unsigned vf[4][4];
            #pragma unroll
            for (int p = 0; p < 4; ++p)
                ldsm4t(vf[p], Vsb + (unsigned)((c * 16 + vrow) * KVP + p * 16 + vcol) * 2);

            #pragma unroll
            for (int dt = 0; dt < 8; ++dt)
                mma16816(o[dt], pa,
                         vf[dt >> 1][(dt & 1) * 2 + 0],
                         vf[dt >> 1][(dt & 1) * 2 + 1]);
        }
        __syncthreads();
    }

    float i0 = 1.f / l0, i1 = 1.f / l1;
    __half* y0 = y + (bT + r0g) * CDIM + h * HDIM;
    __half* y1 = y0 + 8 * CDIM;
    #pragma unroll
    for (int dt = 0; dt < 8; ++dt) {
        __half2 a, bb;
        a.x  = __float2half_rn(o[dt][0] * i0);
        a.y  = __float2half_rn(o[dt][1] * i0);
        bb.x = __float2half_rn(o[dt][2] * i1);
        bb.y = __float2half_rn(o[dt][3] * i1);
        *(__half2*)(y0 + dt * 8 + 2 * tig) = a;
        *(__half2*)(y1 + dt * 8 + 2 * tig) = bb;
    }
}

// ---------------- launch --------------------------------------------------
extern "C" void kernel_launch(void* const* d_in, const int* in_sizes, int n_in,
                              void* d_out, int out_size) {
    const float* x      = (const float*)d_in[0];
    const float* ln1_g  = (const float*)d_in[1];
    const float* ln1_b  = (const float*)d_in[2];
    const float* w_qkv  = (const float*)d_in[3];
    const float* w_o    = (const float*)d_in[4];
    const float* ln2_g  = (const float*)d_in[5];
    const float* ln2_b  = (const float*)d_in[6];
    const float* w_fc   = (const float*)d_in[7];
    const float* b_fc   = (const float*)d_in[8];
    const float* w_proj = (const float*)d_in[9];
    const float* b_proj = (const float*)d_in[10];
    float* out = (float*)d_out;

    __half *lnh, *qkvh, *atth, *hh, *wqkv_h, *wo_h, *wfc_h, *wproj_h;
    float *x1;
    cudaGetSymbolAddress((void**)&lnh,  g_lnh);
    cudaGetSymbolAddress((void**)&qkvh, g_qkvh);
    cudaGetSymbolAddress((void**)&atth, g_atth);
    cudaGetSymbolAddress((void**)&x1,   g_x1);
    cudaGetSymbolAddress((void**)&hh,   g_hh);
    cudaGetSymbolAddress((void**)&wqkv_h,  g_wqkv_h);
    cudaGetSymbolAddress((void**)&wo_h,    g_wo_h);
    cudaGetSymbolAddress((void**)&wfc_h,   g_wfc_h);
    cudaGetSymbolAddress((void**)&wproj_h, g_wproj_h);

    static int smem_set = 0;
    if (!smem_set) {
        cudaFuncSetAttribute(attn_k, cudaFuncAttributeMaxDynamicSharedMemorySize, ATT_SMEM);
        cudaFuncSetAttribute(gemm_k<1>, cudaFuncAttributeMaxDynamicSharedMemorySize, GEMM_SMEM);
        cudaFuncSetAttribute(gemm_k<2>, cudaFuncAttributeMaxDynamicSharedMemorySize, GEMM_SMEM);
        cudaFuncSetAttribute(gemm_k<3>, cudaFuncAttributeMaxDynamicSharedMemorySize, GEMM_SMEM);
        cudaFuncSetAttribute(gemm_k<4>, cudaFuncAttributeMaxDynamicSharedMemorySize, GEMM_SMEM);
        smem_set = 1;
    }

    // weights -> fp16
    roundh_k<<<(CDIM * 3 * CDIM / 4 + 255) / 256, 256>>>(w_qkv,  wqkv_h,  CDIM * 3 * CDIM / 4);
    roundh_k<<<(CDIM * CDIM / 4 + 255) / 256, 256>>>(w_o,    wo_h,    CDIM * CDIM / 4);
    roundh_k<<<(CDIM * DFF / 4 + 255) / 256, 256>>>(w_fc,   wfc_h,   CDIM * DFF / 4);
    roundh_k<<<(DFF * CDIM / 4 + 255) / 256, 256>>>(w_proj, wproj_h, DFF * CDIM / 4);

    ln_k<<<ROWS, 256>>>(x, ln1_g, ln1_b, lnh);
    gemm_k<4><<<dim3(3 * CDIM / BN, ROWS / BM), 128, GEMM_SMEM>>>(lnh, wqkv_h, nullptr, nullptr,
                                                                  qkvh, ROWS, 3 * CDIM, CDIM);
    attn_k<<<dim3(TSEQ / 128, NB * NH), 256, ATT_SMEM>>>(qkvh, atth);
    gemm_k<1><<<dim3(CDIM / BN, ROWS / BM), 128, GEMM_SMEM>>>(atth, wo_h, nullptr, x,
                                                              x1, ROWS, CDIM, CDIM);
    ln_k<<<ROWS, 256>>>(x1, ln2_g, ln2_b, lnh);
    gemm_k<2><<<dim3(DFF / BN, ROWS / BM), 128, GEMM_SMEM>>>(lnh, wfc_h, b_fc, nullptr,
                                                             hh, ROWS, DFF, CDIM);
    gemm_k<3><<<dim3(CDIM / BN, ROWS / BM), 128, GEMM_SMEM>>>(hh, wproj_h, b_proj, x1,
                                                              out, ROWS, CDIM, DFF);
}

// round 10
// speedup vs baseline: 14.9459x; 1.0385x over previous
#include <cuda_runtime.h>
#include <cuda_fp16.h>
#include <math.h>

#define TSEQ 2048
#define NB   2
#define CDIM 768
#define NH   12
#define HDIM 64
#define DFF  3072
#define ROWS (NB * TSEQ)   // 4096

// ---------------- scratch (device globals: allocation-free) ----------------
__device__ __half g_lnh [ROWS * CDIM];
__device__ __half g_qkvh[ROWS * 3 * CDIM];
__device__ __half g_atth[ROWS * CDIM];
__device__ float  g_x1  [ROWS * CDIM];
__device__ __half g_hh  [ROWS * DFF];
__device__ __half g_wqkv_h [CDIM * 3 * CDIM];
__device__ __half g_wo_h   [CDIM * CDIM];
__device__ __half g_wfc_h  [CDIM * DFF];
__device__ __half g_wproj_h[DFF * CDIM];

__device__ __forceinline__ float gelu_f(float v) {
    return 0.5f * v * (1.0f + erff(v * 0.70710678118654752f));
}

union Pack4 { __half h[4]; uint2 u; };

__device__ __forceinline__ void cp16(unsigned dst, const void* src) {
    asm volatile("cp.async.cg.shared.global [%0], [%1], 16;\n"
                 :: "r"(dst), "l"(src) : "memory");
}
__device__ __forceinline__ void cp_commit() {
    asm volatile("cp.async.commit_group;\n" ::: "memory");
}
__device__ __forceinline__ void ldsm4(unsigned* r, unsigned addr) {
    asm volatile("ldmatrix.sync.aligned.m8n8.x4.shared.b16 {%0,%1,%2,%3}, [%4];"
                 : "=r"(r[0]), "=r"(r[1]), "=r"(r[2]), "=r"(r[3]) : "r"(addr));
}
__device__ __forceinline__ void ldsm4t(unsigned* r, unsigned addr) {
    asm volatile("ldmatrix.sync.aligned.m8n8.x4.trans.shared.b16 {%0,%1,%2,%3}, [%4];"
                 : "=r"(r[0]), "=r"(r[1]), "=r"(r[2]), "=r"(r[3]) : "r"(addr));
}
__device__ __forceinline__ void mma16816(float* c, const unsigned* a,
                                         unsigned b0, unsigned b1) {
    asm volatile(
        "mma.sync.aligned.m16n8k16.row.col.f32.f16.f16.f32 "
        "{%0,%1,%2,%3}, {%4,%5,%6,%7}, {%8,%9}, {%0,%1,%2,%3};"
        : "+f"(c[0]), "+f"(c[1]), "+f"(c[2]), "+f"(c[3])
        : "r"(a[0]), "r"(a[1]), "r"(a[2]), "r"(a[3]), "r"(b0), "r"(b1));
}
__device__ __forceinline__ unsigned f22h2(float x, float y) {
    __half2 h = __floats2half2_rn(x, y);
    return *(unsigned*)&h;
}

// ---------------- weight fp32 -> fp16 (once per launch) --------------------
__global__ __launch_bounds__(256) void roundh_k(const float* __restrict__ in,
                                                __half* __restrict__ out,
                                                int n4) {
    int i = blockIdx.x * 256 + threadIdx.x;
    if (i < n4) {
        float4 v = ((const float4*)in)[i];
        Pack4 p;
        p.h[0] = __float2half_rn(v.x); p.h[1] = __float2half_rn(v.y);
        p.h[2] = __float2half_rn(v.z); p.h[3] = __float2half_rn(v.w);
        ((uint2*)out)[i] = p.u;
    }
}

// ---------------- LayerNorm (fp32 in, fp16 out) ----------------------------
__global__ __launch_bounds__(256) void ln_k(const float* __restrict__ xin,
                                            const float* __restrict__ g,
                                            const float* __restrict__ b,
                                            __half* __restrict__ out) {
    int row = blockIdx.x;
    int tid = threadIdx.x;
    const float* xr = xin + (size_t)row * CDIM;

    float v0 = xr[tid], v1 = xr[tid + 256], v2 = xr[tid + 512];
    float s  = v0 + v1 + v2;
    float ss = v0 * v0 + v1 * v1 + v2 * v2;

    #pragma unroll
    for (int off = 16; off > 0; off >>= 1) {
        s  += __shfl_xor_sync(0xffffffffu, s,  off);
        ss += __shfl_xor_sync(0xffffffffu, ss, off);
    }
    __shared__ float sh_s[8], sh_ss[8];
    int wid = tid >> 5, lane = tid & 31;
    if (lane == 0) { sh_s[wid] = s; sh_ss[wid] = ss; }
    __syncthreads();
    float ts = 0.f, tss = 0.f;
    #pragma unroll
    for (int i = 0; i < 8; ++i) { ts += sh_s[i]; tss += sh_ss[i]; }

    const float inv = 1.0f / (float)CDIM;
    float mu   = ts * inv;
    float var  = tss * inv - mu * mu;
    float rstd = rsqrtf(var + 1e-5f);

    __half* orow = out + (size_t)row * CDIM;
    orow[tid      ] = __float2half_rn((v0 - mu) * rstd * g[tid      ] + b[tid      ]);
    orow[tid + 256] = __float2half_rn((v1 - mu) * rstd * g[tid + 256] + b[tid + 256]);
    orow[tid + 512] = __float2half_rn((v2 - mu) * rstd * g[tid + 512] + b[tid + 512]);
}

// ---------------- fp16 GEMM (BM=128): 4 warps, 64x64 warp tiles, BK=32 -----
// EPI: 1 +res(f32), 2 +bias+GELU(fp16), 3 +bias+res(f32), 4 none(fp16)
#define BN 128
#define BK 32
#define AROW2 40     // halves per A smem row (32 + 8 pad) = 80 B
#define BROW2 136    // halves per B smem row (128 + 8 pad) = 272 B
#define BSZ2 (BK * BROW2 * 2)     // 8704 B
#define NSTG 3

#define ASZ128 (128 * AROW2 * 2)          // 10240 B
#define STG128 (ASZ128 + BSZ2)            // 18944 B
#define GEMM_SMEM128 (NSTG * STG128)      // 56832 B

template <int EPI>
__global__ __launch_bounds__(128, 2) void gemm_k(const __half* __restrict__ A,
                                                 const __half* __restrict__ Bm,
                                                 const float* __restrict__ bias,
                                                 const float* __restrict__ res,
                                                 void* __restrict__ Cv,
                                                 int M, int N, int K) {
    extern __shared__ char smc[];
    unsigned smem_base = (unsigned)__cvta_generic_to_shared(smc);

    int tid  = threadIdx.x;
    int lane = tid & 31;
    int wid  = tid >> 5;
    int warp_m = wid & 1;
    int warp_n = wid >> 1;
    int bm = blockIdx.y * 128;
    int bn = blockIdx.x * BN;
    int grp = lane >> 2;
    int tig = lane & 3;

    const __half* aP[4]; unsigned aO[4];
    const __half* bP[4]; unsigned bO[4];
    #pragma unroll
    for (int l = 0; l < 4; ++l) {
        int idx = l * 128 + tid;
        int ar = idx >> 2, ac = idx & 3;
        aP[l] = A + (size_t)(bm + ar) * K + ac * 8;
        aO[l] = (unsigned)(ar * AROW2 + ac * 8) * 2u;
        int br = idx >> 4, bc = idx & 15;
        bP[l] = Bm + (size_t)br * N + bn + bc * 8;
        bO[l] = (unsigned)ASZ128 + (unsigned)(br * BROW2 + bc * 8) * 2u;
    }

    auto stage = [&](int t) {
        unsigned s = smem_base + (unsigned)(t % NSTG) * STG128;
        #pragma unroll
        for (int l = 0; l < 4; ++l) {
            cp16(s + aO[l], aP[l] + (size_t)t * BK);
            cp16(s + bO[l], bP[l] + (size_t)t * BK * N);
        }
        cp_commit();
    };

    float acc[4][8][4];
    #pragma unroll
    for (int i = 0; i < 4; ++i)
        #pragma unroll
        for (int j = 0; j < 8; ++j)
            #pragma unroll
            for (int r = 0; r < 4; ++r) acc[i][j][r] = 0.f;

    int ntiles = K / BK;
    stage(0); stage(1);

    unsigned aLrow = (unsigned)(warp_m * 64 + (lane & 15));
    unsigned aLcol = (unsigned)((lane >> 4) * 8);
    unsigned bLrow = (unsigned)(lane & 15);
    unsigned bLcol = (unsigned)(warp_n * 64 + (lane >> 4) * 8);

    for (int t = 0; t < ntiles; ++t) {
        if (t + 2 < ntiles) {
            stage(t + 2);
            asm volatile("cp.async.wait_group %0;\n" :: "n"(2));
        } else if (t + 1 < ntiles) {
            asm volatile("cp.async.wait_group %0;\n" :: "n"(1));
        } else {
            asm volatile("cp.async.wait_group %0;\n" :: "n"(0));
        }
        __syncthreads();

        unsigned base = smem_base + (unsigned)(t % NSTG) * STG128;

        #pragma unroll
        for (int ks = 0; ks < 2; ++ks) {
            unsigned af[4][4], bf[4][4];
            #pragma unroll
            for (int mi = 0; mi < 4; ++mi)
                ldsm4(af[mi], base +
                      (unsigned)(((aLrow + mi * 16) * AROW2) + ks * 16 + aLcol) * 2);
            #pragma unroll
            for (int j = 0; j < 4; ++j)
                ldsm4t(bf[j], base + (unsigned)ASZ128 +
                       (unsigned)(((ks * 16 + bLrow) * BROW2) + bLcol + j * 16) * 2);

            #pragma unroll
            for (int mi = 0; mi < 4; ++mi)
                #pragma unroll
                for (int ni = 0; ni < 8; ++ni)
                    mma16816(acc[mi][ni], af[mi],
                             bf[ni >> 1][(ni & 1) * 2 + 0],
                             bf[ni >> 1][(ni & 1) * 2 + 1]);
        }
        __syncthreads();
    }

    #pragma unroll
    for (int mi = 0; mi < 4; ++mi) {
        #pragma unroll
        for (int rr = 0; rr < 2; ++rr) {
            int r = bm + warp_m * 64 + mi * 16 + grp + rr * 8;
            #pragma unroll
            for (int ni = 0; ni < 8; ++ni) {
                int c = bn + warp_n * 64 + ni * 8 + 2 * tig;
                float v0 = acc[mi][ni][rr * 2 + 0];
                float v1 = acc[mi][ni][rr * 2 + 1];
                if (EPI == 2 || EPI == 3) { v0 += bias[c]; v1 += bias[c + 1]; }
                if (EPI == 2)             { v0 = gelu_f(v0); v1 = gelu_f(v1); }
                if (EPI == 1 || EPI == 3) {
                    const float* rp = res + (size_t)r * N + c;
                    v0 += rp[0]; v1 += rp[1];
                }
                if (EPI == 2 || EPI == 4) {
                    __half2 o;
                    o.x = __float2half_rn(v0);
                    o.y = __float2half_rn(v1);
                    *(__half2*)((__half*)Cv + (size_t)r * N + c) = o;
                } else {
                    float2 o2; o2.x = v0; o2.y = v1;
                    *(float2*)((float*)Cv + (size_t)r * N + c) = o2;
                }
            }
        }
    }
}

// ---------------- fp16 GEMM (BM=64): for N=768 GEMMs (wave balance) --------
// CTA 64x128x32, 128 threads, warps 2Mx2N, warp tile 32x64, occ 4.
#define ASZ64 (64 * AROW2 * 2)            // 5120 B
#define STG64 (ASZ64 + BSZ2)              // 13824 B
#define GEMM_SMEM64 (NSTG * STG64)        // 41472 B

template <int EPI>
__global__ __launch_bounds__(128, 4) void gemm64_k(const __half* __restrict__ A,
                                                   const __half* __restrict__ Bm,
                                                   const float* __restrict__ bias,
                                                   const float* __restrict__ res,
                                                   void* __restrict__ Cv,
                                                   int M, int N, int K) {
    extern __shared__ char smc[];
    unsigned smem_base = (unsigned)__cvta_generic_to_shared(smc);

    int tid  = threadIdx.x;
    int lane = tid & 31;
    int wid  = tid >> 5;
    int warp_m = wid & 1;
    int warp_n = wid >> 1;
    int bm = blockIdx.y * 64;
    int bn = blockIdx.x * BN;
    int grp = lane >> 2;
    int tig = lane & 3;

    // A: 64 rows x 4 chunks = 256 cp16 -> 2/thread; B: 4/thread
    const __half* aP[2]; unsigned aO[2];
    const __half* bP[4]; unsigned bO[4];
    #pragma unroll
    for (int l = 0; l < 2; ++l) {
        int idx = l * 128 + tid;           // 0..255
        int ar = idx >> 2, ac = idx & 3;
        aP[l] = A + (size_t)(bm + ar) * K + ac * 8;
        aO[l] = (unsigned)(ar * AROW2 + ac * 8) * 2u;
    }
    #pragma unroll
    for (int l = 0; l < 4; ++l) {
        int idx = l * 128 + tid;
        int br = idx >> 4, bc = idx & 15;
        bP[l] = Bm + (size_t)br * N + bn + bc * 8;
        bO[l] = (unsigned)ASZ64 + (unsigned)(br * BROW2 + bc * 8) * 2u;
    }

    auto stage = [&](int t) {
        unsigned s = smem_base + (unsigned)(t % NSTG) * STG64;
        #pragma unroll
        for (int l = 0; l < 2; ++l)
            cp16(s + aO[l], aP[l] + (size_t)t * BK);
        #pragma unroll
        for (int l = 0; l < 4; ++l)
            cp16(s + bO[l], bP[l] + (size_t)t * BK * N);
        cp_commit();
    };

    float acc[2][8][4];
    #pragma unroll
    for (int i = 0; i < 2; ++i)
        #pragma unroll
        for (int j = 0; j < 8; ++j)
            #pragma unroll
            for (int r = 0; r < 4; ++r) acc[i][j][r] = 0.f;

    int ntiles = K / BK;
    stage(0); stage(1);

    unsigned aLrow = (unsigned)(warp_m * 32 + (lane & 15));
    unsigned aLcol = (unsigned)((lane >> 4) * 8);
    unsigned bLrow = (unsigned)(lane & 15);
    unsigned bLcol = (unsigned)(warp_n * 64 + (lane >> 4) * 8);

    for (int t = 0; t < ntiles; ++t) {
        if (t + 2 < ntiles) {
            stage(t + 2);
            asm volatile("cp.async.wait_group %0;\n" :: "n"(2));
        } else if (t + 1 < ntiles) {
            asm volatile("cp.async.wait_group %0;\n" :: "n"(1));
        } else {
            asm volatile("cp.async.wait_group %0;\n" :: "n"(0));
        }
        __syncthreads();

        unsigned base = smem_base + (unsigned)(t % NSTG) * STG64;

        #pragma unroll
        for (int ks = 0; ks < 2; ++ks) {
            unsigned af[2][4], bf[4][4];
            #pragma unroll
            for (int mi = 0; mi < 2; ++mi)
                ldsm4(af[mi], base +
                      (unsigned)(((aLrow + mi * 16) * AROW2) + ks * 16 + aLcol) * 2);
            #pragma unroll
            for (int j = 0; j < 4; ++j)
                ldsm4t(bf[j], base + (unsigned)ASZ64 +
                       (unsigned)(((ks * 16 + bLrow) * BROW2) + bLcol + j * 16) * 2);

            #pragma unroll
            for (int mi = 0; mi < 2; ++mi)
                #pragma unroll
                for (int ni = 0; ni < 8; ++ni)
                    mma16816(acc[mi][ni], af[mi],
                             bf[ni >> 1][(ni & 1) * 2 + 0],
                             bf[ni >> 1][(ni & 1) * 2 + 1]);
        }
        __syncthreads();
    }

    #pragma unroll
    for (int mi = 0; mi < 2; ++mi) {
        #pragma unroll
        for (int rr = 0; rr < 2; ++rr) {
            int r = bm + warp_m * 32 + mi * 16 + grp + rr * 8;
            #pragma unroll
            for (int ni = 0; ni < 8; ++ni) {
                int c = bn + warp_n * 64 + ni * 8 + 2 * tig;
                float v0 = acc[mi][ni][rr * 2 + 0];
                float v1 = acc[mi][ni][rr * 2 + 1];
                if (EPI == 2 || EPI == 3) { v0 += bias[c]; v1 += bias[c + 1]; }
                if (EPI == 2)             { v0 = gelu_f(v0); v1 = gelu_f(v1); }
                if (EPI == 1 || EPI == 3) {
                    const float* rp = res + (size_t)r * N + c;
                    v0 += rp[0]; v1 += rp[1];
                }
                if (EPI == 2 || EPI == 4) {
                    __half2 o;
                    o.x = __float2half_rn(v0);
                    o.y = __float2half_rn(v1);
                    *(__half2*)((__half*)Cv + (size_t)r * N + c) = o;
                } else {
                    float2 o2; o2.x = v0; o2.y = v1;
                    *(float2*)((float*)Cv + (size_t)r * N + c) = o2;
                }
            }
        }
    }
}

// ---------------- Flash attention: fp16 tensor cores (unchanged) -----------
#define KVP 72
#define Q_HALVES   (128 * KVP)
#define KV_STAGE_H (2 * 64 * KVP)
#define ATT_SMEM   ((Q_HALVES + 2 * KV_STAGE_H) * 2)

__global__ __launch_bounds__(256, 2) void attn_k(const __half* __restrict__ qkvh,
                                                 __half* __restrict__ y) {
    extern __shared__ __half smh[];
    unsigned smem_b = (unsigned)__cvta_generic_to_shared(smh);
    unsigned kvb    = smem_b + Q_HALVES * 2;

    int bh = blockIdx.y;
    int b  = bh / NH;
    int h  = bh % NH;
    int qt = gridDim.x - 1 - blockIdx.x;
    int q0 = qt * 128;
    size_t bT = (size_t)b * TSEQ;

    int tid  = threadIdx.x;
    int lane = tid & 31;
    int wid  = tid >> 5;
    int grp  = lane >> 2;
    int tig  = lane & 3;

    #pragma unroll
    for (int i = 0; i < 4; ++i) {
        int c = i * 256 + tid;
        int row = c >> 3, col8 = c & 7;
        const __half* src = qkvh + (bT + q0 + row) * (3 * CDIM) + h * HDIM + col8 * 8;
        cp16(smem_b + (unsigned)(row * KVP + col8 * 8) * 2, src);
    }
    cp_commit();

    auto kvissue = [&](int t) {
        int k0 = t * 64;
        unsigned sb = kvb + (unsigned)(t & 1) * (KV_STAGE_H * 2);
        #pragma unroll
        for (int i = 0; i < 4; ++i) {
            int c = i * 256 + tid;
            int isV = c >> 9;
            int cc = c & 511;
            int row = cc >> 3, col8 = cc & 7;
            const __half* src = qkvh + (bT + k0 + row) * (3 * CDIM)
                                + (1 + isV) * CDIM + h * HDIM + col8 * 8;
            cp16(sb + (unsigned)(isV * (64 * KVP) + row * KVP + col8 * 8) * 2, src);
        }
        cp_commit();
    };

    kvissue(0);
    asm volatile("cp.async.wait_group 0;\n" ::: "memory");
    __syncthreads();

    unsigned qf[4][4];
    {
        unsigned rowb = smem_b + (unsigned)((wid * 16 + (lane & 15)) * KVP) * 2;
        #pragma unroll
        for (int ch = 0; ch < 4; ++ch) {
            ldsm4(qf[ch], rowb + (unsigned)(ch * 16 + (lane >> 4) * 8) * 2);
            __half2 sc = __floats2half2_rn(0.125f, 0.125f);
            #pragma unroll
            for (int r = 0; r < 4; ++r) {
                __half2 v = *(__half2*)&qf[ch][r];
                v = __hmul2(v, sc);
                qf[ch][r] = *(unsigned*)&v;
            }
        }
    }

    float o[8][4];
    #pragma unroll
    for (int i = 0; i < 8; ++i)
        #pragma unroll
        for (int j = 0; j < 4; ++j) o[i][j] = 0.f;
    float m0 = -1e30f, m1 = -1e30f, l0 = 0.f, l1 = 0.f;

    int r0g = q0 + wid * 16 + grp;
    int ntiles = 2 * (qt + 1);

    for (int t = 0; t < ntiles; ++t) {
        if (t + 1 < ntiles) {
            kvissue(t + 1);
            asm volatile("cp.async.wait_group 1;\n" ::: "memory");
        } else {
            asm volatile("cp.async.wait_group 0;\n" ::: "memory");
        }
        __syncthreads();

        int k0 = t * 64;
        unsigned Ksb = kvb + (unsigned)(t & 1) * (KV_STAGE_H * 2);
        unsigned Vsb = Ksb + (unsigned)(64 * KVP) * 2;

        float s[8][4];
        #pragma unroll
        for (int i = 0; i < 8; ++i)
            #pragma unroll
            for (int j = 0; j < 4; ++j) s[i][j] = 0.f;

        int krow = (lane & 7) + ((lane >> 4) << 3);
        int kcol = ((lane >> 3) & 1) << 3;
        #pragma unroll
        for (int ch = 0; ch < 4; ++ch) {
            unsigned kf[4][4];
            #pragma unroll
            for (int p = 0; p < 4; ++p)
                ldsm4(kf[p], Ksb + (unsigned)((p * 16 + krow) * KVP + ch * 16 + kcol) * 2);
            #pragma unroll
            for (int nt = 0; nt < 8; ++nt)
                mma16816(s[nt], qf[ch],
                         kf[nt >> 1][(nt & 1) * 2 + 0],
                         kf[nt >> 1][(nt & 1) * 2 + 1]);
        }

        if (k0 + 63 > r0g + 8) {
            #pragma unroll
            for (int nt = 0; nt < 8; ++nt) {
                int c0 = k0 + nt * 8 + 2 * tig;
                if (c0     > r0g)     s[nt][0] = -1e30f;
                if (c0 + 1 > r0g)     s[nt][1] = -1e30f;
                if (c0     > r0g + 8) s[nt][2] = -1e30f;
                if (c0 + 1 > r0g + 8) s[nt][3] = -1e30f;
            }
        }

        float mx0 = -1e30f, mx1 = -1e30f;
        #pragma unroll
        for (int nt = 0; nt < 8; ++nt) {
            mx0 = fmaxf(mx0, fmaxf(s[nt][0], s[nt][1]));
            mx1 = fmaxf(mx1, fmaxf(s[nt][2], s[nt][3]));
        }
        mx0 = fmaxf(mx0, __shfl_xor_sync(0xffffffffu, mx0, 1));
        mx0 = fmaxf(mx0, __shfl_xor_sync(0xffffffffu, mx0, 2));
        mx1 = fmaxf(mx1, __shfl_xor_sync(0xffffffffu, mx1, 1));
        mx1 = fmaxf(mx1, __shfl_xor_sync(0xffffffffu, mx1, 2));

        float mn0 = fmaxf(m0, mx0), mn1 = fmaxf(m1, mx1);
        float cr0 = __expf(m0 - mn0), cr1 = __expf(m1 - mn1);
        m0 = mn0; m1 = mn1;

        float sum0 = 0.f, sum1 = 0.f;
        #pragma unroll
        for (int nt = 0; nt < 8; ++nt) {
            s[nt][0] = __expf(s[nt][0] - mn0); sum0 += s[nt][0];
            s[nt][1] = __expf(s[nt][1] - mn0); sum0 += s[nt][1];
            s[nt][2] = __expf(s[nt][2] - mn1); sum1 += s[nt][2];
            s[nt][3] = __expf(s[nt][3] - mn1); sum1 += s[nt][3];
        }
        sum0 += __shfl_xor_sync(0xffffffffu, sum0, 1);
        sum0 += __shfl_xor_sync(0xffffffffu, sum0, 2);
        sum1 += __shfl_xor_sync(0xffffffffu, sum1, 1);
        sum1 += __shfl_xor_sync(0xffffffffu, sum1, 2);
        l0 = l0 * cr0 + sum0;
        l1 = l1 * cr1 + sum1;

        #pragma unroll
        for (int nt = 0; nt < 8; ++nt) {
            o[nt][0] *= cr0; o[nt][1] *= cr0;
            o[nt][2] *= cr1; o[nt][3] *= cr1;
        }

        int vrow = (lane & 7) + (((lane >> 3) & 1) << 3);
        int vcol = (lane >> 4) << 3;
        #pragma unroll
        for (int c = 0; c < 4; ++c) {
            unsigned pa[4];
            pa[0] = f22h2(s[2 * c][0],     s[2 * c][1]);
            pa[1] = f22h2(s[2 * c][2],     s[2 * c][3]);
            pa[2] = f22h2(s[2 * c + 1][0], s[2 * c + 1][1]);
            pa[3] = f22h2(s[2 * c + 1][2], s[2 * c + 1][3]);

            unsigned vf[4][4];
            #pragma unroll
            for (int p = 0; p < 4; ++p)
                ldsm4t(vf[p], Vsb + (unsigned)((c * 16 + vrow) * KVP + p * 16 + vcol) * 2);

            #pragma unroll
            for (int dt = 0; dt < 8; ++dt)
                mma16816(o[dt], pa,
                         vf[dt >> 1][(dt & 1) * 2 + 0],
                         vf[dt >> 1][(dt & 1) * 2 + 1]);
        }
        __syncthreads();
    }

    float i0 = 1.f / l0, i1 = 1.f / l1;
    __half* y0 = y + (bT + r0g) * CDIM + h * HDIM;
    __half* y1 = y0 + 8 * CDIM;
    #pragma unroll
    for (int dt = 0; dt < 8; ++dt) {
        __half2 a, bb;
        a.x  = __float2half_rn(o[dt][0] * i0);
        a.y  = __float2half_rn(o[dt][1] * i0);
        bb.x = __float2half_rn(o[dt][2] * i1);
        bb.y = __float2half_rn(o[dt][3] * i1);
        *(__half2*)(y0 + dt * 8 + 2 * tig) = a;
        *(__half2*)(y1 + dt * 8 + 2 * tig) = bb;
    }
}

// ---------------- launch --------------------------------------------------
extern "C" void kernel_launch(void* const* d_in, const int* in_sizes, int n_in,
                              void* d_out, int out_size) {
    const float* x      = (const float*)d_in[0];
    const float* ln1_g  = (const float*)d_in[1];
    const float* ln1_b  = (const float*)d_in[2];
    const float* w_qkv  = (const float*)d_in[3];
    const float* w_o    = (const float*)d_in[4];
    const float* ln2_g  = (const float*)d_in[5];
    const float* ln2_b  = (const float*)d_in[6];
    const float* w_fc   = (const float*)d_in[7];
    const float* b_fc   = (const float*)d_in[8];
    const float* w_proj = (const float*)d_in[9];
    const float* b_proj = (const float*)d_in[10];
    float* out = (float*)d_out;

    __half *lnh, *qkvh, *atth, *hh, *wqkv_h, *wo_h, *wfc_h, *wproj_h;
    float *x1;
    cudaGetSymbolAddress((void**)&lnh,  g_lnh);
    cudaGetSymbolAddress((void**)&qkvh, g_qkvh);
    cudaGetSymbolAddress((void**)&atth, g_atth);
    cudaGetSymbolAddress((void**)&x1,   g_x1);
    cudaGetSymbolAddress((void**)&hh,   g_hh);
    cudaGetSymbolAddress((void**)&wqkv_h,  g_wqkv_h);
    cudaGetSymbolAddress((void**)&wo_h,    g_wo_h);
    cudaGetSymbolAddress((void**)&wfc_h,   g_wfc_h);
    cudaGetSymbolAddress((void**)&wproj_h, g_wproj_h);

    static int smem_set = 0;
    if (!smem_set) {
        cudaFuncSetAttribute(attn_k, cudaFuncAttributeMaxDynamicSharedMemorySize, ATT_SMEM);
        cudaFuncSetAttribute(gemm_k<2>, cudaFuncAttributeMaxDynamicSharedMemorySize, GEMM_SMEM128);
        cudaFuncSetAttribute(gemm_k<4>, cudaFuncAttributeMaxDynamicSharedMemorySize, GEMM_SMEM128);
        cudaFuncSetAttribute(gemm64_k<1>, cudaFuncAttributeMaxDynamicSharedMemorySize, GEMM_SMEM64);
        cudaFuncSetAttribute(gemm64_k<3>, cudaFuncAttributeMaxDynamicSharedMemorySize, GEMM_SMEM64);
        smem_set = 1;
    }

    // weights -> fp16
    roundh_k<<<(CDIM * 3 * CDIM / 4 + 255) / 256, 256>>>(w_qkv,  wqkv_h,  CDIM * 3 * CDIM / 4);
    roundh_k<<<(CDIM * CDIM / 4 + 255) / 256, 256>>>(w_o,    wo_h,    CDIM * CDIM / 4);
    roundh_k<<<(CDIM * DFF / 4 + 255) / 256, 256>>>(w_fc,   wfc_h,   CDIM * DFF / 4);
    roundh_k<<<(DFF * CDIM / 4 + 255) / 256, 256>>>(w_proj, wproj_h, DFF * CDIM / 4);

    ln_k<<<ROWS, 256>>>(x, ln1_g, ln1_b, lnh);
    gemm_k<4><<<dim3(3 * CDIM / BN, ROWS / 128), 128, GEMM_SMEM128>>>(lnh, wqkv_h, nullptr, nullptr,
                                                                      qkvh, ROWS, 3 * CDIM, CDIM);
    attn_k<<<dim3(TSEQ / 128, NB * NH), 256, ATT_SMEM>>>(qkvh, atth);
    gemm64_k<1><<<dim3(CDIM / BN, ROWS / 64), 128, GEMM_SMEM64>>>(atth, wo_h, nullptr, x,
                                                                  x1, ROWS, CDIM, CDIM);
    ln_k<<<ROWS, 256>>>(x1, ln2_g, ln2_b, lnh);
    gemm_k<2><<<dim3(DFF / BN, ROWS / 128), 128, GEMM_SMEM128>>>(lnh, wfc_h, b_fc, nullptr,
                                                                 hh, ROWS, DFF, CDIM);
    gemm64_k<3><<<dim3(CDIM / BN, ROWS / 64), 128, GEMM_SMEM64>>>(hh, wproj_h, b_proj, x1,
                                                                  out, ROWS, CDIM, DFF);
}

// round 11
// speedup vs baseline: 15.1152x; 1.0113x over previous
#include <cuda_runtime.h>
#include <cuda_fp16.h>
#include <math.h>

#define TSEQ 2048
#define NB   2
#define CDIM 768
#define NH   12
#define HDIM 64
#define DFF  3072
#define ROWS (NB * TSEQ)   // 4096

// ---------------- scratch (device globals: allocation-free) ----------------
__device__ __half g_lnh [ROWS * CDIM];
__device__ __half g_qkvh[ROWS * 3 * CDIM];
__device__ __half g_atth[ROWS * CDIM];
__device__ float  g_x1  [ROWS * CDIM];
__device__ __half g_hh  [ROWS * DFF];
__device__ __half g_wqkv_h [CDIM * 3 * CDIM];
__device__ __half g_wo_h   [CDIM * CDIM];
__device__ __half g_wfc_h  [CDIM * DFF];
__device__ __half g_wproj_h[DFF * CDIM];

__device__ __forceinline__ float gelu_f(float v) {
    return 0.5f * v * (1.0f + erff(v * 0.70710678118654752f));
}

union Pack4 { __half h[4]; uint2 u; };

__device__ __forceinline__ void cp16(unsigned dst, const void* src) {
    asm volatile("cp.async.cg.shared.global [%0], [%1], 16;\n"
                 :: "r"(dst), "l"(src) : "memory");
}
__device__ __forceinline__ void cp_commit() {
    asm volatile("cp.async.commit_group;\n" ::: "memory");
}
__device__ __forceinline__ void ldsm4(unsigned* r, unsigned addr) {
    asm volatile("ldmatrix.sync.aligned.m8n8.x4.shared.b16 {%0,%1,%2,%3}, [%4];"
                 : "=r"(r[0]), "=r"(r[1]), "=r"(r[2]), "=r"(r[3]) : "r"(addr));
}
__device__ __forceinline__ void ldsm4t(unsigned* r, unsigned addr) {
    asm volatile("ldmatrix.sync.aligned.m8n8.x4.trans.shared.b16 {%0,%1,%2,%3}, [%4];"
                 : "=r"(r[0]), "=r"(r[1]), "=r"(r[2]), "=r"(r[3]) : "r"(addr));
}
__device__ __forceinline__ void mma16816(float* c, const unsigned* a,
                                         unsigned b0, unsigned b1) {
    asm volatile(
        "mma.sync.aligned.m16n8k16.row.col.f32.f16.f16.f32 "
        "{%0,%1,%2,%3}, {%4,%5,%6,%7}, {%8,%9}, {%0,%1,%2,%3};"
        : "+f"(c[0]), "+f"(c[1]), "+f"(c[2]), "+f"(c[3])
        : "r"(a[0]), "r"(a[1]), "r"(a[2]), "r"(a[3]), "r"(b0), "r"(b1));
}
__device__ __forceinline__ unsigned f22h2(float x, float y) {
    __half2 h = __floats2half2_rn(x, y);
    return *(unsigned*)&h;
}

// ---------------- weight fp32 -> fp16, 4 float4 per thread -----------------
__global__ __launch_bounds__(256) void roundh_k(const float* __restrict__ in,
                                                __half* __restrict__ out,
                                                int n4) {
    int i0 = (blockIdx.x * 256 + threadIdx.x) * 4;
    if (i0 + 3 < n4) {
        float4 v0 = ((const float4*)in)[i0 + 0];
        float4 v1 = ((const float4*)in)[i0 + 1];
        float4 v2 = ((const float4*)in)[i0 + 2];
        float4 v3 = ((const float4*)in)[i0 + 3];
        Pack4 p0, p1, p2, p3;
        p0.h[0] = __float2half_rn(v0.x); p0.h[1] = __float2half_rn(v0.y);
        p0.h[2] = __float2half_rn(v0.z); p0.h[3] = __float2half_rn(v0.w);
        p1.h[0] = __float2half_rn(v1.x); p1.h[1] = __float2half_rn(v1.y);
        p1.h[2] = __float2half_rn(v1.z); p1.h[3] = __float2half_rn(v1.w);
        p2.h[0] = __float2half_rn(v2.x); p2.h[1] = __float2half_rn(v2.y);
        p2.h[2] = __float2half_rn(v2.z); p2.h[3] = __float2half_rn(v2.w);
        p3.h[0] = __float2half_rn(v3.x); p3.h[1] = __float2half_rn(v3.y);
        p3.h[2] = __float2half_rn(v3.z); p3.h[3] = __float2half_rn(v3.w);
        ((uint2*)out)[i0 + 0] = p0.u;
        ((uint2*)out)[i0 + 1] = p1.u;
        ((uint2*)out)[i0 + 2] = p2.u;
        ((uint2*)out)[i0 + 3] = p3.u;
    } else {
        for (int i = i0; i < n4; ++i) {
            float4 v = ((const float4*)in)[i];
            Pack4 p;
            p.h[0] = __float2half_rn(v.x); p.h[1] = __float2half_rn(v.y);
            p.h[2] = __float2half_rn(v.z); p.h[3] = __float2half_rn(v.w);
            ((uint2*)out)[i] = p.u;
        }
    }
}

// ---------------- LayerNorm: one warp per row (fp32 in, fp16 out) ----------
__global__ __launch_bounds__(256) void ln_k(const float* __restrict__ xin,
                                            const float* __restrict__ g,
                                            const float* __restrict__ b,
                                            __half* __restrict__ out) {
    int row  = blockIdx.x * 8 + (threadIdx.x >> 5);
    int lane = threadIdx.x & 31;
    const float4* xr = (const float4*)(xin + (size_t)row * CDIM);

    float4 v[6];
    float s = 0.f, ss = 0.f;
    #pragma unroll
    for (int i = 0; i < 6; ++i) {
        v[i] = xr[i * 32 + lane];
        s  += v[i].x + v[i].y + v[i].z + v[i].w;
        ss += v[i].x * v[i].x + v[i].y * v[i].y
            + v[i].z * v[i].z + v[i].w * v[i].w;
    }
    #pragma unroll
    for (int off = 16; off > 0; off >>= 1) {
        s  += __shfl_xor_sync(0xffffffffu, s,  off);
        ss += __shfl_xor_sync(0xffffffffu, ss, off);
    }

    const float inv = 1.0f / (float)CDIM;
    float mu   = s * inv;
    float var  = ss * inv - mu * mu;
    float rstd = rsqrtf(var + 1e-5f);

    const float4* g4 = (const float4*)g;
    const float4* b4 = (const float4*)b;
    __half* orow = out + (size_t)row * CDIM;
    #pragma unroll
    for (int i = 0; i < 6; ++i) {
        int c4 = i * 32 + lane;
        float4 gv = g4[c4];
        float4 bv = b4[c4];
        Pack4 p;
        p.h[0] = __float2half_rn((v[i].x - mu) * rstd * gv.x + bv.x);
        p.h[1] = __float2half_rn((v[i].y - mu) * rstd * gv.y + bv.y);
        p.h[2] = __float2half_rn((v[i].z - mu) * rstd * gv.z + bv.z);
        p.h[3] = __float2half_rn((v[i].w - mu) * rstd * gv.w + bv.w);
        *(uint2*)(orow + c4 * 4) = p.u;
    }
}

// ---------------- fp16 GEMM (BM=128): 4 warps, 64x64 warp tiles, BK=32 -----
// EPI: 1 +res(f32), 2 +bias+GELU(fp16), 3 +bias+res(f32), 4 none(fp16)
#define BN 128
#define BK 32
#define AROW2 40
#define BROW2 136
#define BSZ2 (BK * BROW2 * 2)
#define NSTG 3

#define ASZ128 (128 * AROW2 * 2)
#define STG128 (ASZ128 + BSZ2)
#define GEMM_SMEM128 (NSTG * STG128)

template <int EPI>
__global__ __launch_bounds__(128, 2) void gemm_k(const __half* __restrict__ A,
                                                 const __half* __restrict__ Bm,
                                                 const float* __restrict__ bias,
                                                 const float* __restrict__ res,
                                                 void* __restrict__ Cv,
                                                 int M, int N, int K) {
    extern __shared__ char smc[];
    unsigned smem_base = (unsigned)__cvta_generic_to_shared(smc);

    int tid  = threadIdx.x;
    int lane = tid & 31;
    int wid  = tid >> 5;
    int warp_m = wid & 1;
    int warp_n = wid >> 1;
    int bm = blockIdx.y * 128;
    int bn = blockIdx.x * BN;
    int grp = lane >> 2;
    int tig = lane & 3;

    const __half* aP[4]; unsigned aO[4];
    const __half* bP[4]; unsigned bO[4];
    #pragma unroll
    for (int l = 0; l < 4; ++l) {
        int idx = l * 128 + tid;
        int ar = idx >> 2, ac = idx & 3;
        aP[l] = A + (size_t)(bm + ar) * K + ac * 8;
        aO[l] = (unsigned)(ar * AROW2 + ac * 8) * 2u;
        int br = idx >> 4, bc = idx & 15;
        bP[l] = Bm + (size_t)br * N + bn + bc * 8;
        bO[l] = (unsigned)ASZ128 + (unsigned)(br * BROW2 + bc * 8) * 2u;
    }

    auto stage = [&](int t) {
        unsigned s = smem_base + (unsigned)(t % NSTG) * STG128;
        #pragma unroll
        for (int l = 0; l < 4; ++l) {
            cp16(s + aO[l], aP[l] + (size_t)t * BK);
            cp16(s + bO[l], bP[l] + (size_t)t * BK * N);
        }
        cp_commit();
    };

    float acc[4][8][4];
    #pragma unroll
    for (int i = 0; i < 4; ++i)
        #pragma unroll
        for (int j = 0; j < 8; ++j)
            #pragma unroll
            for (int r = 0; r < 4; ++r) acc[i][j][r] = 0.f;

    int ntiles = K / BK;
    stage(0); stage(1);

    unsigned aLrow = (unsigned)(warp_m * 64 + (lane & 15));
    unsigned aLcol = (unsigned)((lane >> 4) * 8);
    unsigned bLrow = (unsigned)(lane & 15);
    unsigned bLcol = (unsigned)(warp_n * 64 + (lane >> 4) * 8);

    for (int t = 0; t < ntiles; ++t) {
        if (t + 2 < ntiles) {
            stage(t + 2);
            asm volatile("cp.async.wait_group %0;\n" :: "n"(2));
        } else if (t + 1 < ntiles) {
            asm volatile("cp.async.wait_group %0;\n" :: "n"(1));
        } else {
            asm volatile("cp.async.wait_group %0;\n" :: "n"(0));
        }
        __syncthreads();

        unsigned base = smem_base + (unsigned)(t % NSTG) * STG128;

        #pragma unroll
        for (int ks = 0; ks < 2; ++ks) {
            unsigned af[4][4], bf[4][4];
            #pragma unroll
            for (int mi = 0; mi < 4; ++mi)
                ldsm4(af[mi], base +
                      (unsigned)(((aLrow + mi * 16) * AROW2) + ks * 16 + aLcol) * 2);
            #pragma unroll
            for (int j = 0; j < 4; ++j)
                ldsm4t(bf[j], base + (unsigned)ASZ128 +
                       (unsigned)(((ks * 16 + bLrow) * BROW2) + bLcol + j * 16) * 2);

            #pragma unroll
            for (int mi = 0; mi < 4; ++mi)
                #pragma unroll
                for (int ni = 0; ni < 8; ++ni)
                    mma16816(acc[mi][ni], af[mi],
                             bf[ni >> 1][(ni & 1) * 2 + 0],
                             bf[ni >> 1][(ni & 1) * 2 + 1]);
        }
        __syncthreads();
    }

    #pragma unroll
    for (int mi = 0; mi < 4; ++mi) {
        #pragma unroll
        for (int rr = 0; rr < 2; ++rr) {
            int r = bm + warp_m * 64 + mi * 16 + grp + rr * 8;
            #pragma unroll
            for (int ni = 0; ni < 8; ++ni) {
                int c = bn + warp_n * 64 + ni * 8 + 2 * tig;
                float v0 = acc[mi][ni][rr * 2 + 0];
                float v1 = acc[mi][ni][rr * 2 + 1];
                if (EPI == 2 || EPI == 3) { v0 += bias[c]; v1 += bias[c + 1]; }
                if (EPI == 2)             { v0 = gelu_f(v0); v1 = gelu_f(v1); }
                if (EPI == 1 || EPI == 3) {
                    const float* rp = res + (size_t)r * N + c;
                    v0 += rp[0]; v1 += rp[1];
                }
                if (EPI == 2 || EPI == 4) {
                    __half2 o;
                    o.x = __float2half_rn(v0);
                    o.y = __float2half_rn(v1);
                    *(__half2*)((__half*)Cv + (size_t)r * N + c) = o;
                } else {
                    float2 o2; o2.x = v0; o2.y = v1;
                    *(float2*)((float*)Cv + (size_t)r * N + c) = o2;
                }
            }
        }
    }
}

// ---------------- fp16 GEMM (BM=64): for N=768 GEMMs (wave balance) --------
#define ASZ64 (64 * AROW2 * 2)
#define STG64 (ASZ64 + BSZ2)
#define GEMM_SMEM64 (NSTG * STG64)

template <int EPI>
__global__ __launch_bounds__(128, 4) void gemm64_k(const __half* __restrict__ A,
                                                   const __half* __restrict__ Bm,
                                                   const float* __restrict__ bias,
                                                   const float* __restrict__ res,
                                                   void* __restrict__ Cv,
                                                   int M, int N, int K) {
    extern __shared__ char smc[];
    unsigned smem_base = (unsigned)__cvta_generic_to_shared(smc);

    int tid  = threadIdx.x;
    int lane = tid & 31;
    int wid  = tid >> 5;
    int warp_m = wid & 1;
    int warp_n = wid >> 1;
    int bm = blockIdx.y * 64;
    int bn = blockIdx.x * BN;
    int grp = lane >> 2;
    int tig = lane & 3;

    const __half* aP[2]; unsigned aO[2];
    const __half* bP[4]; unsigned bO[4];
    #pragma unroll
    for (int l = 0; l < 2; ++l) {
        int idx = l * 128 + tid;
        int ar = idx >> 2, ac = idx & 3;
        aP[l] = A + (size_t)(bm + ar) * K + ac * 8;
        aO[l] = (unsigned)(ar * AROW2 + ac * 8) * 2u;
    }
    #pragma unroll
    for (int l = 0; l < 4; ++l) {
        int idx = l * 128 + tid;
        int br = idx >> 4, bc = idx & 15;
        bP[l] = Bm + (size_t)br * N + bn + bc * 8;
        bO[l] = (unsigned)ASZ64 + (unsigned)(br * BROW2 + bc * 8) * 2u;
    }

    auto stage = [&](int t) {
        unsigned s = smem_base + (unsigned)(t % NSTG) * STG64;
        #pragma unroll
        for (int l = 0; l < 2; ++l)
            cp16(s + aO[l], aP[l] + (size_t)t * BK);
        #pragma unroll
        for (int l = 0; l < 4; ++l)
            cp16(s + bO[l], bP[l] + (size_t)t * BK * N);
        cp_commit();
    };

    float acc[2][8][4];
    #pragma unroll
    for (int i = 0; i < 2; ++i)
        #pragma unroll
        for (int j = 0; j < 8; ++j)
            #pragma unroll
            for (int r = 0; r < 4; ++r) acc[i][j][r] = 0.f;

    int ntiles = K / BK;
    stage(0); stage(1);

    unsigned aLrow = (unsigned)(warp_m * 32 + (lane & 15));
    unsigned aLcol = (unsigned)((lane >> 4) * 8);
    unsigned bLrow = (unsigned)(lane & 15);
    unsigned bLcol = (unsigned)(warp_n * 64 + (lane >> 4) * 8);

    for (int t = 0; t < ntiles; ++t) {
        if (t + 2 < ntiles) {
            stage(t + 2);
            asm volatile("cp.async.wait_group %0;\n" :: "n"(2));
        } else if (t + 1 < ntiles) {
            asm volatile("cp.async.wait_group %0;\n" :: "n"(1));
        } else {
            asm volatile("cp.async.wait_group %0;\n" :: "n"(0));
        }
        __syncthreads();

        unsigned base = smem_base + (unsigned)(t % NSTG) * STG64;

        #pragma unroll
        for (int ks = 0; ks < 2; ++ks) {
            unsigned af[2][4], bf[4][4];
            #pragma unroll
            for (int mi = 0; mi < 2; ++mi)
                ldsm4(af[mi], base +
                      (unsigned)(((aLrow + mi * 16) * AROW2) + ks * 16 + aLcol) * 2);
            #pragma unroll
            for (int j = 0; j < 4; ++j)
                ldsm4t(bf[j], base + (unsigned)ASZ64 +
                       (unsigned)(((ks * 16 + bLrow) * BROW2) + bLcol + j * 16) * 2);

            #pragma unroll
            for (int mi = 0; mi < 2; ++mi)
                #pragma unroll
                for (int ni = 0; ni < 8; ++ni)
                    mma16816(acc[mi][ni], af[mi],
                             bf[ni >> 1][(ni & 1) * 2 + 0],
                             bf[ni >> 1][(ni & 1) * 2 + 1]);
        }
        __syncthreads();
    }

    #pragma unroll
    for (int mi = 0; mi < 2; ++mi) {
        #pragma unroll
        for (int rr = 0; rr < 2; ++rr) {
            int r = bm + warp_m * 32 + mi * 16 + grp + rr * 8;
            #pragma unroll
            for (int ni = 0; ni < 8; ++ni) {
                int c = bn + warp_n * 64 + ni * 8 + 2 * tig;
                float v0 = acc[mi][ni][rr * 2 + 0];
                float v1 = acc[mi][ni][rr * 2 + 1];
                if (EPI == 2 || EPI == 3) { v0 += bias[c]; v1 += bias[c + 1]; }
                if (EPI == 2)             { v0 = gelu_f(v0); v1 = gelu_f(v1); }
                if (EPI == 1 || EPI == 3) {
                    const float* rp = res + (size_t)r * N + c;
                    v0 += rp[0]; v1 += rp[1];
                }
                if (EPI == 2 || EPI == 4) {
                    __half2 o;
                    o.x = __float2half_rn(v0);
                    o.y = __float2half_rn(v1);
                    *(__half2*)((__half*)Cv + (size_t)r * N + c) = o;
                } else {
                    float2 o2; o2.x = v0; o2.y = v1;
                    *(float2*)((float*)Cv + (size_t)r * N + c) = o2;
                }
            }
        }
    }
}

// ---------------- Flash attention: fp16 tensor cores (unchanged) -----------
#define KVP 72
#define Q_HALVES   (128 * KVP)
#define KV_STAGE_H (2 * 64 * KVP)
#define ATT_SMEM   ((Q_HALVES + 2 * KV_STAGE_H) * 2)

__global__ __launch_bounds__(256, 2) void attn_k(const __half* __restrict__ qkvh,
                                                 __half* __restrict__ y) {
    extern __shared__ __half smh[];
    unsigned smem_b = (unsigned)__cvta_generic_to_shared(smh);
    unsigned kvb    = smem_b + Q_HALVES * 2;

    int bh = blockIdx.y;
    int b  = bh / NH;
    int h  = bh % NH;
    int qt = gridDim.x - 1 - blockIdx.x;
    int q0 = qt * 128;
    size_t bT = (size_t)b * TSEQ;

    int tid  = threadIdx.x;
    int lane = tid & 31;
    int wid  = tid >> 5;
    int grp  = lane >> 2;
    int tig  = lane & 3;

    #pragma unroll
    for (int i = 0; i < 4; ++i) {
        int c = i * 256 + tid;
        int row = c >> 3, col8 = c & 7;
        const __half* src = qkvh + (bT + q0 + row) * (3 * CDIM) + h * HDIM + col8 * 8;
        cp16(smem_b + (unsigned)(row * KVP + col8 * 8) * 2, src);
    }
    cp_commit();

    auto kvissue = [&](int t) {
        int k0 = t * 64;
        unsigned sb = kvb + (unsigned)(t & 1) * (KV_STAGE_H * 2);
        #pragma unroll
        for (int i = 0; i < 4; ++i) {
            int c = i * 256 + tid;
            int isV = c >> 9;
            int cc = c & 511;
            int row = cc >> 3, col8 = cc & 7;
            const __half* src = qkvh + (bT + k0 + row) * (3 * CDIM)
                                + (1 + isV) * CDIM + h * HDIM + col8 * 8;
            cp16(sb + (unsigned)(isV * (64 * KVP) + row * KVP + col8 * 8) * 2, src);
        }
        cp_commit();
    };

    kvissue(0);
    asm volatile("cp.async.wait_group 0;\n" ::: "memory");
    __syncthreads();

    unsigned qf[4][4];
    {
        unsigned rowb = smem_b + (unsigned)((wid * 16 + (lane & 15)) * KVP) * 2;
        #pragma unroll
        for (int ch = 0; ch < 4; ++ch) {
            ldsm4(qf[ch], rowb + (unsigned)(ch * 16 + (lane >> 4) * 8) * 2);
            __half2 sc = __floats2half2_rn(0.125f, 0.125f);
            #pragma unroll
            for (int r = 0; r < 4; ++r) {
                __half2 v = *(__half2*)&qf[ch][r];
                v = __hmul2(v, sc);
                qf[ch][r] = *(unsigned*)&v;
            }
        }
    }

    float o[8][4];
    #pragma unroll
    for (int i = 0; i < 8; ++i)
        #pragma unroll
        for (int j = 0; j < 4; ++j) o[i][j] = 0.f;
    float m0 = -1e30f, m1 = -1e30f, l0 = 0.f, l1 = 0.f;

    int r0g = q0 + wid * 16 + grp;
    int ntiles = 2 * (qt + 1);

    for (int t = 0; t < ntiles; ++t) {
        if (t + 1 < ntiles) {
            kvissue(t + 1);
            asm volatile("cp.async.wait_group 1;\n" ::: "memory");
        } else {
            asm volatile("cp.async.wait_group 0;\n" ::: "memory");
        }
        __syncthreads();

        int k0 = t * 64;
        unsigned Ksb = kvb + (unsigned)(t & 1) * (KV_STAGE_H * 2);
        unsigned Vsb = Ksb + (unsigned)(64 * KVP) * 2;

        float s[8][4];
        #pragma unroll
        for (int i = 0; i < 8; ++i)
            #pragma unroll
            for (int j = 0; j < 4; ++j) s[i][j] = 0.f;

        int krow = (lane & 7) + ((lane >> 4) << 3);
        int kcol = ((lane >> 3) & 1) << 3;
        #pragma unroll
        for (int ch = 0; ch < 4; ++ch) {
            unsigned kf[4][4];
            #pragma unroll
            for (int p = 0; p < 4; ++p)
                ldsm4(kf[p], Ksb + (unsigned)((p * 16 + krow) * KVP + ch * 16 + kcol) * 2);
            #pragma unroll
            for (int nt = 0; nt < 8; ++nt)
                mma16816(s[nt], qf[ch],
                         kf[nt >> 1][(nt & 1) * 2 + 0],
                         kf[nt >> 1][(nt & 1) * 2 + 1]);
        }

        if (k0 + 63 > r0g + 8) {
            #pragma unroll
            for (int nt = 0; nt < 8; ++nt) {
                int c0 = k0 + nt * 8 + 2 * tig;
                if (c0     > r0g)     s[nt][0] = -1e30f;
                if (c0 + 1 > r0g)     s[nt][1] = -1e30f;
                if (c0     > r0g + 8) s[nt][2] = -1e30f;
                if (c0 + 1 > r0g + 8) s[nt][3] = -1e30f;
            }
        }

        float mx0 = -1e30f, mx1 = -1e30f;
        #pragma unroll
        for (int nt = 0; nt < 8; ++nt) {
            mx0 = fmaxf(mx0, fmaxf(s[nt][0], s[nt][1]));
            mx1 = fmaxf(mx1, fmaxf(s[nt][2], s[nt][3]));
        }
        mx0 = fmaxf(mx0, __shfl_xor_sync(0xffffffffu, mx0, 1));
        mx0 = fmaxf(mx0, __shfl_xor_sync(0xffffffffu, mx0, 2));
        mx1 = fmaxf(mx1, __shfl_xor_sync(0xffffffffu, mx1, 1));
        mx1 = fmaxf(mx1, __shfl_xor_sync(0xffffffffu, mx1, 2));

        float mn0 = fmaxf(m0, mx0), mn1 = fmaxf(m1, mx1);
        float cr0 = __expf(m0 - mn0), cr1 = __expf(m1 - mn1);
        m0 = mn0; m1 = mn1;

        float sum0 = 0.f, sum1 = 0.f;
        #pragma unroll
        for (int nt = 0; nt < 8; ++nt) {
            s[nt][0] = __expf(s[nt][0] - mn0); sum0 += s[nt][0];
            s[nt][1] = __expf(s[nt][1] - mn0); sum0 += s[nt][1];
            s[nt][2] = __expf(s[nt][2] - mn1); sum1 += s[nt][2];
            s[nt][3] = __expf(s[nt][3] - mn1); sum1 += s[nt][3];
        }
        sum0 += __shfl_xor_sync(0xffffffffu, sum0, 1);
        sum0 += __shfl_xor_sync(0xffffffffu, sum0, 2);
        sum1 += __shfl_xor_sync(0xffffffffu, sum1, 1);
        sum1 += __shfl_xor_sync(0xffffffffu, sum1, 2);
        l0 = l0 * cr0 + sum0;
        l1 = l1 * cr1 + sum1;

        #pragma unroll
        for (int nt = 0; nt < 8; ++nt) {
            o[nt][0] *= cr0; o[nt][1] *= cr0;
            o[nt][2] *= cr1; o[nt][3] *= cr1;
        }

        int vrow = (lane & 7) + (((lane >> 3) & 1) << 3);
        int vcol = (lane >> 4) << 3;
        #pragma unroll
        for (int c = 0; c < 4; ++c) {
            unsigned pa[4];
            pa[0] = f22h2(s[2 * c][0],     s[2 * c][1]);
            pa[1] = f22h2(s[2 * c][2],     s[2 * c][3]);
            pa[2] = f22h2(s[2 * c + 1][0], s[2 * c + 1][1]);
            pa[3] = f22h2(s[2 * c + 1][2], s[2 * c + 1][3]);

            unsigned vf[4][4];
            #pragma unroll
            for (int p = 0; p < 4; ++p)
                ldsm4t(vf[p], Vsb + (unsigned)((c * 16 + vrow) * KVP + p * 16 + vcol) * 2);

            #pragma unroll
            for (int dt = 0; dt < 8; ++dt)
                mma16816(o[dt], pa,
                         vf[dt >> 1][(dt & 1) * 2 + 0],
                         vf[dt >> 1][(dt & 1) * 2 + 1]);
        }
        __syncthreads();
    }

    float i0 = 1.f / l0, i1 = 1.f / l1;
    __half* y0 = y + (bT + r0g) * CDIM + h * HDIM;
    __half* y1 = y0 + 8 * CDIM;
    #pragma unroll
    for (int dt = 0; dt < 8; ++dt) {
        __half2 a, bb;
        a.x  = __float2half_rn(o[dt][0] * i0);
        a.y  = __float2half_rn(o[dt][1] * i0);
        bb.x = __float2half_rn(o[dt][2] * i1);
        bb.y = __float2half_rn(o[dt][3] * i1);
        *(__half2*)(y0 + dt * 8 + 2 * tig) = a;
        *(__half2*)(y1 + dt * 8 + 2 * tig) = bb;
    }
}

// ---------------- launch --------------------------------------------------
extern "C" void kernel_launch(void* const* d_in, const int* in_sizes, int n_in,
                              void* d_out, int out_size) {
    const float* x      = (const float*)d_in[0];
    const float* ln1_g  = (const float*)d_in[1];
    const float* ln1_b  = (const float*)d_in[2];
    const float* w_qkv  = (const float*)d_in[3];
    const float* w_o    = (const float*)d_in[4];
    const float* ln2_g  = (const float*)d_in[5];
    const float* ln2_b  = (const float*)d_in[6];
    const float* w_fc   = (const float*)d_in[7];
    const float* b_fc   = (const float*)d_in[8];
    const float* w_proj = (const float*)d_in[9];
    const float* b_proj = (const float*)d_in[10];
    float* out = (float*)d_out;

    __half *lnh, *qkvh, *atth, *hh, *wqkv_h, *wo_h, *wfc_h, *wproj_h;
    float *x1;
    cudaGetSymbolAddress((void**)&lnh,  g_lnh);
    cudaGetSymbolAddress((void**)&qkvh, g_qkvh);
    cudaGetSymbolAddress((void**)&atth, g_atth);
    cudaGetSymbolAddress((void**)&x1,   g_x1);
    cudaGetSymbolAddress((void**)&hh,   g_hh);
    cudaGetSymbolAddress((void**)&wqkv_h,  g_wqkv_h);
    cudaGetSymbolAddress((void**)&wo_h,    g_wo_h);
    cudaGetSymbolAddress((void**)&wfc_h,   g_wfc_h);
    cudaGetSymbolAddress((void**)&wproj_h, g_wproj_h);

    static int smem_set = 0;
    if (!smem_set) {
        cudaFuncSetAttribute(attn_k, cudaFuncAttributeMaxDynamicSharedMemorySize, ATT_SMEM);
        cudaFuncSetAttribute(gemm_k<2>, cudaFuncAttributeMaxDynamicSharedMemorySize, GEMM_SMEM128);
        cudaFuncSetAttribute(gemm_k<4>, cudaFuncAttributeMaxDynamicSharedMemorySize, GEMM_SMEM128);
        cudaFuncSetAttribute(gemm64_k<1>, cudaFuncAttributeMaxDynamicSharedMemorySize, GEMM_SMEM64);
        cudaFuncSetAttribute(gemm64_k<3>, cudaFuncAttributeMaxDynamicSharedMemorySize, GEMM_SMEM64);
        smem_set = 1;
    }

    // weights -> fp16 (4 float4 per thread)
    roundh_k<<<(CDIM * 3 * CDIM / 4 + 1023) / 1024, 256>>>(w_qkv,  wqkv_h,  CDIM * 3 * CDIM / 4);
    roundh_k<<<(CDIM * CDIM / 4 + 1023) / 1024, 256>>>(w_o,    wo_h,    CDIM * CDIM / 4);
    roundh_k<<<(CDIM * DFF / 4 + 1023) / 1024, 256>>>(w_fc,   wfc_h,   CDIM * DFF / 4);
    roundh_k<<<(DFF * CDIM / 4 + 1023) / 1024, 256>>>(w_proj, wproj_h, DFF * CDIM / 4);

    ln_k<<<ROWS / 8, 256>>>(x, ln1_g, ln1_b, lnh);
    gemm_k<4><<<dim3(3 * CDIM / BN, ROWS / 128), 128, GEMM_SMEM128>>>(lnh, wqkv_h, nullptr, nullptr,
                                                                      qkvh, ROWS, 3 * CDIM, CDIM);
    attn_k<<<dim3(TSEQ / 128, NB * NH), 256, ATT_SMEM>>>(qkvh, atth);
    gemm64_k<1><<<dim3(CDIM / BN, ROWS / 64), 128, GEMM_SMEM64>>>(atth, wo_h, nullptr, x,
                                                                  x1, ROWS, CDIM, CDIM);
    ln_k<<<ROWS / 8, 256>>>(x1, ln2_g, ln2_b, lnh);
    gemm_k<2><<<dim3(DFF / BN, ROWS / 128), 128, GEMM_SMEM128>>>(lnh, wfc_h, b_fc, nullptr,
                                                                 hh, ROWS, DFF, CDIM);
    gemm64_k<3><<<dim3(CDIM / BN, ROWS / 64), 128, GEMM_SMEM64>>>(hh, wproj_h, b_proj, x1,
                                                                  out, ROWS, CDIM, DFF);
}

// round 12
// speedup vs baseline: 15.3244x; 1.0138x over previous
#include <cuda_runtime.h>
#include <cuda_fp16.h>
#include <math.h>

#define TSEQ 2048
#define NB   2
#define CDIM 768
#define NH   12
#define HDIM 64
#define DFF  3072
#define ROWS (NB * TSEQ)   // 4096

// ---------------- scratch (device globals: allocation-free) ----------------
__device__ __half g_lnh [ROWS * CDIM];
__device__ __half g_qkvh[ROWS * 3 * CDIM];
__device__ __half g_atth[ROWS * CDIM];
__device__ float  g_x1  [ROWS * CDIM];
__device__ __half g_hh  [ROWS * DFF];
__device__ __half g_wqkv_h [CDIM * 3 * CDIM];
__device__ __half g_wo_h   [CDIM * CDIM];
__device__ __half g_wfc_h  [CDIM * DFF];
__device__ __half g_wproj_h[DFF * CDIM];

__device__ __forceinline__ float gelu_f(float v) {
    return 0.5f * v * (1.0f + erff(v * 0.70710678118654752f));
}

union Pack4 { __half h[4]; uint2 u; };

__device__ __forceinline__ void cp16(unsigned dst, const void* src) {
    asm volatile("cp.async.cg.shared.global [%0], [%1], 16;\n"
                 :: "r"(dst), "l"(src) : "memory");
}
__device__ __forceinline__ void cp_commit() {
    asm volatile("cp.async.commit_group;\n" ::: "memory");
}
__device__ __forceinline__ void ldsm4(unsigned* r, unsigned addr) {
    asm volatile("ldmatrix.sync.aligned.m8n8.x4.shared.b16 {%0,%1,%2,%3}, [%4];"
                 : "=r"(r[0]), "=r"(r[1]), "=r"(r[2]), "=r"(r[3]) : "r"(addr));
}
__device__ __forceinline__ void ldsm4t(unsigned* r, unsigned addr) {
    asm volatile("ldmatrix.sync.aligned.m8n8.x4.trans.shared.b16 {%0,%1,%2,%3}, [%4];"
                 : "=r"(r[0]), "=r"(r[1]), "=r"(r[2]), "=r"(r[3]) : "r"(addr));
}
__device__ __forceinline__ void mma16816(float* c, const unsigned* a,
                                         unsigned b0, unsigned b1) {
    asm volatile(
        "mma.sync.aligned.m16n8k16.row.col.f32.f16.f16.f32 "
        "{%0,%1,%2,%3}, {%4,%5,%6,%7}, {%8,%9}, {%0,%1,%2,%3};"
        : "+f"(c[0]), "+f"(c[1]), "+f"(c[2]), "+f"(c[3])
        : "r"(a[0]), "r"(a[1]), "r"(a[2]), "r"(a[3]), "r"(b0), "r"(b1));
}
__device__ __forceinline__ unsigned f22h2(float x, float y) {
    __half2 h = __floats2half2_rn(x, y);
    return *(unsigned*)&h;
}

// ---------------- ALL weights fp32 -> fp16 in ONE kernel -------------------
// Segment sizes in float4 units (each a multiple of 4 -> chunks never split).
#define N4_QKV  (CDIM * 3 * CDIM / 4)   // 442368
#define N4_O    (CDIM * CDIM / 4)       // 147456
#define N4_FC   (CDIM * DFF / 4)        // 589824
#define N4_PROJ (DFF * CDIM / 4)        // 589824
#define N4_TOT  (N4_QKV + N4_O + N4_FC + N4_PROJ)   // 1769472
#define NCHUNK  (N4_TOT / 4)            // 442368 chunks of 4 float4

__global__ __launch_bounds__(256) void roundall_k(const float* __restrict__ wqkv,
                                                  const float* __restrict__ wo,
                                                  const float* __restrict__ wfc,
                                                  const float* __restrict__ wproj,
                                                  __half* __restrict__ oqkv,
                                                  __half* __restrict__ oo,
                                                  __half* __restrict__ ofc,
                                                  __half* __restrict__ oproj) {
    int base = (blockIdx.x * 256 + threadIdx.x) * 4;   // float4 index
    if (base >= N4_TOT) return;

    const float4* src;
    uint2* dst;
    int off;
    if (base < N4_QKV) {
        src = (const float4*)wqkv;  dst = (uint2*)oqkv;  off = base;
    } else if (base < N4_QKV + N4_O) {
        src = (const float4*)wo;    dst = (uint2*)oo;    off = base - N4_QKV;
    } else if (base < N4_QKV + N4_O + N4_FC) {
        src = (const float4*)wfc;   dst = (uint2*)ofc;   off = base - N4_QKV - N4_O;
    } else {
        src = (const float4*)wproj; dst = (uint2*)oproj; off = base - N4_QKV - N4_O - N4_FC;
    }

    float4 v0 = src[off + 0], v1 = src[off + 1],
           v2 = src[off + 2], v3 = src[off + 3];
    Pack4 p0, p1, p2, p3;
    p0.h[0] = __float2half_rn(v0.x); p0.h[1] = __float2half_rn(v0.y);
    p0.h[2] = __float2half_rn(v0.z); p0.h[3] = __float2half_rn(v0.w);
    p1.h[0] = __float2half_rn(v1.x); p1.h[1] = __float2half_rn(v1.y);
    p1.h[2] = __float2half_rn(v1.z); p1.h[3] = __float2half_rn(v1.w);
    p2.h[0] = __float2half_rn(v2.x); p2.h[1] = __float2half_rn(v2.y);
    p2.h[2] = __float2half_rn(v2.z); p2.h[3] = __float2half_rn(v2.w);
    p3.h[0] = __float2half_rn(v3.x); p3.h[1] = __float2half_rn(v3.y);
    p3.h[2] = __float2half_rn(v3.z); p3.h[3] = __float2half_rn(v3.w);
    dst[off + 0] = p0.u; dst[off + 1] = p1.u;
    dst[off + 2] = p2.u; dst[off + 3] = p3.u;
}

// ---------------- LayerNorm: one warp per row (fp32 in, fp16 out) ----------
__global__ __launch_bounds__(256) void ln_k(const float* __restrict__ xin,
                                            const float* __restrict__ g,
                                            const float* __restrict__ b,
                                            __half* __restrict__ out) {
    int row  = blockIdx.x * 8 + (threadIdx.x >> 5);
    int lane = threadIdx.x & 31;
    const float4* xr = (const float4*)(xin + (size_t)row * CDIM);

    float4 v[6];
    float s = 0.f, ss = 0.f;
    #pragma unroll
    for (int i = 0; i < 6; ++i) {
        v[i] = xr[i * 32 + lane];
        s  += v[i].x + v[i].y + v[i].z + v[i].w;
        ss += v[i].x * v[i].x + v[i].y * v[i].y
            + v[i].z * v[i].z + v[i].w * v[i].w;
    }
    #pragma unroll
    for (int off = 16; off > 0; off >>= 1) {
        s  += __shfl_xor_sync(0xffffffffu, s,  off);
        ss += __shfl_xor_sync(0xffffffffu, ss, off);
    }

    const float inv = 1.0f / (float)CDIM;
    float mu   = s * inv;
    float var  = ss * inv - mu * mu;
    float rstd = rsqrtf(var + 1e-5f);

    const float4* g4 = (const float4*)g;
    const float4* b4 = (const float4*)b;
    __half* orow = out + (size_t)row * CDIM;
    #pragma unroll
    for (int i = 0; i < 6; ++i) {
        int c4 = i * 32 + lane;
        float4 gv = g4[c4];
        float4 bv = b4[c4];
        Pack4 p;
        p.h[0] = __float2half_rn((v[i].x - mu) * rstd * gv.x + bv.x);
        p.h[1] = __float2half_rn((v[i].y - mu) * rstd * gv.y + bv.y);
        p.h[2] = __float2half_rn((v[i].z - mu) * rstd * gv.z + bv.z);
        p.h[3] = __float2half_rn((v[i].w - mu) * rstd * gv.w + bv.w);
        *(uint2*)(orow + c4 * 4) = p.u;
    }
}

// ---------------- fp16 GEMM (BM=128): 4 warps, 64x64 warp tiles, BK=32 -----
// EPI: 1 +res(f32), 2 +bias+GELU(fp16), 3 +bias+res(f32), 4 none(fp16)
#define BN 128
#define BK 32
#define AROW2 40
#define BROW2 136
#define BSZ2 (BK * BROW2 * 2)
#define NSTG 3

#define ASZ128 (128 * AROW2 * 2)
#define STG128 (ASZ128 + BSZ2)
#define GEMM_SMEM128 (NSTG * STG128)

template <int EPI>
__global__ __launch_bounds__(128, 2) void gemm_k(const __half* __restrict__ A,
                                                 const __half* __restrict__ Bm,
                                                 const float* __restrict__ bias,
                                                 const float* __restrict__ res,
                                                 void* __restrict__ Cv,
                                                 int M, int N, int K) {
    extern __shared__ char smc[];
    unsigned smem_base = (unsigned)__cvta_generic_to_shared(smc);

    int tid  = threadIdx.x;
    int lane = tid & 31;
    int wid  = tid >> 5;
    int warp_m = wid & 1;
    int warp_n = wid >> 1;
    int bm = blockIdx.y * 128;
    int bn = blockIdx.x * BN;
    int grp = lane >> 2;
    int tig = lane & 3;

    const __half* aP[4]; unsigned aO[4];
    const __half* bP[4]; unsigned bO[4];
    #pragma unroll
    for (int l = 0; l < 4; ++l) {
        int idx = l * 128 + tid;
        int ar = idx >> 2, ac = idx & 3;
        aP[l] = A + (size_t)(bm + ar) * K + ac * 8;
        aO[l] = (unsigned)(ar * AROW2 + ac * 8) * 2u;
        int br = idx >> 4, bc = idx & 15;
        bP[l] = Bm + (size_t)br * N + bn + bc * 8;
        bO[l] = (unsigned)ASZ128 + (unsigned)(br * BROW2 + bc * 8) * 2u;
    }

    auto stage = [&](int t) {
        unsigned s = smem_base + (unsigned)(t % NSTG) * STG128;
        #pragma unroll
        for (int l = 0; l < 4; ++l) {
            cp16(s + aO[l], aP[l] + (size_t)t * BK);
            cp16(s + bO[l], bP[l] + (size_t)t * BK * N);
        }
        cp_commit();
    };

    float acc[4][8][4];
    #pragma unroll
    for (int i = 0; i < 4; ++i)
        #pragma unroll
        for (int j = 0; j < 8; ++j)
            #pragma unroll
            for (int r = 0; r < 4; ++r) acc[i][j][r] = 0.f;

    int ntiles = K / BK;
    stage(0); stage(1);

    unsigned aLrow = (unsigned)(warp_m * 64 + (lane & 15));
    unsigned aLcol = (unsigned)((lane >> 4) * 8);
    unsigned bLrow = (unsigned)(lane & 15);
    unsigned bLcol = (unsigned)(warp_n * 64 + (lane >> 4) * 8);

    for (int t = 0; t < ntiles; ++t) {
        if (t + 2 < ntiles) {
            stage(t + 2);
            asm volatile("cp.async.wait_group %0;\n" :: "n"(2));
        } else if (t + 1 < ntiles) {
            asm volatile("cp.async.wait_group %0;\n" :: "n"(1));
        } else {
            asm volatile("cp.async.wait_group %0;\n" :: "n"(0));
        }
        __syncthreads();

        unsigned base = smem_base + (unsigned)(t % NSTG) * STG128;

        #pragma unroll
        for (int ks = 0; ks < 2; ++ks) {
            unsigned af[4][4], bf[4][4];
            #pragma unroll
            for (int mi = 0; mi < 4; ++mi)
                ldsm4(af[mi], base +
                      (unsigned)(((aLrow + mi * 16) * AROW2) + ks * 16 + aLcol) * 2);
            #pragma unroll
            for (int j = 0; j < 4; ++j)
                ldsm4t(bf[j], base + (unsigned)ASZ128 +
                       (unsigned)(((ks * 16 + bLrow) * BROW2) + bLcol + j * 16) * 2);

            #pragma unroll
            for (int mi = 0; mi < 4; ++mi)
                #pragma unroll
                for (int ni = 0; ni < 8; ++ni)
                    mma16816(acc[mi][ni], af[mi],
                             bf[ni >> 1][(ni & 1) * 2 + 0],
                             bf[ni >> 1][(ni & 1) * 2 + 1]);
        }
        __syncthreads();
    }

    #pragma unroll
    for (int mi = 0; mi < 4; ++mi) {
        #pragma unroll
        for (int rr = 0; rr < 2; ++rr) {
            int r = bm + warp_m * 64 + mi * 16 + grp + rr * 8;
            #pragma unroll
            for (int ni = 0; ni < 8; ++ni) {
                int c = bn + warp_n * 64 + ni * 8 + 2 * tig;
                float v0 = acc[mi][ni][rr * 2 + 0];
                float v1 = acc[mi][ni][rr * 2 + 1];
                if (EPI == 2 || EPI == 3) { v0 += bias[c]; v1 += bias[c + 1]; }
                if (EPI == 2)             { v0 = gelu_f(v0); v1 = gelu_f(v1); }
                if (EPI == 1 || EPI == 3) {
                    const float* rp = res + (size_t)r * N + c;
                    v0 += rp[0]; v1 += rp[1];
                }
                if (EPI == 2 || EPI == 4) {
                    __half2 o;
                    o.x = __float2half_rn(v0);
                    o.y = __float2half_rn(v1);
                    *(__half2*)((__half*)Cv + (size_t)r * N + c) = o;
                } else {
                    float2 o2; o2.x = v0; o2.y = v1;
                    *(float2*)((float*)Cv + (size_t)r * N + c) = o2;
                }
            }
        }
    }
}

// ---------------- fp16 GEMM (BM=64): for N=768 GEMMs (wave balance) --------
#define ASZ64 (64 * AROW2 * 2)
#define STG64 (ASZ64 + BSZ2)
#define GEMM_SMEM64 (NSTG * STG64)

template <int EPI>
__global__ __launch_bounds__(128, 4) void gemm64_k(const __half* __restrict__ A,
                                                   const __half* __restrict__ Bm,
                                                   const float* __restrict__ bias,
                                                   const float* __restrict__ res,
                                                   void* __restrict__ Cv,
                                                   int M, int N, int K) {
    extern __shared__ char smc[];
    unsigned smem_base = (unsigned)__cvta_generic_to_shared(smc);

    int tid  = threadIdx.x;
    int lane = tid & 31;
    int wid  = tid >> 5;
    int warp_m = wid & 1;
    int warp_n = wid >> 1;
    int bm = blockIdx.y * 64;
    int bn = blockIdx.x * BN;
    int grp = lane >> 2;
    int tig = lane & 3;

    const __half* aP[2]; unsigned aO[2];
    const __half* bP[4]; unsigned bO[4];
    #pragma unroll
    for (int l = 0; l < 2; ++l) {
        int idx = l * 128 + tid;
        int ar = idx >> 2, ac = idx & 3;
        aP[l] = A + (size_t)(bm + ar) * K + ac * 8;
        aO[l] = (unsigned)(ar * AROW2 + ac * 8) * 2u;
    }
    #pragma unroll
    for (int l = 0; l < 4; ++l) {
        int idx = l * 128 + tid;
        int br = idx >> 4, bc = idx & 15;
        bP[l] = Bm + (size_t)br * N + bn + bc * 8;
        bO[l] = (unsigned)ASZ64 + (unsigned)(br * BROW2 + bc * 8) * 2u;
    }

    auto stage = [&](int t) {
        unsigned s = smem_base + (unsigned)(t % NSTG) * STG64;
        #pragma unroll
        for (int l = 0; l < 2; ++l)
            cp16(s + aO[l], aP[l] + (size_t)t * BK);
        #pragma unroll
        for (int l = 0; l < 4; ++l)
            cp16(s + bO[l], bP[l] + (size_t)t * BK * N);
        cp_commit();
    };

    float acc[2][8][4];
    #pragma unroll
    for (int i = 0; i < 2; ++i)
        #pragma unroll
        for (int j = 0; j < 8; ++j)
            #pragma unroll
            for (int r = 0; r < 4; ++r) acc[i][j][r] = 0.f;

    int ntiles = K / BK;
    stage(0); stage(1);

    unsigned aLrow = (unsigned)(warp_m * 32 + (lane & 15));
    unsigned aLcol = (unsigned)((lane >> 4) * 8);
    unsigned bLrow = (unsigned)(lane & 15);
    unsigned bLcol = (unsigned)(warp_n * 64 + (lane >> 4) * 8);

    for (int t = 0; t < ntiles; ++t) {
        if (t + 2 < ntiles) {
            stage(t + 2);
            asm volatile("cp.async.wait_group %0;\n" :: "n"(2));
        } else if (t + 1 < ntiles) {
            asm volatile("cp.async.wait_group %0;\n" :: "n"(1));
        } else {
            asm volatile("cp.async.wait_group %0;\n" :: "n"(0));
        }
        __syncthreads();

        unsigned base = smem_base + (unsigned)(t % NSTG) * STG64;

        #pragma unroll
        for (int ks = 0; ks < 2; ++ks) {
            unsigned af[2][4], bf[4][4];
            #pragma unroll
            for (int mi = 0; mi < 2; ++mi)
                ldsm4(af[mi], base +
                      (unsigned)(((aLrow + mi * 16) * AROW2) + ks * 16 + aLcol) * 2);
            #pragma unroll
            for (int j = 0; j < 4; ++j)
                ldsm4t(bf[j], base + (unsigned)ASZ64 +
                       (unsigned)(((ks * 16 + bLrow) * BROW2) + bLcol + j * 16) * 2);

            #pragma unroll
            for (int mi = 0; mi < 2; ++mi)
                #pragma unroll
                for (int ni = 0; ni < 8; ++ni)
                    mma16816(acc[mi][ni], af[mi],
                             bf[ni >> 1][(ni & 1) * 2 + 0],
                             bf[ni >> 1][(ni & 1) * 2 + 1]);
        }
        __syncthreads();
    }

    #pragma unroll
    for (int mi = 0; mi < 2; ++mi) {
        #pragma unroll
        for (int rr = 0; rr < 2; ++rr) {
            int r = bm + warp_m * 32 + mi * 16 + grp + rr * 8;
            #pragma unroll
            for (int ni = 0; ni < 8; ++ni) {
                int c = bn + warp_n * 64 + ni * 8 + 2 * tig;
                float v0 = acc[mi][ni][rr * 2 + 0];
                float v1 = acc[mi][ni][rr * 2 + 1];
                if (EPI == 2 || EPI == 3) { v0 += bias[c]; v1 += bias[c + 1]; }
                if (EPI == 2)             { v0 = gelu_f(v0); v1 = gelu_f(v1); }
                if (EPI == 1 || EPI == 3) {
                    const float* rp = res + (size_t)r * N + c;
                    v0 += rp[0]; v1 += rp[1];
                }
                if (EPI == 2 || EPI == 4) {
                    __half2 o;
                    o.x = __float2half_rn(v0);
                    o.y = __float2half_rn(v1);
                    *(__half2*)((__half*)Cv + (size_t)r * N + c) = o;
                } else {
                    float2 o2; o2.x = v0; o2.y = v1;
                    *(float2*)((float*)Cv + (size_t)r * N + c) = o2;
                }
            }
        }
    }
}

// ---------------- Flash attention: fp16 tensor cores (unchanged) -----------
#define KVP 72
#define Q_HALVES   (128 * KVP)
#define KV_STAGE_H (2 * 64 * KVP)
#define ATT_SMEM   ((Q_HALVES + 2 * KV_STAGE_H) * 2)

__global__ __launch_bounds__(256, 2) void attn_k(const __half* __restrict__ qkvh,
                                                 __half* __restrict__ y) {
    extern __shared__ __half smh[];
    unsigned smem_b = (unsigned)__cvta_generic_to_shared(smh);
    unsigned kvb    = smem_b + Q_HALVES * 2;

    int bh = blockIdx.y;
    int b  = bh / NH;
    int h  = bh % NH;
    int qt = gridDim.x - 1 - blockIdx.x;
    int q0 = qt * 128;
    size_t bT = (size_t)b * TSEQ;

    int tid  = threadIdx.x;
    int lane = tid & 31;
    int wid  = tid >> 5;
    int grp  = lane >> 2;
    int tig  = lane & 3;

    #pragma unroll
    for (int i = 0; i < 4; ++i) {
        int c = i * 256 + tid;
        int row = c >> 3, col8 = c & 7;
        const __half* src = qkvh + (bT + q0 + row) * (3 * CDIM) + h * HDIM + col8 * 8;
        cp16(smem_b + (unsigned)(row * KVP + col8 * 8) * 2, src);
    }
    cp_commit();

    auto kvissue = [&](int t) {
        int k0 = t * 64;
        unsigned sb = kvb + (unsigned)(t & 1) * (KV_STAGE_H * 2);
        #pragma unroll
        for (int i = 0; i < 4; ++i) {
            int c = i * 256 + tid;
            int isV = c >> 9;
            int cc = c & 511;
            int row = cc >> 3, col8 = cc & 7;
            const __half* src = qkvh + (bT + k0 + row) * (3 * CDIM)
                                + (1 + isV) * CDIM + h * HDIM + col8 * 8;
            cp16(sb + (unsigned)(isV * (64 * KVP) + row * KVP + col8 * 8) * 2, src);
        }
        cp_commit();
    };

    kvissue(0);
    asm volatile("cp.async.wait_group 0;\n" ::: "memory");
    __syncthreads();

    unsigned qf[4][4];
    {
        unsigned rowb = smem_b + (unsigned)((wid * 16 + (lane & 15)) * KVP) * 2;
        #pragma unroll
        for (int ch = 0; ch < 4; ++ch) {
            ldsm4(qf[ch], rowb + (unsigned)(ch * 16 + (lane >> 4) * 8) * 2);
            __half2 sc = __floats2half2_rn(0.125f, 0.125f);
            #pragma unroll
            for (int r = 0; r < 4; ++r) {
                __half2 v = *(__half2*)&qf[ch][r];
                v = __hmul2(v, sc);
                qf[ch][r] = *(unsigned*)&v;
            }
        }
    }

    float o[8][4];
    #pragma unroll
    for (int i = 0; i < 8; ++i)
        #pragma unroll
        for (int j = 0; j < 4; ++j) o[i][j] = 0.f;
    float m0 = -1e30f, m1 = -1e30f, l0 = 0.f, l1 = 0.f;

    int r0g = q0 + wid * 16 + grp;
    int ntiles = 2 * (qt + 1);

    for (int t = 0; t < ntiles; ++t) {
        if (t + 1 < ntiles) {
            kvissue(t + 1);
            asm volatile("cp.async.wait_group 1;\n" ::: "memory");
        } else {
            asm volatile("cp.async.wait_group 0;\n" ::: "memory");
        }
        __syncthreads();

        int k0 = t * 64;
        unsigned Ksb = kvb + (unsigned)(t & 1) * (KV_STAGE_H * 2);
        unsigned Vsb = Ksb + (unsigned)(64 * KVP) * 2;

        float s[8][4];
        #pragma unroll
        for (int i = 0; i < 8; ++i)
            #pragma unroll
            for (int j = 0; j < 4; ++j) s[i][j] = 0.f;

        int krow = (lane & 7) + ((lane >> 4) << 3);
        int kcol = ((lane >> 3) & 1) << 3;
        #pragma unroll
        for (int ch = 0; ch < 4; ++ch) {
            unsigned kf[4][4];
            #pragma unroll
            for (int p = 0; p < 4; ++p)
                ldsm4(kf[p], Ksb + (unsigned)((p * 16 + krow) * KVP + ch * 16 + kcol) * 2);
            #pragma unroll
            for (int nt = 0; nt < 8; ++nt)
                mma16816(s[nt], qf[ch],
                         kf[nt >> 1][(nt & 1) * 2 + 0],
                         kf[nt >> 1][(nt & 1) * 2 + 1]);
        }

        if (k0 + 63 > r0g + 8) {
            #pragma unroll
            for (int nt = 0; nt < 8; ++nt) {
                int c0 = k0 + nt * 8 + 2 * tig;
                if (c0     > r0g)     s[nt][0] = -1e30f;
                if (c0 + 1 > r0g)     s[nt][1] = -1e30f;
                if (c0     > r0g + 8) s[nt][2] = -1e30f;
                if (c0 + 1 > r0g + 8) s[nt][3] = -1e30f;
            }
        }

        float mx0 = -1e30f, mx1 = -1e30f;
        #pragma unroll
        for (int nt = 0; nt < 8; ++nt) {
            mx0 = fmaxf(mx0, fmaxf(s[nt][0], s[nt][1]));
            mx1 = fmaxf(mx1, fmaxf(s[nt][2], s[nt][3]));
        }
        mx0 = fmaxf(mx0, __shfl_xor_sync(0xffffffffu, mx0, 1));
        mx0 = fmaxf(mx0, __shfl_xor_sync(0xffffffffu, mx0, 2));
        mx1 = fmaxf(mx1, __shfl_xor_sync(0xffffffffu, mx1, 1));
        mx1 = fmaxf(mx1, __shfl_xor_sync(0xffffffffu, mx1, 2));

        float mn0 = fmaxf(m0, mx0), mn1 = fmaxf(m1, mx1);
        float cr0 = __expf(m0 - mn0), cr1 = __expf(m1 - mn1);
        m0 = mn0; m1 = mn1;

        float sum0 = 0.f, sum1 = 0.f;
        #pragma unroll
        for (int nt = 0; nt < 8; ++nt) {
            s[nt][0] = __expf(s[nt][0] - mn0); sum0 += s[nt][0];
            s[nt][1] = __expf(s[nt][1] - mn0); sum0 += s[nt][1];
            s[nt][2] = __expf(s[nt][2] - mn1); sum1 += s[nt][2];
            s[nt][3] = __expf(s[nt][3] - mn1); sum1 += s[nt][3];
        }
        sum0 += __shfl_xor_sync(0xffffffffu, sum0, 1);
        sum0 += __shfl_xor_sync(0xffffffffu, sum0, 2);
        sum1 += __shfl_xor_sync(0xffffffffu, sum1, 1);
        sum1 += __shfl_xor_sync(0xffffffffu, sum1, 2);
        l0 = l0 * cr0 + sum0;
        l1 = l1 * cr1 + sum1;

        #pragma unroll
        for (int nt = 0; nt < 8; ++nt) {
            o[nt][0] *= cr0; o[nt][1] *= cr0;
            o[nt][2] *= cr1; o[nt][3] *= cr1;
        }

        int vrow = (lane & 7) + (((lane >> 3) & 1) << 3);
        int vcol = (lane >> 4) << 3;
        #pragma unroll
        for (int c = 0; c < 4; ++c) {
            unsigned pa[4];
            pa[0] = f22h2(s[2 * c][0],     s[2 * c][1]);
            pa[1] = f22h2(s[2 * c][2],     s[2 * c][3]);
            pa[2] = f22h2(s[2 * c + 1][0], s[2 * c + 1][1]);
            pa[3] = f22h2(s[2 * c + 1][2], s[2 * c + 1][3]);

            unsigned vf[4][4];
            #pragma unroll
            for (int p = 0; p < 4; ++p)
                ldsm4t(vf[p], Vsb + (unsigned)((c * 16 + vrow) * KVP + p * 16 + vcol) * 2);

            #pragma unroll
            for (int dt = 0; dt < 8; ++dt)
                mma16816(o[dt], pa,
                         vf[dt >> 1][(dt & 1) * 2 + 0],
                         vf[dt >> 1][(dt & 1) * 2 + 1]);
        }
        __syncthreads();
    }

    float i0 = 1.f / l0, i1 = 1.f / l1;
    __half* y0 = y + (bT + r0g) * CDIM + h * HDIM;
    __half* y1 = y0 + 8 * CDIM;
    #pragma unroll
    for (int dt = 0; dt < 8; ++dt) {
        __half2 a, bb;
        a.x  = __float2half_rn(o[dt][0] * i0);
        a.y  = __float2half_rn(o[dt][1] * i0);
        bb.x = __float2half_rn(o[dt][2] * i1);
        bb.y = __float2half_rn(o[dt][3] * i1);
        *(__half2*)(y0 + dt * 8 + 2 * tig) = a;
        *(__half2*)(y1 + dt * 8 + 2 * tig) = bb;
    }
}

// ---------------- launch --------------------------------------------------
extern "C" void kernel_launch(void* const* d_in, const int* in_sizes, int n_in,
                              void* d_out, int out_size) {
    const float* x      = (const float*)d_in[0];
    const float* ln1_g  = (const float*)d_in[1];
    const float* ln1_b  = (const float*)d_in[2];
    const float* w_qkv  = (const float*)d_in[3];
    const float* w_o    = (const float*)d_in[4];
    const float* ln2_g  = (const float*)d_in[5];
    const float* ln2_b  = (const float*)d_in[6];
    const float* w_fc   = (const float*)d_in[7];
    const float* b_fc   = (const float*)d_in[8];
    const float* w_proj = (const float*)d_in[9];
    const float* b_proj = (const float*)d_in[10];
    float* out = (float*)d_out;

    __half *lnh, *qkvh, *atth, *hh, *wqkv_h, *wo_h, *wfc_h, *wproj_h;
    float *x1;
    cudaGetSymbolAddress((void**)&lnh,  g_lnh);
    cudaGetSymbolAddress((void**)&qkvh, g_qkvh);
    cudaGetSymbolAddress((void**)&atth, g_atth);
    cudaGetSymbolAddress((void**)&x1,   g_x1);
    cudaGetSymbolAddress((void**)&hh,   g_hh);
    cudaGetSymbolAddress((void**)&wqkv_h,  g_wqkv_h);
    cudaGetSymbolAddress((void**)&wo_h,    g_wo_h);
    cudaGetSymbolAddress((void**)&wfc_h,   g_wfc_h);
    cudaGetSymbolAddress((void**)&wproj_h, g_wproj_h);

    static int smem_set = 0;
    if (!smem_set) {
        cudaFuncSetAttribute(attn_k, cudaFuncAttributeMaxDynamicSharedMemorySize, ATT_SMEM);
        cudaFuncSetAttribute(gemm_k<2>, cudaFuncAttributeMaxDynamicSharedMemorySize, GEMM_SMEM128);
        cudaFuncSetAttribute(gemm_k<4>, cudaFuncAttributeMaxDynamicSharedMemorySize, GEMM_SMEM128);
        cudaFuncSetAttribute(gemm64_k<1>, cudaFuncAttributeMaxDynamicSharedMemorySize, GEMM_SMEM64);
        cudaFuncSetAttribute(gemm64_k<3>, cudaFuncAttributeMaxDynamicSharedMemorySize, GEMM_SMEM64);
        smem_set = 1;
    }

    // ALL weights -> fp16 in one launch
    roundall_k<<<(NCHUNK + 255) / 256, 256>>>(w_qkv, w_o, w_fc, w_proj,
                                              wqkv_h, wo_h, wfc_h, wproj_h);

    ln_k<<<ROWS / 8, 256>>>(x, ln1_g, ln1_b, lnh);
    gemm_k<4><<<dim3(3 * CDIM / BN, ROWS / 128), 128, GEMM_SMEM128>>>(lnh, wqkv_h, nullptr, nullptr,
                                                                      qkvh, ROWS, 3 * CDIM, CDIM);
    attn_k<<<dim3(TSEQ / 128, NB * NH), 256, ATT_SMEM>>>(qkvh, atth);
    gemm64_k<1><<<dim3(CDIM / BN, ROWS / 64), 128, GEMM_SMEM64>>>(atth, wo_h, nullptr, x,
                                                                  x1, ROWS, CDIM, CDIM);
    ln_k<<<ROWS / 8, 256>>>(x1, ln2_g, ln2_b, lnh);
    gemm_k<2><<<dim3(DFF / BN, ROWS / 128), 128, GEMM_SMEM128>>>(lnh, wfc_h, b_fc, nullptr,
                                                                 hh, ROWS, DFF, CDIM);
    gemm64_k<3><<<dim3(CDIM / BN, ROWS / 64), 128, GEMM_SMEM64>>>(hh, wproj_h, b_proj, x1,
                                                                  out, ROWS, CDIM, DFF);
}

// round 13
// speedup vs baseline: 15.6913x; 1.0239x over previous
#include <cuda_runtime.h>
#include <cuda_fp16.h>
#include <math.h>

#define TSEQ 2048
#define NB   2
#define CDIM 768
#define NH   12
#define HDIM 64
#define DFF  3072
#define ROWS (NB * TSEQ)   // 4096

// ---------------- scratch (device globals: allocation-free) ----------------
__device__ __half g_lnh [ROWS * CDIM];
__device__ __half g_qkvh[ROWS * 3 * CDIM];
__device__ __half g_atth[ROWS * CDIM];
__device__ float  g_x1  [ROWS * CDIM];
__device__ __half g_hh  [ROWS * DFF];
__device__ __half g_wqkv_h [CDIM * 3 * CDIM];
__device__ __half g_wo_h   [CDIM * CDIM];
__device__ __half g_wfc_h  [CDIM * DFF];
__device__ __half g_wproj_h[DFF * CDIM];

__device__ __forceinline__ float gelu_f(float v) {
    return 0.5f * v * (1.0f + erff(v * 0.70710678118654752f));
}

union Pack4 { __half h[4]; uint2 u; };

__device__ __forceinline__ void cp16(unsigned dst, const void* src) {
    asm volatile("cp.async.cg.shared.global [%0], [%1], 16;\n"
                 :: "r"(dst), "l"(src) : "memory");
}
__device__ __forceinline__ void cp_commit() {
    asm volatile("cp.async.commit_group;\n" ::: "memory");
}
__device__ __forceinline__ void ldsm4(unsigned* r, unsigned addr) {
    asm volatile("ldmatrix.sync.aligned.m8n8.x4.shared.b16 {%0,%1,%2,%3}, [%4];"
                 : "=r"(r[0]), "=r"(r[1]), "=r"(r[2]), "=r"(r[3]) : "r"(addr));
}
__device__ __forceinline__ void ldsm4t(unsigned* r, unsigned addr) {
    asm volatile("ldmatrix.sync.aligned.m8n8.x4.trans.shared.b16 {%0,%1,%2,%3}, [%4];"
                 : "=r"(r[0]), "=r"(r[1]), "=r"(r[2]), "=r"(r[3]) : "r"(addr));
}
__device__ __forceinline__ void ldsm2t(unsigned& r0, unsigned& r1, unsigned addr) {
    asm volatile("ldmatrix.sync.aligned.m8n8.x2.trans.shared.b16 {%0,%1}, [%2];"
                 : "=r"(r0), "=r"(r1) : "r"(addr));
}
__device__ __forceinline__ void mma16816(float* c, const unsigned* a,
                                         unsigned b0, unsigned b1) {
    asm volatile(
        "mma.sync.aligned.m16n8k16.row.col.f32.f16.f16.f32 "
        "{%0,%1,%2,%3}, {%4,%5,%6,%7}, {%8,%9}, {%0,%1,%2,%3};"
        : "+f"(c[0]), "+f"(c[1]), "+f"(c[2]), "+f"(c[3])
        : "r"(a[0]), "r"(a[1]), "r"(a[2]), "r"(a[3]), "r"(b0), "r"(b1));
}
__device__ __forceinline__ unsigned f22h2(float x, float y) {
    __half2 h = __floats2half2_rn(x, y);
    return *(unsigned*)&h;
}
__device__ __forceinline__ unsigned h2exp2_u(unsigned x) {
    unsigned r;
    asm("ex2.approx.f16x2 %0, %1;" : "=r"(r) : "r"(x));
    return r;
}

// ---------------- ALL weights fp32 -> fp16 in ONE kernel -------------------
#define N4_QKV  (CDIM * 3 * CDIM / 4)
#define N4_O    (CDIM * CDIM / 4)
#define N4_FC   (CDIM * DFF / 4)
#define N4_PROJ (DFF * CDIM / 4)
#define N4_TOT  (N4_QKV + N4_O + N4_FC + N4_PROJ)
#define NCHUNK  (N4_TOT / 4)

__global__ __launch_bounds__(256) void roundall_k(const float* __restrict__ wqkv,
                                                  const float* __restrict__ wo,
                                                  const float* __restrict__ wfc,
                                                  const float* __restrict__ wproj,
                                                  __half* __restrict__ oqkv,
                                                  __half* __restrict__ oo,
                                                  __half* __restrict__ ofc,
                                                  __half* __restrict__ oproj) {
    int base = (blockIdx.x * 256 + threadIdx.x) * 4;
    if (base >= N4_TOT) return;

    const float4* src;
    uint2* dst;
    int off;
    if (base < N4_QKV) {
        src = (const float4*)wqkv;  dst = (uint2*)oqkv;  off = base;
    } else if (base < N4_QKV + N4_O) {
        src = (const float4*)wo;    dst = (uint2*)oo;    off = base - N4_QKV;
    } else if (base < N4_QKV + N4_O + N4_FC) {
        src = (const float4*)wfc;   dst = (uint2*)ofc;   off = base - N4_QKV - N4_O;
    } else {
        src = (const float4*)wproj; dst = (uint2*)oproj; off = base - N4_QKV - N4_O - N4_FC;
    }

    float4 v0 = src[off + 0], v1 = src[off + 1],
           v2 = src[off + 2], v3 = src[off + 3];
    Pack4 p0, p1, p2, p3;
    p0.h[0] = __float2half_rn(v0.x); p0.h[1] = __float2half_rn(v0.y);
    p0.h[2] = __float2half_rn(v0.z); p0.h[3] = __float2half_rn(v0.w);
    p1.h[0] = __float2half_rn(v1.x); p1.h[1] = __float2half_rn(v1.y);
    p1.h[2] = __float2half_rn(v1.z); p1.h[3] = __float2half_rn(v1.w);
    p2.h[0] = __float2half_rn(v2.x); p2.h[1] = __float2half_rn(v2.y);
    p2.h[2] = __float2half_rn(v2.z); p2.h[3] = __float2half_rn(v2.w);
    p3.h[0] = __float2half_rn(v3.x); p3.h[1] = __float2half_rn(v3.y);
    p3.h[2] = __float2half_rn(v3.z); p3.h[3] = __float2half_rn(v3.w);
    dst[off + 0] = p0.u; dst[off + 1] = p1.u;
    dst[off + 2] = p2.u; dst[off + 3] = p3.u;
}

// ---------------- LayerNorm: one warp per row (fp32 in, fp16 out) ----------
__global__ __launch_bounds__(256) void ln_k(const float* __restrict__ xin,
                                            const float* __restrict__ g,
                                            const float* __restrict__ b,
                                            __half* __restrict__ out) {
    int row  = blockIdx.x * 8 + (threadIdx.x >> 5);
    int lane = threadIdx.x & 31;
    const float4* xr = (const float4*)(xin + (size_t)row * CDIM);

    float4 v[6];
    float s = 0.f, ss = 0.f;
    #pragma unroll
    for (int i = 0; i < 6; ++i) {
        v[i] = xr[i * 32 + lane];
        s  += v[i].x + v[i].y + v[i].z + v[i].w;
        ss += v[i].x * v[i].x + v[i].y * v[i].y
            + v[i].z * v[i].z + v[i].w * v[i].w;
    }
    #pragma unroll
    for (int off = 16; off > 0; off >>= 1) {
        s  += __shfl_xor_sync(0xffffffffu, s,  off);
        ss += __shfl_xor_sync(0xffffffffu, ss, off);
    }

    const float inv = 1.0f / (float)CDIM;
    float mu   = s * inv;
    float var  = ss * inv - mu * mu;
    float rstd = rsqrtf(var + 1e-5f);

    const float4* g4 = (const float4*)g;
    const float4* b4 = (const float4*)b;
    __half* orow = out + (size_t)row * CDIM;
    #pragma unroll
    for (int i = 0; i < 6; ++i) {
        int c4 = i * 32 + lane;
        float4 gv = g4[c4];
        float4 bv = b4[c4];
        Pack4 p;
        p.h[0] = __float2half_rn((v[i].x - mu) * rstd * gv.x + bv.x);
        p.h[1] = __float2half_rn((v[i].y - mu) * rstd * gv.y + bv.y);
        p.h[2] = __float2half_rn((v[i].z - mu) * rstd * gv.z + bv.z);
        p.h[3] = __float2half_rn((v[i].w - mu) * rstd * gv.w + bv.w);
        *(uint2*)(orow + c4 * 4) = p.u;
    }
}

// ---------------- fp16 GEMM (BM=128): 4 warps, 64x64 warp tiles, BK=32 -----
// EPI: 1 +res(f32), 2 +bias+GELU(fp16), 3 +bias+res(f32), 4 none(fp16)
#define BN 128
#define BK 32
#define AROW2 40
#define BROW2 136
#define BSZ2 (BK * BROW2 * 2)
#define NSTG 3

#define ASZ128 (128 * AROW2 * 2)
#define STG128 (ASZ128 + BSZ2)
#define GEMM_SMEM128 (NSTG * STG128)

template <int EPI>
__global__ __launch_bounds__(128, 2) void gemm_k(const __half* __restrict__ A,
                                                 const __half* __restrict__ Bm,
                                                 const float* __restrict__ bias,
                                                 const float* __restrict__ res,
                                                 void* __restrict__ Cv,
                                                 int M, int N, int K) {
    extern __shared__ char smc[];
    unsigned smem_base = (unsigned)__cvta_generic_to_shared(smc);

    int tid  = threadIdx.x;
    int lane = tid & 31;
    int wid  = tid >> 5;
    int warp_m = wid & 1;
    int warp_n = wid >> 1;
    int bm = blockIdx.y * 128;
    int bn = blockIdx.x * BN;
    int grp = lane >> 2;
    int tig = lane & 3;

    const __half* aP[4]; unsigned aO[4];
    const __half* bP[4]; unsigned bO[4];
    #pragma unroll
    for (int l = 0; l < 4; ++l) {
        int idx = l * 128 + tid;
        int ar = idx >> 2, ac = idx & 3;
        aP[l] = A + (size_t)(bm + ar) * K + ac * 8;
        aO[l] = (unsigned)(ar * AROW2 + ac * 8) * 2u;
        int br = idx >> 4, bc = idx & 15;
        bP[l] = Bm + (size_t)br * N + bn + bc * 8;
        bO[l] = (unsigned)ASZ128 + (unsigned)(br * BROW2 + bc * 8) * 2u;
    }

    auto stage = [&](int t) {
        unsigned s = smem_base + (unsigned)(t % NSTG) * STG128;
        #pragma unroll
        for (int l = 0; l < 4; ++l) {
            cp16(s + aO[l], aP[l] + (size_t)t * BK);
            cp16(s + bO[l], bP[l] + (size_t)t * BK * N);
        }
        cp_commit();
    };

    float acc[4][8][4];
    #pragma unroll
    for (int i = 0; i < 4; ++i)
        #pragma unroll
        for (int j = 0; j < 8; ++j)
            #pragma unroll
            for (int r = 0; r < 4; ++r) acc[i][j][r] = 0.f;

    int ntiles = K / BK;
    stage(0); stage(1);

    unsigned aLrow = (unsigned)(warp_m * 64 + (lane & 15));
    unsigned aLcol = (unsigned)((lane >> 4) * 8);
    unsigned bLrow = (unsigned)(lane & 15);
    unsigned bLcol = (unsigned)(warp_n * 64 + (lane >> 4) * 8);

    for (int t = 0; t < ntiles; ++t) {
        if (t + 2 < ntiles) {
            stage(t + 2);
            asm volatile("cp.async.wait_group %0;\n" :: "n"(2));
        } else if (t + 1 < ntiles) {
            asm volatile("cp.async.wait_group %0;\n" :: "n"(1));
        } else {
            asm volatile("cp.async.wait_group %0;\n" :: "n"(0));
        }
        __syncthreads();

        unsigned base = smem_base + (unsigned)(t % NSTG) * STG128;

        #pragma unroll
        for (int ks = 0; ks < 2; ++ks) {
            unsigned af[4][4], bf[4][4];
            #pragma unroll
            for (int mi = 0; mi < 4; ++mi)
                ldsm4(af[mi], base +
                      (unsigned)(((aLrow + mi * 16) * AROW2) + ks * 16 + aLcol) * 2);
            #pragma unroll
            for (int j = 0; j < 4; ++j)
                ldsm4t(bf[j], base + (unsigned)ASZ128 +
                       (unsigned)(((ks * 16 + bLrow) * BROW2) + bLcol + j * 16) * 2);

            #pragma unroll
            for (int mi = 0; mi < 4; ++mi)
                #pragma unroll
                for (int ni = 0; ni < 8; ++ni)
                    mma16816(acc[mi][ni], af[mi],
                             bf[ni >> 1][(ni & 1) * 2 + 0],
                             bf[ni >> 1][(ni & 1) * 2 + 1]);
        }
        __syncthreads();
    }

    #pragma unroll
    for (int mi = 0; mi < 4; ++mi) {
        #pragma unroll
        for (int rr = 0; rr < 2; ++rr) {
            int r = bm + warp_m * 64 + mi * 16 + grp + rr * 8;
            #pragma unroll
            for (int ni = 0; ni < 8; ++ni) {
                int c = bn + warp_n * 64 + ni * 8 + 2 * tig;
                float v0 = acc[mi][ni][rr * 2 + 0];
                float v1 = acc[mi][ni][rr * 2 + 1];
                if (EPI == 2 || EPI == 3) { v0 += bias[c]; v1 += bias[c + 1]; }
                if (EPI == 2)             { v0 = gelu_f(v0); v1 = gelu_f(v1); }
                if (EPI == 1 || EPI == 3) {
                    const float* rp = res + (size_t)r * N + c;
                    v0 += rp[0]; v1 += rp[1];
                }
                if (EPI == 2 || EPI == 4) {
                    __half2 o;
                    o.x = __float2half_rn(v0);
                    o.y = __float2half_rn(v1);
                    *(__half2*)((__half*)Cv + (size_t)r * N + c) = o;
                } else {
                    float2 o2; o2.x = v0; o2.y = v1;
                    *(float2*)((float*)Cv + (size_t)r * N + c) = o2;
                }
            }
        }
    }
}

// ---------------- fp16 GEMM (BM=64): for N=768 GEMMs (wave balance) --------
#define ASZ64 (64 * AROW2 * 2)
#define STG64 (ASZ64 + BSZ2)
#define GEMM_SMEM64 (NSTG * STG64)

template <int EPI>
__global__ __launch_bounds__(128, 4) void gemm64_k(const __half* __restrict__ A,
                                                   const __half* __restrict__ Bm,
                                                   const float* __restrict__ bias,
                                                   const float* __restrict__ res,
                                                   void* __restrict__ Cv,
                                                   int M, int N, int K) {
    extern __shared__ char smc[];
    unsigned smem_base = (unsigned)__cvta_generic_to_shared(smc);

    int tid  = threadIdx.x;
    int lane = tid & 31;
    int wid  = tid >> 5;
    int warp_m = wid & 1;
    int warp_n = wid >> 1;
    int bm = blockIdx.y * 64;
    int bn = blockIdx.x * BN;
    int grp = lane >> 2;
    int tig = lane & 3;

    const __half* aP[2]; unsigned aO[2];
    const __half* bP[4]; unsigned bO[4];
    #pragma unroll
    for (int l = 0; l < 2; ++l) {
        int idx = l * 128 + tid;
        int ar = idx >> 2, ac = idx & 3;
        aP[l] = A + (size_t)(bm + ar) * K + ac * 8;
        aO[l] = (unsigned)(ar * AROW2 + ac * 8) * 2u;
    }
    #pragma unroll
    for (int l = 0; l < 4; ++l) {
        int idx = l * 128 + tid;
        int br = idx >> 4, bc = idx & 15;
        bP[l] = Bm + (size_t)br * N + bn + bc * 8;
        bO[l] = (unsigned)ASZ64 + (unsigned)(br * BROW2 + bc * 8) * 2u;
    }

    auto stage = [&](int t) {
        unsigned s = smem_base + (unsigned)(t % NSTG) * STG64;
        #pragma unroll
        for (int l = 0; l < 2; ++l)
            cp16(s + aO[l], aP[l] + (size_t)t * BK);
        #pragma unroll
        for (int l = 0; l < 4; ++l)
            cp16(s + bO[l], bP[l] + (size_t)t * BK * N);
        cp_commit();
    };

    float acc[2][8][4];
    #pragma unroll
    for (int i = 0; i < 2; ++i)
        #pragma unroll
        for (int j = 0; j < 8; ++j)
            #pragma unroll
            for (int r = 0; r < 4; ++r) acc[i][j][r] = 0.f;

    int ntiles = K / BK;
    stage(0); stage(1);

    unsigned aLrow = (unsigned)(warp_m * 32 + (lane & 15));
    unsigned aLcol = (unsigned)((lane >> 4) * 8);
    unsigned bLrow = (unsigned)(lane & 15);
    unsigned bLcol = (unsigned)(warp_n * 64 + (lane >> 4) * 8);

    for (int t = 0; t < ntiles; ++t) {
        if (t + 2 < ntiles) {
            stage(t + 2);
            asm volatile("cp.async.wait_group %0;\n" :: "n"(2));
        } else if (t + 1 < ntiles) {
            asm volatile("cp.async.wait_group %0;\n" :: "n"(1));
        } else {
            asm volatile("cp.async.wait_group %0;\n" :: "n"(0));
        }
        __syncthreads();

        unsigned base = smem_base + (unsigned)(t % NSTG) * STG64;

        #pragma unroll
        for (int ks = 0; ks < 2; ++ks) {
            unsigned af[2][4], bf[4][4];
            #pragma unroll
            for (int mi = 0; mi < 2; ++mi)
                ldsm4(af[mi], base +
                      (unsigned)(((aLrow + mi * 16) * AROW2) + ks * 16 + aLcol) * 2);
            #pragma unroll
            for (int j = 0; j < 4; ++j)
                ldsm4t(bf[j], base + (unsigned)ASZ64 +
                       (unsigned)(((ks * 16 + bLrow) * BROW2) + bLcol + j * 16) * 2);

            #pragma unroll
            for (int mi = 0; mi < 2; ++mi)
                #pragma unroll
                for (int ni = 0; ni < 8; ++ni)
                    mma16816(acc[mi][ni], af[mi],
                             bf[ni >> 1][(ni & 1) * 2 + 0],
                             bf[ni >> 1][(ni & 1) * 2 + 1]);
        }
        __syncthreads();
    }

    #pragma unroll
    for (int mi = 0; mi < 2; ++mi) {
        #pragma unroll
        for (int rr = 0; rr < 2; ++rr) {
            int r = bm + warp_m * 32 + mi * 16 + grp + rr * 8;
            #pragma unroll
            for (int ni = 0; ni < 8; ++ni) {
                int c = bn + warp_n * 64 + ni * 8 + 2 * tig;
                float v0 = acc[mi][ni][rr * 2 + 0];
                float v1 = acc[mi][ni][rr * 2 + 1];
                if (EPI == 2 || EPI == 3) { v0 += bias[c]; v1 += bias[c + 1]; }
                if (EPI == 2)             { v0 = gelu_f(v0); v1 = gelu_f(v1); }
                if (EPI == 1 || EPI == 3) {
                    const float* rp = res + (size_t)r * N + c;
                    v0 += rp[0]; v1 += rp[1];
                }
                if (EPI == 2 || EPI == 4) {
                    __half2 o;
                    o.x = __float2half_rn(v0);
                    o.y = __float2half_rn(v1);
                    *(__half2*)((__half*)Cv + (size_t)r * N + c) = o;
                } else {
                    float2 o2; o2.x = v0; o2.y = v1;
                    *(float2*)((float*)Cv + (size_t)r * N + c) = o2;
                }
            }
        }
    }
}

// ---------------- Flash attention: fp16 TC + fp16x2 exp + ones-col l -------
// Scores in log2 domain (log2e folded into Q scale). l accumulated by an
// extra ones-column MMA into fp32 (exact sum of the fp16 p's used for PV).
#define KVP 72
#define Q_HALVES   (128 * KVP)
#define KV_STAGE_H (2 * 64 * KVP)
#define ATT_SMEM   ((Q_HALVES + 2 * KV_STAGE_H) * 2)
#define QSCALE     0.1803368801111244f   // 0.125 * log2(e)

__global__ __launch_bounds__(256, 2) void attn_k(const __half* __restrict__ qkvh,
                                                 __half* __restrict__ y) {
    extern __shared__ __half smh[];
    unsigned smem_b = (unsigned)__cvta_generic_to_shared(smh);
    unsigned kvb    = smem_b + Q_HALVES * 2;

    int bh = blockIdx.y;
    int b  = bh / NH;
    int h  = bh % NH;
    int qt = gridDim.x - 1 - blockIdx.x;
    int q0 = qt * 128;
    size_t bT = (size_t)b * TSEQ;

    int tid  = threadIdx.x;
    int lane = tid & 31;
    int wid  = tid >> 5;
    int grp  = lane >> 2;
    int tig  = lane & 3;

    // init V pad columns (64 = 1.0, 65-71 = 0) in BOTH stage buffers.
    // cp.async only writes cols 0..63, so this persists across tiles.
    if (tid < 128) {
        int sbuf = tid >> 6, r = tid & 63;
        __half* vp = smh + Q_HALVES + sbuf * KV_STAGE_H + 64 * KVP + r * KVP + 64;
        uint4 ones = {0x00003C00u, 0u, 0u, 0u};   // {1.0h, 0...0}
        *(uint4*)vp = ones;
    }

    #pragma unroll
    for (int i = 0; i < 4; ++i) {
        int c = i * 256 + tid;
        int row = c >> 3, col8 = c & 7;
        const __half* src = qkvh + (bT + q0 + row) * (3 * CDIM) + h * HDIM + col8 * 8;
        cp16(smem_b + (unsigned)(row * KVP + col8 * 8) * 2, src);
    }
    cp_commit();

    auto kvissue = [&](int t) {
        int k0 = t * 64;
        unsigned sb = kvb + (unsigned)(t & 1) * (KV_STAGE_H * 2);
        #pragma unroll
        for (int i = 0; i < 4; ++i) {
            int c = i * 256 + tid;
            int isV = c >> 9;
            int cc = c & 511;
            int row = cc >> 3, col8 = cc & 7;
            const __half* src = qkvh + (bT + k0 + row) * (3 * CDIM)
                                + (1 + isV) * CDIM + h * HDIM + col8 * 8;
            cp16(sb + (unsigned)(isV * (64 * KVP) + row * KVP + col8 * 8) * 2, src);
        }
        cp_commit();
    };

    kvissue(0);
    asm volatile("cp.async.wait_group 0;\n" ::: "memory");
    __syncthreads();

    unsigned qf[4][4];
    {
        unsigned rowb = smem_b + (unsigned)((wid * 16 + (lane & 15)) * KVP) * 2;
        #pragma unroll
        for (int ch = 0; ch < 4; ++ch) {
            ldsm4(qf[ch], rowb + (unsigned)(ch * 16 + (lane >> 4) * 8) * 2);
            __half2 sc = __floats2half2_rn(QSCALE, QSCALE);
            #pragma unroll
            for (int r = 0; r < 4; ++r) {
                __half2 v = *(__half2*)&qf[ch][r];
                v = __hmul2(v, sc);
                qf[ch][r] = *(unsigned*)&v;
            }
        }
    }

    float o[8][4];
    #pragma unroll
    for (int i = 0; i < 8; ++i)
        #pragma unroll
        for (int j = 0; j < 4; ++j) o[i][j] = 0.f;
    float lacc[4];
    lacc[0] = lacc[1] = lacc[2] = lacc[3] = 0.f;
    float m0 = -1e30f, m1 = -1e30f;

    int r0g = q0 + wid * 16 + grp;
    int ntiles = 2 * (qt + 1);

    for (int t = 0; t < ntiles; ++t) {
        if (t + 1 < ntiles) {
            kvissue(t + 1);
            asm volatile("cp.async.wait_group 1;\n" ::: "memory");
        } else {
            asm volatile("cp.async.wait_group 0;\n" ::: "memory");
        }
        __syncthreads();

        int k0 = t * 64;
        unsigned Ksb = kvb + (unsigned)(t & 1) * (KV_STAGE_H * 2);
        unsigned Vsb = Ksb + (unsigned)(64 * KVP) * 2;

        float s[8][4];
        #pragma unroll
        for (int i = 0; i < 8; ++i)
            #pragma unroll
            for (int j = 0; j < 4; ++j) s[i][j] = 0.f;

        int krow = (lane & 7) + ((lane >> 4) << 3);
        int kcol = ((lane >> 3) & 1) << 3;
        #pragma unroll
        for (int ch = 0; ch < 4; ++ch) {
            unsigned kf[4][4];
            #pragma unroll
            for (int p = 0; p < 4; ++p)
                ldsm4(kf[p], Ksb + (unsigned)((p * 16 + krow) * KVP + ch * 16 + kcol) * 2);
            #pragma unroll
            for (int nt = 0; nt < 8; ++nt)
                mma16816(s[nt], qf[ch],
                         kf[nt >> 1][(nt & 1) * 2 + 0],
                         kf[nt >> 1][(nt & 1) * 2 + 1]);
        }

        if (k0 + 63 > r0g + 8) {
            #pragma unroll
            for (int nt = 0; nt < 8; ++nt) {
                int c0 = k0 + nt * 8 + 2 * tig;
                if (c0     > r0g)     s[nt][0] = -1e30f;
                if (c0 + 1 > r0g)     s[nt][1] = -1e30f;
                if (c0     > r0g + 8) s[nt][2] = -1e30f;
                if (c0 + 1 > r0g + 8) s[nt][3] = -1e30f;
            }
        }

        // ---- online softmax (log2 domain) ----
        float mx0 = -1e30f, mx1 = -1e30f;
        #pragma unroll
        for (int nt = 0; nt < 8; ++nt) {
            mx0 = fmaxf(mx0, fmaxf(s[nt][0], s[nt][1]));
            mx1 = fmaxf(mx1, fmaxf(s[nt][2], s[nt][3]));
        }
        mx0 = fmaxf(mx0, __shfl_xor_sync(0xffffffffu, mx0, 1));
        mx0 = fmaxf(mx0, __shfl_xor_sync(0xffffffffu, mx0, 2));
        mx1 = fmaxf(mx1, __shfl_xor_sync(0xffffffffu, mx1, 1));
        mx1 = fmaxf(mx1, __shfl_xor_sync(0xffffffffu, mx1, 2));

        float mn0 = fmaxf(m0, mx0), mn1 = fmaxf(m1, mx1);
        float cr0 = exp2f(m0 - mn0), cr1 = exp2f(m1 - mn1);
        m0 = mn0; m1 = mn1;

        #pragma unroll
        for (int nt = 0; nt < 8; ++nt) {
            o[nt][0] *= cr0; o[nt][1] *= cr0;
            o[nt][2] *= cr1; o[nt][3] *= cr1;
        }
        lacc[0] *= cr0; lacc[1] *= cr0;
        lacc[2] *= cr1; lacc[3] *= cr1;

        // ---- O += P V, l += P . ones (p = 2^(s-m) in fp16) ----
        int vrow = (lane & 7) + (((lane >> 3) & 1) << 3);
        int vcol = (lane >> 4) << 3;
        unsigned onesAddr = Vsb +
            (unsigned)(((lane & 15)) * KVP + 64) * 2;   // + c*16*KVP*2 added below
        #pragma unroll
        for (int c = 0; c < 4; ++c) {
            unsigned pa[4];
            pa[0] = h2exp2_u(f22h2(s[2 * c][0] - mn0, s[2 * c][1] - mn0));
            pa[1] = h2exp2_u(f22h2(s[2 * c][2] - mn1, s[2 * c][3] - mn1));
            pa[2] = h2exp2_u(f22h2(s[2 * c + 1][0] - mn0, s[2 * c + 1][1] - mn0));
            pa[3] = h2exp2_u(f22h2(s[2 * c + 1][2] - mn1, s[2 * c + 1][3] - mn1));

            unsigned vf[4][4];
            #pragma unroll
            for (int p = 0; p < 4; ++p)
                ldsm4t(vf[p], Vsb + (unsigned)((c * 16 + vrow) * KVP + p * 16 + vcol) * 2);

            #pragma unroll
            for (int dt = 0; dt < 8; ++dt)
                mma16816(o[dt], pa,
                         vf[dt >> 1][(dt & 1) * 2 + 0],
                         vf[dt >> 1][(dt & 1) * 2 + 1]);

            unsigned w0, w1;
            ldsm2t(w0, w1, onesAddr + (unsigned)(c * 16 * KVP) * 2);
            mma16816(lacc, pa, w0, w1);
        }
        __syncthreads();
    }

    // l lives in tig==0 lanes (column 64 of the ones tile); broadcast.
    float l0 = __shfl_sync(0xffffffffu, lacc[0], lane & ~3);
    float l1 = __shfl_sync(0xffffffffu, lacc[2], lane & ~3);
    float i0 = 1.f / l0, i1 = 1.f / l1;
    __half* y0 = y + (bT + r0g) * CDIM + h * HDIM;
    __half* y1 = y0 + 8 * CDIM;
    #pragma unroll
    for (int dt = 0; dt < 8; ++dt) {
        __half2 a, bb;
        a.x  = __float2half_rn(o[dt][0] * i0);
        a.y  = __float2half_rn(o[dt][1] * i0);
        bb.x = __float2half_rn(o[dt][2] * i1);
        bb.y = __float2half_rn(o[dt][3] * i1);
        *(__half2*)(y0 + dt * 8 + 2 * tig) = a;
        *(__half2*)(y1 + dt * 8 + 2 * tig) = bb;
    }
}

// ---------------- launch --------------------------------------------------
extern "C" void kernel_launch(void* const* d_in, const int* in_sizes, int n_in,
                              void* d_out, int out_size) {
    const float* x      = (const float*)d_in[0];
    const float* ln1_g  = (const float*)d_in[1];
    const float* ln1_b  = (const float*)d_in[2];
    const float* w_qkv  = (const float*)d_in[3];
    const float* w_o    = (const float*)d_in[4];
    const float* ln2_g  = (const float*)d_in[5];
    const float* ln2_b  = (const float*)d_in[6];
    const float* w_fc   = (const float*)d_in[7];
    const float* b_fc   = (const float*)d_in[8];
    const float* w_proj = (const float*)d_in[9];
    const float* b_proj = (const float*)d_in[10];
    float* out = (float*)d_out;

    __half *lnh, *qkvh, *atth, *hh, *wqkv_h, *wo_h, *wfc_h, *wproj_h;
    float *x1;
    cudaGetSymbolAddress((void**)&lnh,  g_lnh);
    cudaGetSymbolAddress((void**)&qkvh, g_qkvh);
    cudaGetSymbolAddress((void**)&atth, g_atth);
    cudaGetSymbolAddress((void**)&x1,   g_x1);
    cudaGetSymbolAddress((void**)&hh,   g_hh);
    cudaGetSymbolAddress((void**)&wqkv_h,  g_wqkv_h);
    cudaGetSymbolAddress((void**)&wo_h,    g_wo_h);
    cudaGetSymbolAddress((void**)&wfc_h,   g_wfc_h);
    cudaGetSymbolAddress((void**)&wproj_h, g_wproj_h);

    static int smem_set = 0;
    if (!smem_set) {
        cudaFuncSetAttribute(attn_k, cudaFuncAttributeMaxDynamicSharedMemorySize, ATT_SMEM);
        cudaFuncSetAttribute(gemm_k<2>, cudaFuncAttributeMaxDynamicSharedMemorySize, GEMM_SMEM128);
        cudaFuncSetAttribute(gemm_k<4>, cudaFuncAttributeMaxDynamicSharedMemorySize, GEMM_SMEM128);
        cudaFuncSetAttribute(gemm64_k<1>, cudaFuncAttributeMaxDynamicSharedMemorySize, GEMM_SMEM64);
        cudaFuncSetAttribute(gemm64_k<3>, cudaFuncAttributeMaxDynamicSharedMemorySize, GEMM_SMEM64);
        smem_set = 1;
    }

    roundall_k<<<(NCHUNK + 255) / 256, 256>>>(w_qkv, w_o, w_fc, w_proj,
                                              wqkv_h, wo_h, wfc_h, wproj_h);

    ln_k<<<ROWS / 8, 256>>>(x, ln1_g, ln1_b, lnh);
    gemm_k<4><<<dim3(3 * CDIM / BN, ROWS / 128), 128, GEMM_SMEM128>>>(lnh, wqkv_h, nullptr, nullptr,
                                                                      qkvh, ROWS, 3 * CDIM, CDIM);
    attn_k<<<dim3(TSEQ / 128, NB * NH), 256, ATT_SMEM>>>(qkvh, atth);
    gemm64_k<1><<<dim3(CDIM / BN, ROWS / 64), 128, GEMM_SMEM64>>>(atth, wo_h, nullptr, x,
                                                                  x1, ROWS, CDIM, CDIM);
    ln_k<<<ROWS / 8, 256>>>(x1, ln2_g, ln2_b, lnh);
    gemm_k<2><<<dim3(DFF / BN, ROWS / 128), 128, GEMM_SMEM128>>>(lnh, wfc_h, b_fc, nullptr,
                                                                 hh, ROWS, DFF, CDIM);
    gemm64_k<3><<<dim3(CDIM / BN, ROWS / 64), 128, GEMM_SMEM64>>>(hh, wproj_h, b_proj, x1,
                                                                  out, ROWS, CDIM, DFF);
}

// round 14
// speedup vs baseline: 15.7392x; 1.0031x over previous
#include <cuda_runtime.h>
#include <cuda_fp16.h>
#include <math.h>

#define TSEQ 2048
#define NB   2
#define CDIM 768
#define NH   12
#define HDIM 64
#define DFF  3072
#define ROWS (NB * TSEQ)   // 4096

// ---------------- scratch (device globals: allocation-free) ----------------
__device__ __half g_lnh [ROWS * CDIM];
__device__ __half g_qkvh[ROWS * 3 * CDIM];
__device__ __half g_atth[ROWS * CDIM];
__device__ float  g_x1  [ROWS * CDIM];
__device__ __half g_hh  [ROWS * DFF];
__device__ __half g_wqkv_h [CDIM * 3 * CDIM];
__device__ __half g_wo_h   [CDIM * CDIM];
__device__ __half g_wfc_h  [CDIM * DFF];
__device__ __half g_wproj_h[DFF * CDIM];

__device__ __forceinline__ float gelu_f(float v) {
    return 0.5f * v * (1.0f + erff(v * 0.70710678118654752f));
}

union Pack4 { __half h[4]; uint2 u; };

__device__ __forceinline__ void cp16(unsigned dst, const void* src) {
    asm volatile("cp.async.cg.shared.global [%0], [%1], 16;\n"
                 :: "r"(dst), "l"(src) : "memory");
}
__device__ __forceinline__ void cp_commit() {
    asm volatile("cp.async.commit_group;\n" ::: "memory");
}
__device__ __forceinline__ void ldsm4(unsigned* r, unsigned addr) {
    asm volatile("ldmatrix.sync.aligned.m8n8.x4.shared.b16 {%0,%1,%2,%3}, [%4];"
                 : "=r"(r[0]), "=r"(r[1]), "=r"(r[2]), "=r"(r[3]) : "r"(addr));
}
__device__ __forceinline__ void ldsm4t(unsigned* r, unsigned addr) {
    asm volatile("ldmatrix.sync.aligned.m8n8.x4.trans.shared.b16 {%0,%1,%2,%3}, [%4];"
                 : "=r"(r[0]), "=r"(r[1]), "=r"(r[2]), "=r"(r[3]) : "r"(addr));
}
__device__ __forceinline__ void ldsm2t(unsigned& r0, unsigned& r1, unsigned addr) {
    asm volatile("ldmatrix.sync.aligned.m8n8.x2.trans.shared.b16 {%0,%1}, [%2];"
                 : "=r"(r0), "=r"(r1) : "r"(addr));
}
__device__ __forceinline__ void mma16816(float* c, const unsigned* a,
                                         unsigned b0, unsigned b1) {
    asm volatile(
        "mma.sync.aligned.m16n8k16.row.col.f32.f16.f16.f32 "
        "{%0,%1,%2,%3}, {%4,%5,%6,%7}, {%8,%9}, {%0,%1,%2,%3};"
        : "+f"(c[0]), "+f"(c[1]), "+f"(c[2]), "+f"(c[3])
        : "r"(a[0]), "r"(a[1]), "r"(a[2]), "r"(a[3]), "r"(b0), "r"(b1));
}
__device__ __forceinline__ unsigned f22h2(float x, float y) {
    __half2 h = __floats2half2_rn(x, y);
    return *(unsigned*)&h;
}
__device__ __forceinline__ unsigned h2exp2_u(unsigned x) {
    unsigned r;
    asm("ex2.approx.f16x2 %0, %1;" : "=r"(r) : "r"(x));
    return r;
}

// ---------------- ALL weights fp32 -> fp16 in ONE kernel -------------------
#define N4_QKV  (CDIM * 3 * CDIM / 4)
#define N4_O    (CDIM * CDIM / 4)
#define N4_FC   (CDIM * DFF / 4)
#define N4_PROJ (DFF * CDIM / 4)
#define N4_TOT  (N4_QKV + N4_O + N4_FC + N4_PROJ)
#define NCHUNK  (N4_TOT / 4)

__global__ __launch_bounds__(256) void roundall_k(const float* __restrict__ wqkv,
                                                  const float* __restrict__ wo,
                                                  const float* __restrict__ wfc,
                                                  const float* __restrict__ wproj,
                                                  __half* __restrict__ oqkv,
                                                  __half* __restrict__ oo,
                                                  __half* __restrict__ ofc,
                                                  __half* __restrict__ oproj) {
    int base = (blockIdx.x * 256 + threadIdx.x) * 4;
    if (base >= N4_TOT) return;

    const float4* src;
    uint2* dst;
    int off;
    if (base < N4_QKV) {
        src = (const float4*)wqkv;  dst = (uint2*)oqkv;  off = base;
    } else if (base < N4_QKV + N4_O) {
        src = (const float4*)wo;    dst = (uint2*)oo;    off = base - N4_QKV;
    } else if (base < N4_QKV + N4_O + N4_FC) {
        src = (const float4*)wfc;   dst = (uint2*)ofc;   off = base - N4_QKV - N4_O;
    } else {
        src = (const float4*)wproj; dst = (uint2*)oproj; off = base - N4_QKV - N4_O - N4_FC;
    }

    float4 v0 = src[off + 0], v1 = src[off + 1],
           v2 = src[off + 2], v3 = src[off + 3];
    Pack4 p0, p1, p2, p3;
    p0.h[0] = __float2half_rn(v0.x); p0.h[1] = __float2half_rn(v0.y);
    p0.h[2] = __float2half_rn(v0.z); p0.h[3] = __float2half_rn(v0.w);
    p1.h[0] = __float2half_rn(v1.x); p1.h[1] = __float2half_rn(v1.y);
    p1.h[2] = __float2half_rn(v1.z); p1.h[3] = __float2half_rn(v1.w);
    p2.h[0] = __float2half_rn(v2.x); p2.h[1] = __float2half_rn(v2.y);
    p2.h[2] = __float2half_rn(v2.z); p2.h[3] = __float2half_rn(v2.w);
    p3.h[0] = __float2half_rn(v3.x); p3.h[1] = __float2half_rn(v3.y);
    p3.h[2] = __float2half_rn(v3.z); p3.h[3] = __float2half_rn(v3.w);
    dst[off + 0] = p0.u; dst[off + 1] = p1.u;
    dst[off + 2] = p2.u; dst[off + 3] = p3.u;
}

// ---------------- LayerNorm: one warp per row (fp32 in, fp16 out) ----------
__global__ __launch_bounds__(256) void ln_k(const float* __restrict__ xin,
                                            const float* __restrict__ g,
                                            const float* __restrict__ b,
                                            __half* __restrict__ out) {
    int row  = blockIdx.x * 8 + (threadIdx.x >> 5);
    int lane = threadIdx.x & 31;
    const float4* xr = (const float4*)(xin + (size_t)row * CDIM);

    float4 v[6];
    float s = 0.f, ss = 0.f;
    #pragma unroll
    for (int i = 0; i < 6; ++i) {
        v[i] = xr[i * 32 + lane];
        s  += v[i].x + v[i].y + v[i].z + v[i].w;
        ss += v[i].x * v[i].x + v[i].y * v[i].y
            + v[i].z * v[i].z + v[i].w * v[i].w;
    }
    #pragma unroll
    for (int off = 16; off > 0; off >>= 1) {
        s  += __shfl_xor_sync(0xffffffffu, s,  off);
        ss += __shfl_xor_sync(0xffffffffu, ss, off);
    }

    const float inv = 1.0f / (float)CDIM;
    float mu   = s * inv;
    float var  = ss * inv - mu * mu;
    float rstd = rsqrtf(var + 1e-5f);

    const float4* g4 = (const float4*)g;
    const float4* b4 = (const float4*)b;
    __half* orow = out + (size_t)row * CDIM;
    #pragma unroll
    for (int i = 0; i < 6; ++i) {
        int c4 = i * 32 + lane;
        float4 gv = g4[c4];
        float4 bv = b4[c4];
        Pack4 p;
        p.h[0] = __float2half_rn((v[i].x - mu) * rstd * gv.x + bv.x);
        p.h[1] = __float2half_rn((v[i].y - mu) * rstd * gv.y + bv.y);
        p.h[2] = __float2half_rn((v[i].z - mu) * rstd * gv.z + bv.z);
        p.h[3] = __float2half_rn((v[i].w - mu) * rstd * gv.w + bv.w);
        *(uint2*)(orow + c4 * 4) = p.u;
    }
}

// ---------------- fp16 GEMM (BM=128): 4 warps, 64x64 warp tiles, BK=32 -----
// EPI: 1 +res(f32), 2 +bias+GELU(fp16), 3 +bias+res(f32), 4 none(fp16)
#define BN 128
#define BK 32
#define AROW2 40
#define BROW2 136
#define BSZ2 (BK * BROW2 * 2)
#define NSTG 3

#define ASZ128 (128 * AROW2 * 2)
#define STG128 (ASZ128 + BSZ2)
#define GEMM_SMEM128 (NSTG * STG128)

template <int EPI>
__global__ __launch_bounds__(128, 2) void gemm_k(const __half* __restrict__ A,
                                                 const __half* __restrict__ Bm,
                                                 const float* __restrict__ bias,
                                                 const float* __restrict__ res,
                                                 void* __restrict__ Cv,
                                                 int M, int N, int K) {
    extern __shared__ char smc[];
    unsigned smem_base = (unsigned)__cvta_generic_to_shared(smc);

    int tid  = threadIdx.x;
    int lane = tid & 31;
    int wid  = tid >> 5;
    int warp_m = wid & 1;
    int warp_n = wid >> 1;
    int bm = blockIdx.y * 128;
    int bn = blockIdx.x * BN;
    int grp = lane >> 2;
    int tig = lane & 3;

    const __half* aP[4]; unsigned aO[4];
    const __half* bP[4]; unsigned bO[4];
    #pragma unroll
    for (int l = 0; l < 4; ++l) {
        int idx = l * 128 + tid;
        int ar = idx >> 2, ac = idx & 3;
        aP[l] = A + (size_t)(bm + ar) * K + ac * 8;
        aO[l] = (unsigned)(ar * AROW2 + ac * 8) * 2u;
        int br = idx >> 4, bc = idx & 15;
        bP[l] = Bm + (size_t)br * N + bn + bc * 8;
        bO[l] = (unsigned)ASZ128 + (unsigned)(br * BROW2 + bc * 8) * 2u;
    }

    auto stage = [&](int t) {
        unsigned s = smem_base + (unsigned)(t % NSTG) * STG128;
        #pragma unroll
        for (int l = 0; l < 4; ++l) {
            cp16(s + aO[l], aP[l] + (size_t)t * BK);
            cp16(s + bO[l], bP[l] + (size_t)t * BK * N);
        }
        cp_commit();
    };

    float acc[4][8][4];
    #pragma unroll
    for (int i = 0; i < 4; ++i)
        #pragma unroll
        for (int j = 0; j < 8; ++j)
            #pragma unroll
            for (int r = 0; r < 4; ++r) acc[i][j][r] = 0.f;

    int ntiles = K / BK;
    stage(0); stage(1);

    unsigned aLrow = (unsigned)(warp_m * 64 + (lane & 15));
    unsigned aLcol = (unsigned)((lane >> 4) * 8);
    unsigned bLrow = (unsigned)(lane & 15);
    unsigned bLcol = (unsigned)(warp_n * 64 + (lane >> 4) * 8);

    for (int t = 0; t < ntiles; ++t) {
        if (t + 2 < ntiles) {
            stage(t + 2);
            asm volatile("cp.async.wait_group %0;\n" :: "n"(2));
        } else if (t + 1 < ntiles) {
            asm volatile("cp.async.wait_group %0;\n" :: "n"(1));
        } else {
            asm volatile("cp.async.wait_group %0;\n" :: "n"(0));
        }
        __syncthreads();

        unsigned base = smem_base + (unsigned)(t % NSTG) * STG128;

        #pragma unroll
        for (int ks = 0; ks < 2; ++ks) {
            unsigned af[4][4], bf[4][4];
            #pragma unroll
            for (int mi = 0; mi < 4; ++mi)
                ldsm4(af[mi], base +
                      (unsigned)(((aLrow + mi * 16) * AROW2) + ks * 16 + aLcol) * 2);
            #pragma unroll
            for (int j = 0; j < 4; ++j)
                ldsm4t(bf[j], base + (unsigned)ASZ128 +
                       (unsigned)(((ks * 16 + bLrow) * BROW2) + bLcol + j * 16) * 2);

            #pragma unroll
            for (int mi = 0; mi < 4; ++mi)
                #pragma unroll
                for (int ni = 0; ni < 8; ++ni)
                    mma16816(acc[mi][ni], af[mi],
                             bf[ni >> 1][(ni & 1) * 2 + 0],
                             bf[ni >> 1][(ni & 1) * 2 + 1]);
        }
        __syncthreads();
    }

    #pragma unroll
    for (int mi = 0; mi < 4; ++mi) {
        #pragma unroll
        for (int rr = 0; rr < 2; ++rr) {
            int r = bm + warp_m * 64 + mi * 16 + grp + rr * 8;
            #pragma unroll
            for (int ni = 0; ni < 8; ++ni) {
                int c = bn + warp_n * 64 + ni * 8 + 2 * tig;
                float v0 = acc[mi][ni][rr * 2 + 0];
                float v1 = acc[mi][ni][rr * 2 + 1];
                if (EPI == 2 || EPI == 3) { v0 += bias[c]; v1 += bias[c + 1]; }
                if (EPI == 2)             { v0 = gelu_f(v0); v1 = gelu_f(v1); }
                if (EPI == 1 || EPI == 3) {
                    const float* rp = res + (size_t)r * N + c;
                    v0 += rp[0]; v1 += rp[1];
                }
                if (EPI == 2 || EPI == 4) {
                    __half2 o;
                    o.x = __float2half_rn(v0);
                    o.y = __float2half_rn(v1);
                    *(__half2*)((__half*)Cv + (size_t)r * N + c) = o;
                } else {
                    float2 o2; o2.x = v0; o2.y = v1;
                    *(float2*)((float*)Cv + (size_t)r * N + c) = o2;
                }
            }
        }
    }
}

// ---------------- fp16 GEMM (BM=64): for N=768 GEMMs (wave balance) --------
#define ASZ64 (64 * AROW2 * 2)
#define STG64 (ASZ64 + BSZ2)
#define GEMM_SMEM64 (NSTG * STG64)

template <int EPI>
__global__ __launch_bounds__(128, 4) void gemm64_k(const __half* __restrict__ A,
                                                   const __half* __restrict__ Bm,
                                                   const float* __restrict__ bias,
                                                   const float* __restrict__ res,
                                                   void* __restrict__ Cv,
                                                   int M, int N, int K) {
    extern __shared__ char smc[];
    unsigned smem_base = (unsigned)__cvta_generic_to_shared(smc);

    int tid  = threadIdx.x;
    int lane = tid & 31;
    int wid  = tid >> 5;
    int warp_m = wid & 1;
    int warp_n = wid >> 1;
    int bm = blockIdx.y * 64;
    int bn = blockIdx.x * BN;
    int grp = lane >> 2;
    int tig = lane & 3;

    const __half* aP[2]; unsigned aO[2];
    const __half* bP[4]; unsigned bO[4];
    #pragma unroll
    for (int l = 0; l < 2; ++l) {
        int idx = l * 128 + tid;
        int ar = idx >> 2, ac = idx & 3;
        aP[l] = A + (size_t)(bm + ar) * K + ac * 8;
        aO[l] = (unsigned)(ar * AROW2 + ac * 8) * 2u;
    }
    #pragma unroll
    for (int l = 0; l < 4; ++l) {
        int idx = l * 128 + tid;
        int br = idx >> 4, bc = idx & 15;
        bP[l] = Bm + (size_t)br * N + bn + bc * 8;
        bO[l] = (unsigned)ASZ64 + (unsigned)(br * BROW2 + bc * 8) * 2u;
    }

    auto stage = [&](int t) {
        unsigned s = smem_base + (unsigned)(t % NSTG) * STG64;
        #pragma unroll
        for (int l = 0; l < 2; ++l)
            cp16(s + aO[l], aP[l] + (size_t)t * BK);
        #pragma unroll
        for (int l = 0; l < 4; ++l)
            cp16(s + bO[l], bP[l] + (size_t)t * BK * N);
        cp_commit();
    };

    float acc[2][8][4];
    #pragma unroll
    for (int i = 0; i < 2; ++i)
        #pragma unroll
        for (int j = 0; j < 8; ++j)
            #pragma unroll
            for (int r = 0; r < 4; ++r) acc[i][j][r] = 0.f;

    int ntiles = K / BK;
    stage(0); stage(1);

    unsigned aLrow = (unsigned)(warp_m * 32 + (lane & 15));
    unsigned aLcol = (unsigned)((lane >> 4) * 8);
    unsigned bLrow = (unsigned)(lane & 15);
    unsigned bLcol = (unsigned)(warp_n * 64 + (lane >> 4) * 8);

    for (int t = 0; t < ntiles; ++t) {
        if (t + 2 < ntiles) {
            stage(t + 2);
            asm volatile("cp.async.wait_group %0;\n" :: "n"(2));
        } else if (t + 1 < ntiles) {
            asm volatile("cp.async.wait_group %0;\n" :: "n"(1));
        } else {
            asm volatile("cp.async.wait_group %0;\n" :: "n"(0));
        }
        __syncthreads();

        unsigned base = smem_base + (unsigned)(t % NSTG) * STG64;

        #pragma unroll
        for (int ks = 0; ks < 2; ++ks) {
            unsigned af[2][4], bf[4][4];
            #pragma unroll
            for (int mi = 0; mi < 2; ++mi)
                ldsm4(af[mi], base +
                      (unsigned)(((aLrow + mi * 16) * AROW2) + ks * 16 + aLcol) * 2);
            #pragma unroll
            for (int j = 0; j < 4; ++j)
                ldsm4t(bf[j], base + (unsigned)ASZ64 +
                       (unsigned)(((ks * 16 + bLrow) * BROW2) + bLcol + j * 16) * 2);

            #pragma unroll
            for (int mi = 0; mi < 2; ++mi)
                #pragma unroll
                for (int ni = 0; ni < 8; ++ni)
                    mma16816(acc[mi][ni], af[mi],
                             bf[ni >> 1][(ni & 1) * 2 + 0],
                             bf[ni >> 1][(ni & 1) * 2 + 1]);
        }
        __syncthreads();
    }

    #pragma unroll
    for (int mi = 0; mi < 2; ++mi) {
        #pragma unroll
        for (int rr = 0; rr < 2; ++rr) {
            int r = bm + warp_m * 32 + mi * 16 + grp + rr * 8;
            #pragma unroll
            for (int ni = 0; ni < 8; ++ni) {
                int c = bn + warp_n * 64 + ni * 8 + 2 * tig;
                float v0 = acc[mi][ni][rr * 2 + 0];
                float v1 = acc[mi][ni][rr * 2 + 1];
                if (EPI == 2 || EPI == 3) { v0 += bias[c]; v1 += bias[c + 1]; }
                if (EPI == 2)             { v0 = gelu_f(v0); v1 = gelu_f(v1); }
                if (EPI == 1 || EPI == 3) {
                    const float* rp = res + (size_t)r * N + c;
                    v0 += rp[0]; v1 += rp[1];
                }
                if (EPI == 2 || EPI == 4) {
                    __half2 o;
                    o.x = __float2half_rn(v0);
                    o.y = __float2half_rn(v1);
                    *(__half2*)((__half*)Cv + (size_t)r * N + c) = o;
                } else {
                    float2 o2; o2.x = v0; o2.y = v1;
                    *(float2*)((float*)Cv + (size_t)r * N + c) = o2;
                }
            }
        }
    }
}

// ---------------- Flash attention: fp16 TC + fp16x2 exp + ones-col l -------
// Scores in log2 domain (log2e folded into Q scale). l accumulated by an
// extra ones-column MMA into fp32 (exact sum of the fp16 p's used for PV).
#define KVP 72
#define Q_HALVES   (128 * KVP)
#define KV_STAGE_H (2 * 64 * KVP)
#define ATT_SMEM   ((Q_HALVES + 2 * KV_STAGE_H) * 2)
#define QSCALE     0.1803368801111244f   // 0.125 * log2(e)

__global__ __launch_bounds__(256, 2) void attn_k(const __half* __restrict__ qkvh,
                                                 __half* __restrict__ y) {
    extern __shared__ __half smh[];
    unsigned smem_b = (unsigned)__cvta_generic_to_shared(smh);
    unsigned kvb    = smem_b + Q_HALVES * 2;

    int bh = blockIdx.y;
    int b  = bh / NH;
    int h  = bh % NH;
    int qt = gridDim.x - 1 - blockIdx.x;
    int q0 = qt * 128;
    size_t bT = (size_t)b * TSEQ;

    int tid  = threadIdx.x;
    int lane = tid & 31;
    int wid  = tid >> 5;
    int grp  = lane >> 2;
    int tig  = lane & 3;

    // init V pad columns (64 = 1.0, 65-71 = 0) in BOTH stage buffers.
    // cp.async only writes cols 0..63, so this persists across tiles.
    if (tid < 128) {
        int sbuf = tid >> 6, r = tid & 63;
        __half* vp = smh + Q_HALVES + sbuf * KV_STAGE_H + 64 * KVP + r * KVP + 64;
        uint4 ones = {0x00003C00u, 0u, 0u, 0u};   // {1.0h, 0...0}
        *(uint4*)vp = ones;
    }

    #pragma unroll
    for (int i = 0; i < 4; ++i) {
        int c = i * 256 + tid;
        int row = c >> 3, col8 = c & 7;
        const __half* src = qkvh + (bT + q0 + row) * (3 * CDIM) + h * HDIM + col8 * 8;
        cp16(smem_b + (unsigned)(row * KVP + col8 * 8) * 2, src);
    }
    cp_commit();

    auto kvissue = [&](int t) {
        int k0 = t * 64;
        unsigned sb = kvb + (unsigned)(t & 1) * (KV_STAGE_H * 2);
        #pragma unroll
        for (int i = 0; i < 4; ++i) {
            int c = i * 256 + tid;
            int isV = c >> 9;
            int cc = c & 511;
            int row = cc >> 3, col8 = cc & 7;
            const __half* src = qkvh + (bT + k0 + row) * (3 * CDIM)
                                + (1 + isV) * CDIM + h * HDIM + col8 * 8;
            cp16(sb + (unsigned)(isV * (64 * KVP) + row * KVP + col8 * 8) * 2, src);
        }
        cp_commit();
    };

    kvissue(0);
    asm volatile("cp.async.wait_group 0;\n" ::: "memory");
    __syncthreads();

    unsigned qf[4][4];
    {
        unsigned rowb = smem_b + (unsigned)((wid * 16 + (lane & 15)) * KVP) * 2;
        #pragma unroll
        for (int ch = 0; ch < 4; ++ch) {
            ldsm4(qf[ch], rowb + (unsigned)(ch * 16 + (lane >> 4) * 8) * 2);
            __half2 sc = __floats2half2_rn(QSCALE, QSCALE);
            #pragma unroll
            for (int r = 0; r < 4; ++r) {
                __half2 v = *(__half2*)&qf[ch][r];
                v = __hmul2(v, sc);
                qf[ch][r] = *(unsigned*)&v;
            }
        }
    }

    float o[8][4];
    #pragma unroll
    for (int i = 0; i < 8; ++i)
        #pragma unroll
        for (int j = 0; j < 4; ++j) o[i][j] = 0.f;
    float lacc[4];
    lacc[0] = lacc[1] = lacc[2] = lacc[3] = 0.f;
    float m0 = -1e30f, m1 = -1e30f;

    int r0g = q0 + wid * 16 + grp;
    int ntiles = 2 * (qt + 1);

    for (int t = 0; t < ntiles; ++t) {
        if (t + 1 < ntiles) {
            kvissue(t + 1);
            asm volatile("cp.async.wait_group 1;\n" ::: "memory");
        } else {
            asm volatile("cp.async.wait_group 0;\n" ::: "memory");
        }
        __syncthreads();

        int k0 = t * 64;
        unsigned Ksb = kvb + (unsigned)(t & 1) * (KV_STAGE_H * 2);
        unsigned Vsb = Ksb + (unsigned)(64 * KVP) * 2;

        float s[8][4];
        #pragma unroll
        for (int i = 0; i < 8; ++i)
            #pragma unroll
            for (int j = 0; j < 4; ++j) s[i][j] = 0.f;

        int krow = (lane & 7) + ((lane >> 4) << 3);
        int kcol = ((lane >> 3) & 1) << 3;
        #pragma unroll
        for (int ch = 0; ch < 4; ++ch) {
            unsigned kf[4][4];
            #pragma unroll
            for (int p = 0; p < 4; ++p)
                ldsm4(kf[p], Ksb + (unsigned)((p * 16 + krow) * KVP + ch * 16 + kcol) * 2);
            #pragma unroll
            for (int nt = 0; nt < 8; ++nt)
                mma16816(s[nt], qf[ch],
                         kf[nt >> 1][(nt & 1) * 2 + 0],
                         kf[nt >> 1][(nt & 1) * 2 + 1]);
        }

        if (k0 + 63 > r0g + 8) {
            #pragma unroll
            for (int nt = 0; nt < 8; ++nt) {
                int c0 = k0 + nt * 8 + 2 * tig;
                if (c0     > r0g)     s[nt][0] = -1e30f;
                if (c0 + 1 > r0g)     s[nt][1] = -1e30f;
                if (c0     > r0g + 8) s[nt][2] = -1e30f;
                if (c0 + 1 > r0g + 8) s[nt][3] = -1e30f;
            }
        }

        // ---- online softmax (log2 domain) ----
        float mx0 = -1e30f, mx1 = -1e30f;
        #pragma unroll
        for (int nt = 0; nt < 8; ++nt) {
            mx0 = fmaxf(mx0, fmaxf(s[nt][0], s[nt][1]));
            mx1 = fmaxf(mx1, fmaxf(s[nt][2], s[nt][3]));
        }
        mx0 = fmaxf(mx0, __shfl_xor_sync(0xffffffffu, mx0, 1));
        mx0 = fmaxf(mx0, __shfl_xor_sync(0xffffffffu, mx0, 2));
        mx1 = fmaxf(mx1, __shfl_xor_sync(0xffffffffu, mx1, 1));
        mx1 = fmaxf(mx1, __shfl_xor_sync(0xffffffffu, mx1, 2));

        float mn0 = fmaxf(m0, mx0), mn1 = fmaxf(m1, mx1);
        float cr0 = exp2f(m0 - mn0), cr1 = exp2f(m1 - mn1);
        m0 = mn0; m1 = mn1;

        #pragma unroll
        for (int nt = 0; nt < 8; ++nt) {
            o[nt][0] *= cr0; o[nt][1] *= cr0;
            o[nt][2] *= cr1; o[nt][3] *= cr1;
        }
        lacc[0] *= cr0; lacc[1] *= cr0;
        lacc[2] *= cr1; lacc[3] *= cr1;

        // ---- O += P V, l += P . ones (p = 2^(s-m) in fp16) ----
        int vrow = (lane & 7) + (((lane >> 3) & 1) << 3);
        int vcol = (lane >> 4) << 3;
        unsigned onesAddr = Vsb +
            (unsigned)(((lane & 15)) * KVP + 64) * 2;   // + c*16*KVP*2 added below
        #pragma unroll
        for (int c = 0; c < 4; ++c) {
            unsigned pa[4];
            pa[0] = h2exp2_u(f22h2(s[2 * c][0] - mn0, s[2 * c][1] - mn0));
            pa[1] = h2exp2_u(f22h2(s[2 * c][2] - mn1, s[2 * c][3] - mn1));
            pa[2] = h2exp2_u(f22h2(s[2 * c + 1][0] - mn0, s[2 * c + 1][1] - mn0));
            pa[3] = h2exp2_u(f22h2(s[2 * c + 1][2] - mn1, s[2 * c + 1][3] - mn1));

            unsigned vf[4][4];
            #pragma unroll
            for (int p = 0; p < 4; ++p)
                ldsm4t(vf[p], Vsb + (unsigned)((c * 16 + vrow) * KVP + p * 16 + vcol) * 2);

            #pragma unroll
            for (int dt = 0; dt < 8; ++dt)
                mma16816(o[dt], pa,
                         vf[dt >> 1][(dt & 1) * 2 + 0],
                         vf[dt >> 1][(dt & 1) * 2 + 1]);

            unsigned w0, w1;
            ldsm2t(w0, w1, onesAddr + (unsigned)(c * 16 * KVP) * 2);
            mma16816(lacc, pa, w0, w1);
        }
        __syncthreads();
    }

    // l lives in tig==0 lanes (column 64 of the ones tile); broadcast.
    float l0 = __shfl_sync(0xffffffffu, lacc[0], lane & ~3);
    float l1 = __shfl_sync(0xffffffffu, lacc[2], lane & ~3);
    float i0 = 1.f / l0, i1 = 1.f / l1;
    __half* y0 = y + (bT + r0g) * CDIM + h * HDIM;
    __half* y1 = y0 + 8 * CDIM;
    #pragma unroll
    for (int dt = 0; dt < 8; ++dt) {
        __half2 a, bb;
        a.x  = __float2half_rn(o[dt][0] * i0);
        a.y  = __float2half_rn(o[dt][1] * i0);
        bb.x = __float2half_rn(o[dt][2] * i1);
        bb.y = __float2half_rn(o[dt][3] * i1);
        *(__half2*)(y0 + dt * 8 + 2 * tig) = a;
        *(__half2*)(y1 + dt * 8 + 2 * tig) = bb;
    }
}

// ---------------- launch --------------------------------------------------
extern "C" void kernel_launch(void* const* d_in, const int* in_sizes, int n_in,
                              void* d_out, int out_size) {
    const float* x      = (const float*)d_in[0];
    const float* ln1_g  = (const float*)d_in[1];
    const float* ln1_b  = (const float*)d_in[2];
    const float* w_qkv  = (const float*)d_in[3];
    const float* w_o    = (const float*)d_in[4];
    const float* ln2_g  = (const float*)d_in[5];
    const float* ln2_b  = (const float*)d_in[6];
    const float* w_fc   = (const float*)d_in[7];
    const float* b_fc   = (const float*)d_in[8];
    const float* w_proj = (const float*)d_in[9];
    const float* b_proj = (const float*)d_in[10];
    float* out = (float*)d_out;

    __half *lnh, *qkvh, *atth, *hh, *wqkv_h, *wo_h, *wfc_h, *wproj_h;
    float *x1;
    cudaGetSymbolAddress((void**)&lnh,  g_lnh);
    cudaGetSymbolAddress((void**)&qkvh, g_qkvh);
    cudaGetSymbolAddress((void**)&atth, g_atth);
    cudaGetSymbolAddress((void**)&x1,   g_x1);
    cudaGetSymbolAddress((void**)&hh,   g_hh);
    cudaGetSymbolAddress((void**)&wqkv_h,  g_wqkv_h);
    cudaGetSymbolAddress((void**)&wo_h,    g_wo_h);
    cudaGetSymbolAddress((void**)&wfc_h,   g_wfc_h);
    cudaGetSymbolAddress((void**)&wproj_h, g_wproj_h);

    static int smem_set = 0;
    if (!smem_set) {
        cudaFuncSetAttribute(attn_k, cudaFuncAttributeMaxDynamicSharedMemorySize, ATT_SMEM);
        cudaFuncSetAttribute(gemm_k<2>, cudaFuncAttributeMaxDynamicSharedMemorySize, GEMM_SMEM128);
        cudaFuncSetAttribute(gemm_k<4>, cudaFuncAttributeMaxDynamicSharedMemorySize, GEMM_SMEM128);
        cudaFuncSetAttribute(gemm64_k<1>, cudaFuncAttributeMaxDynamicSharedMemorySize, GEMM_SMEM64);
        cudaFuncSetAttribute(gemm64_k<3>, cudaFuncAttributeMaxDynamicSharedMemorySize, GEMM_SMEM64);
        smem_set = 1;
    }

    roundall_k<<<(NCHUNK + 255) / 256, 256>>>(w_qkv, w_o, w_fc, w_proj,
                                              wqkv_h, wo_h, wfc_h, wproj_h);

    ln_k<<<ROWS / 8, 256>>>(x, ln1_g, ln1_b, lnh);
    gemm_k<4><<<dim3(3 * CDIM / BN, ROWS / 128), 128, GEMM_SMEM128>>>(lnh, wqkv_h, nullptr, nullptr,
                                                                      qkvh, ROWS, 3 * CDIM, CDIM);
    attn_k<<<dim3(TSEQ / 128, NB * NH), 256, ATT_SMEM>>>(qkvh, atth);
    gemm64_k<1><<<dim3(CDIM / BN, ROWS / 64), 128, GEMM_SMEM64>>>(atth, wo_h, nullptr, x,
                                                                  x1, ROWS, CDIM, CDIM);
    ln_k<<<ROWS / 8, 256>>>(x1, ln2_g, ln2_b, lnh);
    gemm_k<2><<<dim3(DFF / BN, ROWS / 128), 128, GEMM_SMEM128>>>(lnh, wfc_h, b_fc, nullptr,
                                                                 hh, ROWS, DFF, CDIM);
    gemm64_k<3><<<dim3(CDIM / BN, ROWS / 64), 128, GEMM_SMEM64>>>(hh, wproj_h, b_proj, x1,
                                                                  out, ROWS, CDIM, DFF);
}

// round 15
// speedup vs baseline: 15.8460x; 1.0068x over previous
#include <cuda_runtime.h>
#include <cuda_fp16.h>
#include <math.h>

#define TSEQ 2048
#define NB   2
#define CDIM 768
#define NH   12
#define HDIM 64
#define DFF  3072
#define ROWS (NB * TSEQ)   // 4096

// ---------------- scratch (device globals: allocation-free) ----------------
__device__ __half g_lnh [ROWS * CDIM];
__device__ __half g_qkvh[ROWS * 3 * CDIM];
__device__ __half g_atth[ROWS * CDIM];
__device__ float  g_x1  [ROWS * CDIM];
__device__ __half g_hh  [ROWS * DFF];
__device__ __half g_wqkv_h [CDIM * 3 * CDIM];
__device__ __half g_wo_h   [CDIM * CDIM];
__device__ __half g_wfc_h  [CDIM * DFF];
__device__ __half g_wproj_h[DFF * CDIM];

__device__ __forceinline__ float gelu_f(float v) {
    return 0.5f * v * (1.0f + erff(v * 0.70710678118654752f));
}

union Pack4 { __half h[4]; uint2 u; };

__device__ __forceinline__ void cp16(unsigned dst, const void* src) {
    asm volatile("cp.async.cg.shared.global [%0], [%1], 16;\n"
                 :: "r"(dst), "l"(src) : "memory");
}
__device__ __forceinline__ void cp_commit() {
    asm volatile("cp.async.commit_group;\n" ::: "memory");
}
__device__ __forceinline__ void ldsm4(unsigned* r, unsigned addr) {
    asm volatile("ldmatrix.sync.aligned.m8n8.x4.shared.b16 {%0,%1,%2,%3}, [%4];"
                 : "=r"(r[0]), "=r"(r[1]), "=r"(r[2]), "=r"(r[3]) : "r"(addr));
}
__device__ __forceinline__ void ldsm4t(unsigned* r, unsigned addr) {
    asm volatile("ldmatrix.sync.aligned.m8n8.x4.trans.shared.b16 {%0,%1,%2,%3}, [%4];"
                 : "=r"(r[0]), "=r"(r[1]), "=r"(r[2]), "=r"(r[3]) : "r"(addr));
}
__device__ __forceinline__ void ldsm2t(unsigned& r0, unsigned& r1, unsigned addr) {
    asm volatile("ldmatrix.sync.aligned.m8n8.x2.trans.shared.b16 {%0,%1}, [%2];"
                 : "=r"(r0), "=r"(r1) : "r"(addr));
}
__device__ __forceinline__ void mma16816(float* c, const unsigned* a,
                                         unsigned b0, unsigned b1) {
    asm volatile(
        "mma.sync.aligned.m16n8k16.row.col.f32.f16.f16.f32 "
        "{%0,%1,%2,%3}, {%4,%5,%6,%7}, {%8,%9}, {%0,%1,%2,%3};"
        : "+f"(c[0]), "+f"(c[1]), "+f"(c[2]), "+f"(c[3])
        : "r"(a[0]), "r"(a[1]), "r"(a[2]), "r"(a[3]), "r"(b0), "r"(b1));
}
__device__ __forceinline__ unsigned f22h2(float x, float y) {
    __half2 h = __floats2half2_rn(x, y);
    return *(unsigned*)&h;
}
__device__ __forceinline__ unsigned h2exp2_u(unsigned x) {
    unsigned r;
    asm("ex2.approx.f16x2 %0, %1;" : "=r"(r) : "r"(x));
    return r;
}

// ---------------- ALL weights fp32 -> fp16 in ONE kernel -------------------
#define N4_QKV  (CDIM * 3 * CDIM / 4)
#define N4_O    (CDIM * CDIM / 4)
#define N4_FC   (CDIM * DFF / 4)
#define N4_PROJ (DFF * CDIM / 4)
#define N4_TOT  (N4_QKV + N4_O + N4_FC + N4_PROJ)
#define NCHUNK  (N4_TOT / 4)

__global__ __launch_bounds__(256) void roundall_k(const float* __restrict__ wqkv,
                                                  const float* __restrict__ wo,
                                                  const float* __restrict__ wfc,
                                                  const float* __restrict__ wproj,
                                                  __half* __restrict__ oqkv,
                                                  __half* __restrict__ oo,
                                                  __half* __restrict__ ofc,
                                                  __half* __restrict__ oproj) {
    int base = (blockIdx.x * 256 + threadIdx.x) * 4;
    if (base >= N4_TOT) return;

    const float4* src;
    uint2* dst;
    int off;
    if (base < N4_QKV) {
        src = (const float4*)wqkv;  dst = (uint2*)oqkv;  off = base;
    } else if (base < N4_QKV + N4_O) {
        src = (const float4*)wo;    dst = (uint2*)oo;    off = base - N4_QKV;
    } else if (base < N4_QKV + N4_O + N4_FC) {
        src = (const float4*)wfc;   dst = (uint2*)ofc;   off = base - N4_QKV - N4_O;
    } else {
        src = (const float4*)wproj; dst = (uint2*)oproj; off = base - N4_QKV - N4_O - N4_FC;
    }

    float4 v0 = src[off + 0], v1 = src[off + 1],
           v2 = src[off + 2], v3 = src[off + 3];
    Pack4 p0, p1, p2, p3;
    p0.h[0] = __float2half_rn(v0.x); p0.h[1] = __float2half_rn(v0.y);
    p0.h[2] = __float2half_rn(v0.z); p0.h[3] = __float2half_rn(v0.w);
    p1.h[0] = __float2half_rn(v1.x); p1.h[1] = __float2half_rn(v1.y);
    p1.h[2] = __float2half_rn(v1.z); p1.h[3] = __float2half_rn(v1.w);
    p2.h[0] = __float2half_rn(v2.x); p2.h[1] = __float2half_rn(v2.y);
    p2.h[2] = __float2half_rn(v2.z); p2.h[3] = __float2half_rn(v2.w);
    p3.h[0] = __float2half_rn(v3.x); p3.h[1] = __float2half_rn(v3.y);
    p3.h[2] = __float2half_rn(v3.z); p3.h[3] = __float2half_rn(v3.w);
    dst[off + 0] = p0.u; dst[off + 1] = p1.u;
    dst[off + 2] = p2.u; dst[off + 3] = p3.u;
}

// ---------------- LayerNorm: one warp per row (fp32 in, fp16 out) ----------
__global__ __launch_bounds__(256) void ln_k(const float* __restrict__ xin,
                                            const float* __restrict__ g,
                                            const float* __restrict__ b,
                                            __half* __restrict__ out) {
    int row  = blockIdx.x * 8 + (threadIdx.x >> 5);
    int lane = threadIdx.x & 31;
    const float4* xr = (const float4*)(xin + (size_t)row * CDIM);

    float4 v[6];
    float s = 0.f, ss = 0.f;
    #pragma unroll
    for (int i = 0; i < 6; ++i) {
        v[i] = xr[i * 32 + lane];
        s  += v[i].x + v[i].y + v[i].z + v[i].w;
        ss += v[i].x * v[i].x + v[i].y * v[i].y
            + v[i].z * v[i].z + v[i].w * v[i].w;
    }
    #pragma unroll
    for (int off = 16; off > 0; off >>= 1) {
        s  += __shfl_xor_sync(0xffffffffu, s,  off);
        ss += __shfl_xor_sync(0xffffffffu, ss, off);
    }

    const float inv = 1.0f / (float)CDIM;
    float mu   = s * inv;
    float var  = ss * inv - mu * mu;
    float rstd = rsqrtf(var + 1e-5f);

    const float4* g4 = (const float4*)g;
    const float4* b4 = (const float4*)b;
    __half* orow = out + (size_t)row * CDIM;
    #pragma unroll
    for (int i = 0; i < 6; ++i) {
        int c4 = i * 32 + lane;
        float4 gv = g4[c4];
        float4 bv = b4[c4];
        Pack4 p;
        p.h[0] = __float2half_rn((v[i].x - mu) * rstd * gv.x + bv.x);
        p.h[1] = __float2half_rn((v[i].y - mu) * rstd * gv.y + bv.y);
        p.h[2] = __float2half_rn((v[i].z - mu) * rstd * gv.z + bv.z);
        p.h[3] = __float2half_rn((v[i].w - mu) * rstd * gv.w + bv.w);
        *(uint2*)(orow + c4 * 4) = p.u;
    }
}

// ---------------- fp16 GEMM (BM=128): single-sync 3-stage pipeline ---------
// EPI: 1 +res(f32), 2 +bias+GELU(fp16), 3 +bias+res(f32), 4 none(fp16)
#define BN 128
#define BK 32
#define AROW2 40
#define BROW2 136
#define BSZ2 (BK * BROW2 * 2)
#define NSTG 3

#define ASZ128 (128 * AROW2 * 2)
#define STG128 (ASZ128 + BSZ2)
#define GEMM_SMEM128 (NSTG * STG128)

template <int EPI>
__global__ __launch_bounds__(128, 2) void gemm_k(const __half* __restrict__ A,
                                                 const __half* __restrict__ Bm,
                                                 const float* __restrict__ bias,
                                                 const float* __restrict__ res,
                                                 void* __restrict__ Cv,
                                                 int M, int N, int K) {
    extern __shared__ char smc[];
    unsigned smem_base = (unsigned)__cvta_generic_to_shared(smc);

    int tid  = threadIdx.x;
    int lane = tid & 31;
    int wid  = tid >> 5;
    int warp_m = wid & 1;
    int warp_n = wid >> 1;
    int bm = blockIdx.y * 128;
    int bn = blockIdx.x * BN;
    int grp = lane >> 2;
    int tig = lane & 3;

    const __half* aP[4]; unsigned aO[4];
    const __half* bP[4]; unsigned bO[4];
    #pragma unroll
    for (int l = 0; l < 4; ++l) {
        int idx = l * 128 + tid;
        int ar = idx >> 2, ac = idx & 3;
        aP[l] = A + (size_t)(bm + ar) * K + ac * 8;
        aO[l] = (unsigned)(ar * AROW2 + ac * 8) * 2u;
        int br = idx >> 4, bc = idx & 15;
        bP[l] = Bm + (size_t)br * N + bn + bc * 8;
        bO[l] = (unsigned)ASZ128 + (unsigned)(br * BROW2 + bc * 8) * 2u;
    }

    auto stage = [&](int t) {
        unsigned s = smem_base + (unsigned)(t % NSTG) * STG128;
        #pragma unroll
        for (int l = 0; l < 4; ++l) {
            cp16(s + aO[l], aP[l] + (size_t)t * BK);
            cp16(s + bO[l], bP[l] + (size_t)t * BK * N);
        }
        cp_commit();
    };

    float acc[4][8][4];
    #pragma unroll
    for (int i = 0; i < 4; ++i)
        #pragma unroll
        for (int j = 0; j < 8; ++j)
            #pragma unroll
            for (int r = 0; r < 4; ++r) acc[i][j][r] = 0.f;

    int ntiles = K / BK;
    stage(0); stage(1);

    unsigned aLrow = (unsigned)(warp_m * 64 + (lane & 15));
    unsigned aLcol = (unsigned)((lane >> 4) * 8);
    unsigned bLrow = (unsigned)(lane & 15);
    unsigned bLcol = (unsigned)(warp_n * 64 + (lane >> 4) * 8);

    for (int t = 0; t < ntiles; ++t) {
        if (t + 1 < ntiles) {
            asm volatile("cp.async.wait_group %0;\n" :: "n"(1));
        } else {
            asm volatile("cp.async.wait_group %0;\n" :: "n"(0));
        }
        __syncthreads();                 // single barrier per tile
        if (t + 2 < ntiles) stage(t + 2); // safe: writes (t+2)%3, last read at t-1

        unsigned base = smem_base + (unsigned)(t % NSTG) * STG128;

        #pragma unroll
        for (int ks = 0; ks < 2; ++ks) {
            unsigned af[4][4], bf[4][4];
            #pragma unroll
            for (int mi = 0; mi < 4; ++mi)
                ldsm4(af[mi], base +
                      (unsigned)(((aLrow + mi * 16) * AROW2) + ks * 16 + aLcol) * 2);
            #pragma unroll
            for (int j = 0; j < 4; ++j)
                ldsm4t(bf[j], base + (unsigned)ASZ128 +
                       (unsigned)(((ks * 16 + bLrow) * BROW2) + bLcol + j * 16) * 2);

            #pragma unroll
            for (int mi = 0; mi < 4; ++mi)
                #pragma unroll
                for (int ni = 0; ni < 8; ++ni)
                    mma16816(acc[mi][ni], af[mi],
                             bf[ni >> 1][(ni & 1) * 2 + 0],
                             bf[ni >> 1][(ni & 1) * 2 + 1]);
        }
    }

    #pragma unroll
    for (int mi = 0; mi < 4; ++mi) {
        #pragma unroll
        for (int rr = 0; rr < 2; ++rr) {
            int r = bm + warp_m * 64 + mi * 16 + grp + rr * 8;
            #pragma unroll
            for (int ni = 0; ni < 8; ++ni) {
                int c = bn + warp_n * 64 + ni * 8 + 2 * tig;
                float v0 = acc[mi][ni][rr * 2 + 0];
                float v1 = acc[mi][ni][rr * 2 + 1];
                if (EPI == 2 || EPI == 3) { v0 += bias[c]; v1 += bias[c + 1]; }
                if (EPI == 2)             { v0 = gelu_f(v0); v1 = gelu_f(v1); }
                if (EPI == 1 || EPI == 3) {
                    const float* rp = res + (size_t)r * N + c;
                    v0 += rp[0]; v1 += rp[1];
                }
                if (EPI == 2 || EPI == 4) {
                    __half2 o;
                    o.x = __float2half_rn(v0);
                    o.y = __float2half_rn(v1);
                    *(__half2*)((__half*)Cv + (size_t)r * N + c) = o;
                } else {
                    float2 o2; o2.x = v0; o2.y = v1;
                    *(float2*)((float*)Cv + (size_t)r * N + c) = o2;
                }
            }
        }
    }
}

// ---------------- fp16 GEMM (BM=64): single-sync 3-stage -------------------
#define ASZ64 (64 * AROW2 * 2)
#define STG64 (ASZ64 + BSZ2)
#define GEMM_SMEM64 (NSTG * STG64)

template <int EPI>
__global__ __launch_bounds__(128, 4) void gemm64_k(const __half* __restrict__ A,
                                                   const __half* __restrict__ Bm,
                                                   const float* __restrict__ bias,
                                                   const float* __restrict__ res,
                                                   void* __restrict__ Cv,
                                                   int M, int N, int K) {
    extern __shared__ char smc[];
    unsigned smem_base = (unsigned)__cvta_generic_to_shared(smc);

    int tid  = threadIdx.x;
    int lane = tid & 31;
    int wid  = tid >> 5;
    int warp_m = wid & 1;
    int warp_n = wid >> 1;
    int bm = blockIdx.y * 64;
    int bn = blockIdx.x * BN;
    int grp = lane >> 2;
    int tig = lane & 3;

    const __half* aP[2]; unsigned aO[2];
    const __half* bP[4]; unsigned bO[4];
    #pragma unroll
    for (int l = 0; l < 2; ++l) {
        int idx = l * 128 + tid;
        int ar = idx >> 2, ac = idx & 3;
        aP[l] = A + (size_t)(bm + ar) * K + ac * 8;
        aO[l] = (unsigned)(ar * AROW2 + ac * 8) * 2u;
    }
    #pragma unroll
    for (int l = 0; l < 4; ++l) {
        int idx = l * 128 + tid;
        int br = idx >> 4, bc = idx & 15;
        bP[l] = Bm + (size_t)br * N + bn + bc * 8;
        bO[l] = (unsigned)ASZ64 + (unsigned)(br * BROW2 + bc * 8) * 2u;
    }

    auto stage = [&](int t) {
        unsigned s = smem_base + (unsigned)(t % NSTG) * STG64;
        #pragma unroll
        for (int l = 0; l < 2; ++l)
            cp16(s + aO[l], aP[l] + (size_t)t * BK);
        #pragma unroll
        for (int l = 0; l < 4; ++l)
            cp16(s + bO[l], bP[l] + (size_t)t * BK * N);
        cp_commit();
    };

    float acc[2][8][4];
    #pragma unroll
    for (int i = 0; i < 2; ++i)
        #pragma unroll
        for (int j = 0; j < 8; ++j)
            #pragma unroll
            for (int r = 0; r < 4; ++r) acc[i][j][r] = 0.f;

    int ntiles = K / BK;
    stage(0); stage(1);

    unsigned aLrow = (unsigned)(warp_m * 32 + (lane & 15));
    unsigned aLcol = (unsigned)((lane >> 4) * 8);
    unsigned bLrow = (unsigned)(lane & 15);
    unsigned bLcol = (unsigned)(warp_n * 64 + (lane >> 4) * 8);

    for (int t = 0; t < ntiles; ++t) {
        if (t + 1 < ntiles) {
            asm volatile("cp.async.wait_group %0;\n" :: "n"(1));
        } else {
            asm volatile("cp.async.wait_group %0;\n" :: "n"(0));
        }
        __syncthreads();
        if (t + 2 < ntiles) stage(t + 2);

        unsigned base = smem_base + (unsigned)(t % NSTG) * STG64;

        #pragma unroll
        for (int ks = 0; ks < 2; ++ks) {
            unsigned af[2][4], bf[4][4];
            #pragma unroll
            for (int mi = 0; mi < 2; ++mi)
                ldsm4(af[mi], base +
                      (unsigned)(((aLrow + mi * 16) * AROW2) + ks * 16 + aLcol) * 2);
            #pragma unroll
            for (int j = 0; j < 4; ++j)
                ldsm4t(bf[j], base + (unsigned)ASZ64 +
                       (unsigned)(((ks * 16 + bLrow) * BROW2) + bLcol + j * 16) * 2);

            #pragma unroll
            for (int mi = 0; mi < 2; ++mi)
                #pragma unroll
                for (int ni = 0; ni < 8; ++ni)
                    mma16816(acc[mi][ni], af[mi],
                             bf[ni >> 1][(ni & 1) * 2 + 0],
                             bf[ni >> 1][(ni & 1) * 2 + 1]);
        }
    }

    #pragma unroll
    for (int mi = 0; mi < 2; ++mi) {
        #pragma unroll
        for (int rr = 0; rr < 2; ++rr) {
            int r = bm + warp_m * 32 + mi * 16 + grp + rr * 8;
            #pragma unroll
            for (int ni = 0; ni < 8; ++ni) {
                int c = bn + warp_n * 64 + ni * 8 + 2 * tig;
                float v0 = acc[mi][ni][rr * 2 + 0];
                float v1 = acc[mi][ni][rr * 2 + 1];
                if (EPI == 2 || EPI == 3) { v0 += bias[c]; v1 += bias[c + 1]; }
                if (EPI == 2)             { v0 = gelu_f(v0); v1 = gelu_f(v1); }
                if (EPI == 1 || EPI == 3) {
                    const float* rp = res + (size_t)r * N + c;
                    v0 += rp[0]; v1 += rp[1];
                }
                if (EPI == 2 || EPI == 4) {
                    __half2 o;
                    o.x = __float2half_rn(v0);
                    o.y = __float2half_rn(v1);
                    *(__half2*)((__half*)Cv + (size_t)r * N + c) = o;
                } else {
                    float2 o2; o2.x = v0; o2.y = v1;
                    *(float2*)((float*)Cv + (size_t)r * N + c) = o2;
                }
            }
        }
    }
}

// ---------------- Flash attention: 3-stage KV, single sync per tile --------
#define KVP 72
#define Q_HALVES   (128 * KVP)
#define KV_STAGE_H (2 * 64 * KVP)
#define KVSTG 3
#define ATT_SMEM   ((Q_HALVES + KVSTG * KV_STAGE_H) * 2)   // 73728 B
#define QSCALE     0.1803368801111244f   // 0.125 * log2(e)

__global__ __launch_bounds__(256, 2) void attn_k(const __half* __restrict__ qkvh,
                                                 __half* __restrict__ y) {
    extern __shared__ __half smh[];
    unsigned smem_b = (unsigned)__cvta_generic_to_shared(smh);
    unsigned kvb    = smem_b + Q_HALVES * 2;

    int bh = blockIdx.y;
    int b  = bh / NH;
    int h  = bh % NH;
    int qt = gridDim.x - 1 - blockIdx.x;
    int q0 = qt * 128;
    size_t bT = (size_t)b * TSEQ;

    int tid  = threadIdx.x;
    int lane = tid & 31;
    int wid  = tid >> 5;
    int grp  = lane >> 2;
    int tig  = lane & 3;

    // init V pad columns (64 = 1.0, 65-71 = 0) in ALL 3 stage buffers.
    if (tid < 192) {
        int sbuf = tid >> 6, r = tid & 63;
        __half* vp = smh + Q_HALVES + sbuf * KV_STAGE_H + 64 * KVP + r * KVP + 64;
        uint4 ones = {0x00003C00u, 0u, 0u, 0u};
        *(uint4*)vp = ones;
    }

    #pragma unroll
    for (int i = 0; i < 4; ++i) {
        int c = i * 256 + tid;
        int row = c >> 3, col8 = c & 7;
        const __half* src = qkvh + (bT + q0 + row) * (3 * CDIM) + h * HDIM + col8 * 8;
        cp16(smem_b + (unsigned)(row * KVP + col8 * 8) * 2, src);
    }
    cp_commit();

    auto kvissue = [&](int t) {
        int k0 = t * 64;
        unsigned sb = kvb + (unsigned)(t % KVSTG) * (KV_STAGE_H * 2);
        #pragma unroll
        for (int i = 0; i < 4; ++i) {
            int c = i * 256 + tid;
            int isV = c >> 9;
            int cc = c & 511;
            int row = cc >> 3, col8 = cc & 7;
            const __half* src = qkvh + (bT + k0 + row) * (3 * CDIM)
                                + (1 + isV) * CDIM + h * HDIM + col8 * 8;
            cp16(sb + (unsigned)(isV * (64 * KVP) + row * KVP + col8 * 8) * 2, src);
        }
        cp_commit();
    };

    int ntiles = 2 * (qt + 1);
    kvissue(0);
    asm volatile("cp.async.wait_group 0;\n" ::: "memory");
    __syncthreads();   // Q + kv0 ready; ones-cols visible

    unsigned qf[4][4];
    {
        unsigned rowb = smem_b + (unsigned)((wid * 16 + (lane & 15)) * KVP) * 2;
        #pragma unroll
        for (int ch = 0; ch < 4; ++ch) {
            ldsm4(qf[ch], rowb + (unsigned)(ch * 16 + (lane >> 4) * 8) * 2);
            __half2 sc = __floats2half2_rn(QSCALE, QSCALE);
            #pragma unroll
            for (int r = 0; r < 4; ++r) {
                __half2 v = *(__half2*)&qf[ch][r];
                v = __hmul2(v, sc);
                qf[ch][r] = *(unsigned*)&v;
            }
        }
    }
    if (1 < ntiles) kvissue(1);

    float o[8][4];
    #pragma unroll
    for (int i = 0; i < 8; ++i)
        #pragma unroll
        for (int j = 0; j < 4; ++j) o[i][j] = 0.f;
    float lacc[4];
    lacc[0] = lacc[1] = lacc[2] = lacc[3] = 0.f;
    float m0 = -1e30f, m1 = -1e30f;

    int r0g = q0 + wid * 16 + grp;

    for (int t = 0; t < ntiles; ++t) {
        if (t + 1 < ntiles) {
            asm volatile("cp.async.wait_group 1;\n" ::: "memory");
        } else {
            asm volatile("cp.async.wait_group 0;\n" ::: "memory");
        }
        __syncthreads();                       // single barrier per tile
        if (t + 2 < ntiles) kvissue(t + 2);    // writes (t+2)%3; last read at t-1

        int k0 = t * 64;
        unsigned Ksb = kvb + (unsigned)(t % KVSTG) * (KV_STAGE_H * 2);
        unsigned Vsb = Ksb + (unsigned)(64 * KVP) * 2;

        float s[8][4];
        #pragma unroll
        for (int i = 0; i < 8; ++i)
            #pragma unroll
            for (int j = 0; j < 4; ++j) s[i][j] = 0.f;

        int krow = (lane & 7) + ((lane >> 4) << 3);
        int kcol = ((lane >> 3) & 1) << 3;
        #pragma unroll
        for (int ch = 0; ch < 4; ++ch) {
            unsigned kf[4][4];
            #pragma unroll
            for (int p = 0; p < 4; ++p)
                ldsm4(kf[p], Ksb + (unsigned)((p * 16 + krow) * KVP + ch * 16 + kcol) * 2);
            #pragma unroll
            for (int nt = 0; nt < 8; ++nt)
                mma16816(s[nt], qf[ch],
                         kf[nt >> 1][(nt & 1) * 2 + 0],
                         kf[nt >> 1][(nt & 1) * 2 + 1]);
        }

        if (k0 + 63 > r0g + 8) {
            #pragma unroll
            for (int nt = 0; nt < 8; ++nt) {
                int c0 = k0 + nt * 8 + 2 * tig;
                if (c0     > r0g)     s[nt][0] = -1e30f;
                if (c0 + 1 > r0g)     s[nt][1] = -1e30f;
                if (c0     > r0g + 8) s[nt][2] = -1e30f;
                if (c0 + 1 > r0g + 8) s[nt][3] = -1e30f;
            }
        }

        float mx0 = -1e30f, mx1 = -1e30f;
        #pragma unroll
        for (int nt = 0; nt < 8; ++nt) {
            mx0 = fmaxf(mx0, fmaxf(s[nt][0], s[nt][1]));
            mx1 = fmaxf(mx1, fmaxf(s[nt][2], s[nt][3]));
        }
        mx0 = fmaxf(mx0, __shfl_xor_sync(0xffffffffu, mx0, 1));
        mx0 = fmaxf(mx0, __shfl_xor_sync(0xffffffffu, mx0, 2));
        mx1 = fmaxf(mx1, __shfl_xor_sync(0xffffffffu, mx1, 1));
        mx1 = fmaxf(mx1, __shfl_xor_sync(0xffffffffu, mx1, 2));

        float mn0 = fmaxf(m0, mx0), mn1 = fmaxf(m1, mx1);
        float cr0 = exp2f(m0 - mn0), cr1 = exp2f(m1 - mn1);
        m0 = mn0; m1 = mn1;

        #pragma unroll
        for (int nt = 0; nt < 8; ++nt) {
            o[nt][0] *= cr0; o[nt][1] *= cr0;
            o[nt][2] *= cr1; o[nt][3] *= cr1;
        }
        lacc[0] *= cr0; lacc[1] *= cr0;
        lacc[2] *= cr1; lacc[3] *= cr1;

        int vrow = (lane & 7) + (((lane >> 3) & 1) << 3);
        int vcol = (lane >> 4) << 3;
        unsigned onesAddr = Vsb + (unsigned)(((lane & 15)) * KVP + 64) * 2;
        #pragma unroll
        for (int c = 0; c < 4; ++c) {
            unsigned pa[4];
            pa[0] = h2exp2_u(f22h2(s[2 * c][0] - mn0, s[2 * c][1] - mn0));
            pa[1] = h2exp2_u(f22h2(s[2 * c][2] - mn1, s[2 * c][3] - mn1));
            pa[2] = h2exp2_u(f22h2(s[2 * c + 1][0] - mn0, s[2 * c + 1][1] - mn0));
            pa[3] = h2exp2_u(f22h2(s[2 * c + 1][2] - mn1, s[2 * c + 1][3] - mn1));

            unsigned vf[4][4];
            #pragma unroll
            for (int p = 0; p < 4; ++p)
                ldsm4t(vf[p], Vsb + (unsigned)((c * 16 + vrow) * KVP + p * 16 + vcol) * 2);

            #pragma unroll
            for (int dt = 0; dt < 8; ++dt)
                mma16816(o[dt], pa,
                         vf[dt >> 1][(dt & 1) * 2 + 0],
                         vf[dt >> 1][(dt & 1) * 2 + 1]);

            unsigned w0, w1;
            ldsm2t(w0, w1, onesAddr + (unsigned)(c * 16 * KVP) * 2);
            mma16816(lacc, pa, w0, w1);
        }
    }

    float l0 = __shfl_sync(0xffffffffu, lacc[0], lane & ~3);
    float l1 = __shfl_sync(0xffffffffu, lacc[2], lane & ~3);
    float i0 = 1.f / l0, i1 = 1.f / l1;
    __half* y0 = y + (bT + r0g) * CDIM + h * HDIM;
    __half* y1 = y0 + 8 * CDIM;
    #pragma unroll
    for (int dt = 0; dt < 8; ++dt) {
        __half2 a, bb;
        a.x  = __float2half_rn(o[dt][0] * i0);
        a.y  = __float2half_rn(o[dt][1] * i0);
        bb.x = __float2half_rn(o[dt][2] * i1);
        bb.y = __float2half_rn(o[dt][3] * i1);
        *(__half2*)(y0 + dt * 8 + 2 * tig) = a;
        *(__half2*)(y1 + dt * 8 + 2 * tig) = bb;
    }
}

// ---------------- launch --------------------------------------------------
extern "C" void kernel_launch(void* const* d_in, const int* in_sizes, int n_in,
                              void* d_out, int out_size) {
    const float* x      = (const float*)d_in[0];
    const float* ln1_g  = (const float*)d_in[1];
    const float* ln1_b  = (const float*)d_in[2];
    const float* w_qkv  = (const float*)d_in[3];
    const float* w_o    = (const float*)d_in[4];
    const float* ln2_g  = (const float*)d_in[5];
    const float* ln2_b  = (const float*)d_in[6];
    const float* w_fc   = (const float*)d_in[7];
    const float* b_fc   = (const float*)d_in[8];
    const float* w_proj = (const float*)d_in[9];
    const float* b_proj = (const float*)d_in[10];
    float* out = (float*)d_out;

    __half *lnh, *qkvh, *atth, *hh, *wqkv_h, *wo_h, *wfc_h, *wproj_h;
    float *x1;
    cudaGetSymbolAddress((void**)&lnh,  g_lnh);
    cudaGetSymbolAddress((void**)&qkvh, g_qkvh);
    cudaGetSymbolAddress((void**)&atth, g_atth);
    cudaGetSymbolAddress((void**)&x1,   g_x1);
    cudaGetSymbolAddress((void**)&hh,   g_hh);
    cudaGetSymbolAddress((void**)&wqkv_h,  g_wqkv_h);
    cudaGetSymbolAddress((void**)&wo_h,    g_wo_h);
    cudaGetSymbolAddress((void**)&wfc_h,   g_wfc_h);
    cudaGetSymbolAddress((void**)&wproj_h, g_wproj_h);

    static int smem_set = 0;
    if (!smem_set) {
        cudaFuncSetAttribute(attn_k, cudaFuncAttributeMaxDynamicSharedMemorySize, ATT_SMEM);
        cudaFuncSetAttribute(gemm_k<2>, cudaFuncAttributeMaxDynamicSharedMemorySize, GEMM_SMEM128);
        cudaFuncSetAttribute(gemm_k<4>, cudaFuncAttributeMaxDynamicSharedMemorySize, GEMM_SMEM128);
        cudaFuncSetAttribute(gemm64_k<1>, cudaFuncAttributeMaxDynamicSharedMemorySize, GEMM_SMEM64);
        cudaFuncSetAttribute(gemm64_k<3>, cudaFuncAttributeMaxDynamicSharedMemorySize, GEMM_SMEM64);
        smem_set = 1;
    }

    roundall_k<<<(NCHUNK + 255) / 256, 256>>>(w_qkv, w_o, w_fc, w_proj,
                                              wqkv_h, wo_h, wfc_h, wproj_h);

    ln_k<<<ROWS / 8, 256>>>(x, ln1_g, ln1_b, lnh);
    gemm_k<4><<<dim3(3 * CDIM / BN, ROWS / 128), 128, GEMM_SMEM128>>>(lnh, wqkv_h, nullptr, nullptr,
                                                                      qkvh, ROWS, 3 * CDIM, CDIM);
    attn_k<<<dim3(TSEQ / 128, NB * NH), 256, ATT_SMEM>>>(qkvh, atth);
    gemm64_k<1><<<dim3(CDIM / BN, ROWS / 64), 128, GEMM_SMEM64>>>(atth, wo_h, nullptr, x,
                                                                  x1, ROWS, CDIM, CDIM);
    ln_k<<<ROWS / 8, 256>>>(x1, ln2_g, ln2_b, lnh);
    gemm_k<2><<<dim3(DFF / BN, ROWS / 128), 128, GEMM_SMEM128>>>(lnh, wfc_h, b_fc, nullptr,
                                                                 hh, ROWS, DFF, CDIM);
    gemm64_k<3><<<dim3(CDIM / BN, ROWS / 64), 128, GEMM_SMEM64>>>(hh, wproj_h, b_proj, x1,
                                                                  out, ROWS, CDIM, DFF);
}

// round 16
// speedup vs baseline: 15.9085x; 1.0039x over previous
#include <cuda_runtime.h>
#include <cuda_fp16.h>
#include <math.h>

#define TSEQ 2048
#define NB   2
#define CDIM 768
#define NH   12
#define HDIM 64
#define DFF  3072
#define ROWS (NB * TSEQ)   // 4096

// ---------------- scratch (device globals: allocation-free) ----------------
__device__ __half g_lnh [ROWS * CDIM];
__device__ __half g_qkvh[ROWS * 3 * CDIM];
__device__ __half g_atth[ROWS * CDIM];
__device__ float  g_x1  [ROWS * CDIM];
__device__ __half g_hh  [ROWS * DFF];
__device__ __half g_wqkv_h [CDIM * 3 * CDIM];
__device__ __half g_wo_h   [CDIM * CDIM];
__device__ __half g_wfc_h  [CDIM * DFF];
__device__ __half g_wproj_h[DFF * CDIM];

__device__ __forceinline__ float gelu_f(float v) {
    return 0.5f * v * (1.0f + erff(v * 0.70710678118654752f));
}

union Pack4 { __half h[4]; uint2 u; };

__device__ __forceinline__ void cp16(unsigned dst, const void* src) {
    asm volatile("cp.async.cg.shared.global [%0], [%1], 16;\n"
                 :: "r"(dst), "l"(src) : "memory");
}
__device__ __forceinline__ void cp_commit() {
    asm volatile("cp.async.commit_group;\n" ::: "memory");
}
__device__ __forceinline__ void ldsm4(unsigned* r, unsigned addr) {
    asm volatile("ldmatrix.sync.aligned.m8n8.x4.shared.b16 {%0,%1,%2,%3}, [%4];"
                 : "=r"(r[0]), "=r"(r[1]), "=r"(r[2]), "=r"(r[3]) : "r"(addr));
}
__device__ __forceinline__ void ldsm4t(unsigned* r, unsigned addr) {
    asm volatile("ldmatrix.sync.aligned.m8n8.x4.trans.shared.b16 {%0,%1,%2,%3}, [%4];"
                 : "=r"(r[0]), "=r"(r[1]), "=r"(r[2]), "=r"(r[3]) : "r"(addr));
}
__device__ __forceinline__ void ldsm2t(unsigned& r0, unsigned& r1, unsigned addr) {
    asm volatile("ldmatrix.sync.aligned.m8n8.x2.trans.shared.b16 {%0,%1}, [%2];"
                 : "=r"(r0), "=r"(r1) : "r"(addr));
}
__device__ __forceinline__ void mma16816(float* c, const unsigned* a,
                                         unsigned b0, unsigned b1) {
    asm volatile(
        "mma.sync.aligned.m16n8k16.row.col.f32.f16.f16.f32 "
        "{%0,%1,%2,%3}, {%4,%5,%6,%7}, {%8,%9}, {%0,%1,%2,%3};"
        : "+f"(c[0]), "+f"(c[1]), "+f"(c[2]), "+f"(c[3])
        : "r"(a[0]), "r"(a[1]), "r"(a[2]), "r"(a[3]), "r"(b0), "r"(b1));
}
__device__ __forceinline__ unsigned f22h2(float x, float y) {
    __half2 h = __floats2half2_rn(x, y);
    return *(unsigned*)&h;
}
__device__ __forceinline__ unsigned h2exp2_u(unsigned x) {
    unsigned r;
    asm("ex2.approx.f16x2 %0, %1;" : "=r"(r) : "r"(x));
    return r;
}

// ---------------- ALL weights fp32 -> fp16 in ONE kernel -------------------
#define N4_QKV  (CDIM * 3 * CDIM / 4)
#define N4_O    (CDIM * CDIM / 4)
#define N4_FC   (CDIM * DFF / 4)
#define N4_PROJ (DFF * CDIM / 4)
#define N4_TOT  (N4_QKV + N4_O + N4_FC + N4_PROJ)
#define NCHUNK  (N4_TOT / 4)

__global__ __launch_bounds__(256) void roundall_k(const float* __restrict__ wqkv,
                                                  const float* __restrict__ wo,
                                                  const float* __restrict__ wfc,
                                                  const float* __restrict__ wproj,
                                                  __half* __restrict__ oqkv,
                                                  __half* __restrict__ oo,
                                                  __half* __restrict__ ofc,
                                                  __half* __restrict__ oproj) {
    int base = (blockIdx.x * 256 + threadIdx.x) * 4;
    if (base >= N4_TOT) return;

    const float4* src;
    uint2* dst;
    int off;
    if (base < N4_QKV) {
        src = (const float4*)wqkv;  dst = (uint2*)oqkv;  off = base;
    } else if (base < N4_QKV + N4_O) {
        src = (const float4*)wo;    dst = (uint2*)oo;    off = base - N4_QKV;
    } else if (base < N4_QKV + N4_O + N4_FC) {
        src = (const float4*)wfc;   dst = (uint2*)ofc;   off = base - N4_QKV - N4_O;
    } else {
        src = (const float4*)wproj; dst = (uint2*)oproj; off = base - N4_QKV - N4_O - N4_FC;
    }

    float4 v0 = src[off + 0], v1 = src[off + 1],
           v2 = src[off + 2], v3 = src[off + 3];
    Pack4 p0, p1, p2, p3;
    p0.h[0] = __float2half_rn(v0.x); p0.h[1] = __float2half_rn(v0.y);
    p0.h[2] = __float2half_rn(v0.z); p0.h[3] = __float2half_rn(v0.w);
    p1.h[0] = __float2half_rn(v1.x); p1.h[1] = __float2half_rn(v1.y);
    p1.h[2] = __float2half_rn(v1.z); p1.h[3] = __float2half_rn(v1.w);
    p2.h[0] = __float2half_rn(v2.x); p2.h[1] = __float2half_rn(v2.y);
    p2.h[2] = __float2half_rn(v2.z); p2.h[3] = __float2half_rn(v2.w);
    p3.h[0] = __float2half_rn(v3.x); p3.h[1] = __float2half_rn(v3.y);
    p3.h[2] = __float2half_rn(v3.z); p3.h[3] = __float2half_rn(v3.w);
    dst[off + 0] = p0.u; dst[off + 1] = p1.u;
    dst[off + 2] = p2.u; dst[off + 3] = p3.u;
}

// ---------------- LayerNorm: one warp per row (fp32 in, fp16 out) ----------
__global__ __launch_bounds__(256) void ln_k(const float* __restrict__ xin,
                                            const float* __restrict__ g,
                                            const float* __restrict__ b,
                                            __half* __restrict__ out) {
    int row  = blockIdx.x * 8 + (threadIdx.x >> 5);
    int lane = threadIdx.x & 31;
    const float4* xr = (const float4*)(xin + (size_t)row * CDIM);

    float4 v[6];
    float s = 0.f, ss = 0.f;
    #pragma unroll
    for (int i = 0; i < 6; ++i) {
        v[i] = xr[i * 32 + lane];
        s  += v[i].x + v[i].y + v[i].z + v[i].w;
        ss += v[i].x * v[i].x + v[i].y * v[i].y
            + v[i].z * v[i].z + v[i].w * v[i].w;
    }
    #pragma unroll
    for (int off = 16; off > 0; off >>= 1) {
        s  += __shfl_xor_sync(0xffffffffu, s,  off);
        ss += __shfl_xor_sync(0xffffffffu, ss, off);
    }

    const float inv = 1.0f / (float)CDIM;
    float mu   = s * inv;
    float var  = ss * inv - mu * mu;
    float rstd = rsqrtf(var + 1e-5f);

    const float4* g4 = (const float4*)g;
    const float4* b4 = (const float4*)b;
    __half* orow = out + (size_t)row * CDIM;
    #pragma unroll
    for (int i = 0; i < 6; ++i) {
        int c4 = i * 32 + lane;
        float4 gv = g4[c4];
        float4 bv = b4[c4];
        Pack4 p;
        p.h[0] = __float2half_rn((v[i].x - mu) * rstd * gv.x + bv.x);
        p.h[1] = __float2half_rn((v[i].y - mu) * rstd * gv.y + bv.y);
        p.h[2] = __float2half_rn((v[i].z - mu) * rstd * gv.z + bv.z);
        p.h[3] = __float2half_rn((v[i].w - mu) * rstd * gv.w + bv.w);
        *(uint2*)(orow + c4 * 4) = p.u;
    }
}

// ---------------- fp16 GEMM (BM=128): single-sync 3-stage pipeline ---------
// EPI: 1 +res(f32), 2 +bias+GELU(fp16), 3 +bias+res(f32), 4 none(fp16)
#define BN 128
#define BK 32
#define AROW2 40
#define BROW2 136
#define BSZ2 (BK * BROW2 * 2)
#define NSTG 3

#define ASZ128 (128 * AROW2 * 2)
#define STG128 (ASZ128 + BSZ2)
#define GEMM_SMEM128 (NSTG * STG128)

template <int EPI>
__global__ __launch_bounds__(128, 2) void gemm_k(const __half* __restrict__ A,
                                                 const __half* __restrict__ Bm,
                                                 const float* __restrict__ bias,
                                                 const float* __restrict__ res,
                                                 void* __restrict__ Cv,
                                                 int M, int N, int K) {
    extern __shared__ char smc[];
    unsigned smem_base = (unsigned)__cvta_generic_to_shared(smc);

    int tid  = threadIdx.x;
    int lane = tid & 31;
    int wid  = tid >> 5;
    int warp_m = wid & 1;
    int warp_n = wid >> 1;
    int bm = blockIdx.y * 128;
    int bn = blockIdx.x * BN;
    int grp = lane >> 2;
    int tig = lane & 3;

    const __half* aP[4]; unsigned aO[4];
    const __half* bP[4]; unsigned bO[4];
    #pragma unroll
    for (int l = 0; l < 4; ++l) {
        int idx = l * 128 + tid;
        int ar = idx >> 2, ac = idx & 3;
        aP[l] = A + (size_t)(bm + ar) * K + ac * 8;
        aO[l] = (unsigned)(ar * AROW2 + ac * 8) * 2u;
        int br = idx >> 4, bc = idx & 15;
        bP[l] = Bm + (size_t)br * N + bn + bc * 8;
        bO[l] = (unsigned)ASZ128 + (unsigned)(br * BROW2 + bc * 8) * 2u;
    }

    auto stage = [&](int t) {
        unsigned s = smem_base + (unsigned)(t % NSTG) * STG128;
        #pragma unroll
        for (int l = 0; l < 4; ++l) {
            cp16(s + aO[l], aP[l] + (size_t)t * BK);
            cp16(s + bO[l], bP[l] + (size_t)t * BK * N);
        }
        cp_commit();
    };

    float acc[4][8][4];
    #pragma unroll
    for (int i = 0; i < 4; ++i)
        #pragma unroll
        for (int j = 0; j < 8; ++j)
            #pragma unroll
            for (int r = 0; r < 4; ++r) acc[i][j][r] = 0.f;

    int ntiles = K / BK;
    stage(0); stage(1);

    unsigned aLrow = (unsigned)(warp_m * 64 + (lane & 15));
    unsigned aLcol = (unsigned)((lane >> 4) * 8);
    unsigned bLrow = (unsigned)(lane & 15);
    unsigned bLcol = (unsigned)(warp_n * 64 + (lane >> 4) * 8);

    for (int t = 0; t < ntiles; ++t) {
        if (t + 1 < ntiles) {
            asm volatile("cp.async.wait_group %0;\n" :: "n"(1));
        } else {
            asm volatile("cp.async.wait_group %0;\n" :: "n"(0));
        }
        __syncthreads();
        if (t + 2 < ntiles) stage(t + 2);

        unsigned base = smem_base + (unsigned)(t % NSTG) * STG128;

        #pragma unroll
        for (int ks = 0; ks < 2; ++ks) {
            unsigned af[4][4], bf[4][4];
            #pragma unroll
            for (int mi = 0; mi < 4; ++mi)
                ldsm4(af[mi], base +
                      (unsigned)(((aLrow + mi * 16) * AROW2) + ks * 16 + aLcol) * 2);
            #pragma unroll
            for (int j = 0; j < 4; ++j)
                ldsm4t(bf[j], base + (unsigned)ASZ128 +
                       (unsigned)(((ks * 16 + bLrow) * BROW2) + bLcol + j * 16) * 2);

            #pragma unroll
            for (int mi = 0; mi < 4; ++mi)
                #pragma unroll
                for (int ni = 0; ni < 8; ++ni)
                    mma16816(acc[mi][ni], af[mi],
                             bf[ni >> 1][(ni & 1) * 2 + 0],
                             bf[ni >> 1][(ni & 1) * 2 + 1]);
        }
    }

    #pragma unroll
    for (int mi = 0; mi < 4; ++mi) {
        #pragma unroll
        for (int rr = 0; rr < 2; ++rr) {
            int r = bm + warp_m * 64 + mi * 16 + grp + rr * 8;
            #pragma unroll
            for (int ni = 0; ni < 8; ++ni) {
                int c = bn + warp_n * 64 + ni * 8 + 2 * tig;
                float v0 = acc[mi][ni][rr * 2 + 0];
                float v1 = acc[mi][ni][rr * 2 + 1];
                if (EPI == 2 || EPI == 3) { v0 += bias[c]; v1 += bias[c + 1]; }
                if (EPI == 2)             { v0 = gelu_f(v0); v1 = gelu_f(v1); }
                if (EPI == 1 || EPI == 3) {
                    const float* rp = res + (size_t)r * N + c;
                    v0 += rp[0]; v1 += rp[1];
                }
                if (EPI == 2 || EPI == 4) {
                    __half2 o;
                    o.x = __float2half_rn(v0);
                    o.y = __float2half_rn(v1);
                    *(__half2*)((__half*)Cv + (size_t)r * N + c) = o;
                } else {
                    float2 o2; o2.x = v0; o2.y = v1;
                    *(float2*)((float*)Cv + (size_t)r * N + c) = o2;
                }
            }
        }
    }
}

// ---------------- fp16 GEMM (BM=64): single-sync 3-stage -------------------
#define ASZ64 (64 * AROW2 * 2)
#define STG64 (ASZ64 + BSZ2)
#define GEMM_SMEM64 (NSTG * STG64)

template <int EPI>
__global__ __launch_bounds__(128, 4) void gemm64_k(const __half* __restrict__ A,
                                                   const __half* __restrict__ Bm,
                                                   const float* __restrict__ bias,
                                                   const float* __restrict__ res,
                                                   void* __restrict__ Cv,
                                                   int M, int N, int K) {
    extern __shared__ char smc[];
    unsigned smem_base = (unsigned)__cvta_generic_to_shared(smc);

    int tid  = threadIdx.x;
    int lane = tid & 31;
    int wid  = tid >> 5;
    int warp_m = wid & 1;
    int warp_n = wid >> 1;
    int bm = blockIdx.y * 64;
    int bn = blockIdx.x * BN;
    int grp = lane >> 2;
    int tig = lane & 3;

    const __half* aP[2]; unsigned aO[2];
    const __half* bP[4]; unsigned bO[4];
    #pragma unroll
    for (int l = 0; l < 2; ++l) {
        int idx = l * 128 + tid;
        int ar = idx >> 2, ac = idx & 3;
        aP[l] = A + (size_t)(bm + ar) * K + ac * 8;
        aO[l] = (unsigned)(ar * AROW2 + ac * 8) * 2u;
    }
    #pragma unroll
    for (int l = 0; l < 4; ++l) {
        int idx = l * 128 + tid;
        int br = idx >> 4, bc = idx & 15;
        bP[l] = Bm + (size_t)br * N + bn + bc * 8;
        bO[l] = (unsigned)ASZ64 + (unsigned)(br * BROW2 + bc * 8) * 2u;
    }

    auto stage = [&](int t) {
        unsigned s = smem_base + (unsigned)(t % NSTG) * STG64;
        #pragma unroll
        for (int l = 0; l < 2; ++l)
            cp16(s + aO[l], aP[l] + (size_t)t * BK);
        #pragma unroll
        for (int l = 0; l < 4; ++l)
            cp16(s + bO[l], bP[l] + (size_t)t * BK * N);
        cp_commit();
    };

    float acc[2][8][4];
    #pragma unroll
    for (int i = 0; i < 2; ++i)
        #pragma unroll
        for (int j = 0; j < 8; ++j)
            #pragma unroll
            for (int r = 0; r < 4; ++r) acc[i][j][r] = 0.f;

    int ntiles = K / BK;
    stage(0); stage(1);

    unsigned aLrow = (unsigned)(warp_m * 32 + (lane & 15));
    unsigned aLcol = (unsigned)((lane >> 4) * 8);
    unsigned bLrow = (unsigned)(lane & 15);
    unsigned bLcol = (unsigned)(warp_n * 64 + (lane >> 4) * 8);

    for (int t = 0; t < ntiles; ++t) {
        if (t + 1 < ntiles) {
            asm volatile("cp.async.wait_group %0;\n" :: "n"(1));
        } else {
            asm volatile("cp.async.wait_group %0;\n" :: "n"(0));
        }
        __syncthreads();
        if (t + 2 < ntiles) stage(t + 2);

        unsigned base = smem_base + (unsigned)(t % NSTG) * STG64;

        #pragma unroll
        for (int ks = 0; ks < 2; ++ks) {
            unsigned af[2][4], bf[4][4];
            #pragma unroll
            for (int mi = 0; mi < 2; ++mi)
                ldsm4(af[mi], base +
                      (unsigned)(((aLrow + mi * 16) * AROW2) + ks * 16 + aLcol) * 2);
            #pragma unroll
            for (int j = 0; j < 4; ++j)
                ldsm4t(bf[j], base + (unsigned)ASZ64 +
                       (unsigned)(((ks * 16 + bLrow) * BROW2) + bLcol + j * 16) * 2);

            #pragma unroll
            for (int mi = 0; mi < 2; ++mi)
                #pragma unroll
                for (int ni = 0; ni < 8; ++ni)
                    mma16816(acc[mi][ni], af[mi],
                             bf[ni >> 1][(ni & 1) * 2 + 0],
                             bf[ni >> 1][(ni & 1) * 2 + 1]);
        }
    }

    #pragma unroll
    for (int mi = 0; mi < 2; ++mi) {
        #pragma unroll
        for (int rr = 0; rr < 2; ++rr) {
            int r = bm + warp_m * 32 + mi * 16 + grp + rr * 8;
            #pragma unroll
            for (int ni = 0; ni < 8; ++ni) {
                int c = bn + warp_n * 64 + ni * 8 + 2 * tig;
                float v0 = acc[mi][ni][rr * 2 + 0];
                float v1 = acc[mi][ni][rr * 2 + 1];
                if (EPI == 2 || EPI == 3) { v0 += bias[c]; v1 += bias[c + 1]; }
                if (EPI == 2)             { v0 = gelu_f(v0); v1 = gelu_f(v1); }
                if (EPI == 1 || EPI == 3) {
                    const float* rp = res + (size_t)r * N + c;
                    v0 += rp[0]; v1 += rp[1];
                }
                if (EPI == 2 || EPI == 4) {
                    __half2 o;
                    o.x = __float2half_rn(v0);
                    o.y = __float2half_rn(v1);
                    *(__half2*)((__half*)Cv + (size_t)r * N + c) = o;
                } else {
                    float2 o2; o2.x = v0; o2.y = v1;
                    *(float2*)((float*)Cv + (size_t)r * N + c) = o2;
                }
            }
        }
    }
}

// ---------------- Flash attention: 3-stage KV, single sync, dead-tile skip -
#define KVP 72
#define Q_HALVES   (128 * KVP)
#define KV_STAGE_H (2 * 64 * KVP)
#define KVSTG 3
#define ATT_SMEM   ((Q_HALVES + KVSTG * KV_STAGE_H) * 2)   // 73728 B
#define QSCALE     0.1803368801111244f   // 0.125 * log2(e)

__global__ __launch_bounds__(256, 2) void attn_k(const __half* __restrict__ qkvh,
                                                 __half* __restrict__ y) {
    extern __shared__ __half smh[];
    unsigned smem_b = (unsigned)__cvta_generic_to_shared(smh);
    unsigned kvb    = smem_b + Q_HALVES * 2;

    int bh = blockIdx.y;
    int b  = bh / NH;
    int h  = bh % NH;
    int qt = gridDim.x - 1 - blockIdx.x;
    int q0 = qt * 128;
    size_t bT = (size_t)b * TSEQ;

    int tid  = threadIdx.x;
    int lane = tid & 31;
    int wid  = tid >> 5;
    int grp  = lane >> 2;
    int tig  = lane & 3;

    // init V pad columns (64 = 1.0, 65-71 = 0) in ALL 3 stage buffers.
    if (tid < 192) {
        int sbuf = tid >> 6, r = tid & 63;
        __half* vp = smh + Q_HALVES + sbuf * KV_STAGE_H + 64 * KVP + r * KVP + 64;
        uint4 ones = {0x00003C00u, 0u, 0u, 0u};
        *(uint4*)vp = ones;
    }

    #pragma unroll
    for (int i = 0; i < 4; ++i) {
        int c = i * 256 + tid;
        int row = c >> 3, col8 = c & 7;
        const __half* src = qkvh + (bT + q0 + row) * (3 * CDIM) + h * HDIM + col8 * 8;
        cp16(smem_b + (unsigned)(row * KVP + col8 * 8) * 2, src);
    }
    cp_commit();

    auto kvissue = [&](int t) {
        int k0 = t * 64;
        unsigned sb = kvb + (unsigned)(t % KVSTG) * (KV_STAGE_H * 2);
        #pragma unroll
        for (int i = 0; i < 4; ++i) {
            int c = i * 256 + tid;
            int isV = c >> 9;
            int cc = c & 511;
            int row = cc >> 3, col8 = cc & 7;
            const __half* src = qkvh + (bT + k0 + row) * (3 * CDIM)
                                + (1 + isV) * CDIM + h * HDIM + col8 * 8;
            cp16(sb + (unsigned)(isV * (64 * KVP) + row * KVP + col8 * 8) * 2, src);
        }
        cp_commit();
    };

    int ntiles = 2 * (qt + 1);
    kvissue(0);
    asm volatile("cp.async.wait_group 0;\n" ::: "memory");
    __syncthreads();   // Q + kv0 ready; ones-cols visible

    unsigned qf[4][4];
    {
        unsigned rowb = smem_b + (unsigned)((wid * 16 + (lane & 15)) * KVP) * 2;
        #pragma unroll
        for (int ch = 0; ch < 4; ++ch) {
            ldsm4(qf[ch], rowb + (unsigned)(ch * 16 + (lane >> 4) * 8) * 2);
            __half2 sc = __floats2half2_rn(QSCALE, QSCALE);
            #pragma unroll
            for (int r = 0; r < 4; ++r) {
                __half2 v = *(__half2*)&qf[ch][r];
                v = __hmul2(v, sc);
                qf[ch][r] = *(unsigned*)&v;
            }
        }
    }
    // constant ones-fragment for the l-MMA (same for every c and every tile)
    unsigned w0c, w1c;
    ldsm2t(w0c, w1c, kvb + (unsigned)(64 * KVP) * 2
                        + (unsigned)(((lane & 15)) * KVP + 64) * 2);

    if (1 < ntiles) kvissue(1);

    float o[8][4];
    #pragma unroll
    for (int i = 0; i < 8; ++i)
        #pragma unroll
        for (int j = 0; j < 4; ++j) o[i][j] = 0.f;
    float lacc[4];
    lacc[0] = lacc[1] = lacc[2] = lacc[3] = 0.f;
    float m0 = -1e30f, m1 = -1e30f;

    int r0g = q0 + wid * 16 + grp;
    int wmaxrow = q0 + wid * 16 + 15;   // highest q row this warp owns

    for (int t = 0; t < ntiles; ++t) {
        if (t + 1 < ntiles) {
            asm volatile("cp.async.wait_group 1;\n" ::: "memory");
        } else {
            asm volatile("cp.async.wait_group 0;\n" ::: "memory");
        }
        __syncthreads();                       // single barrier per tile
        if (t + 2 < ntiles) kvissue(t + 2);

        int k0 = t * 64;
        if (k0 > wmaxrow) continue;            // tile fully masked for this warp
                                               // (p==0, corr==1: bit-identical skip)

        unsigned Ksb = kvb + (unsigned)(t % KVSTG) * (KV_STAGE_H * 2);
        unsigned Vsb = Ksb + (unsigned)(64 * KVP) * 2;

        float s[8][4];
        #pragma unroll
        for (int i = 0; i < 8; ++i)
            #pragma unroll
            for (int j = 0; j < 4; ++j) s[i][j] = 0.f;

        int krow = (lane & 7) + ((lane >> 4) << 3);
        int kcol = ((lane >> 3) & 1) << 3;
        #pragma unroll
        for (int ch = 0; ch < 4; ++ch) {
            unsigned kf[4][4];
            #pragma unroll
            for (int p = 0; p < 4; ++p)
                ldsm4(kf[p], Ksb + (unsigned)((p * 16 + krow) * KVP + ch * 16 + kcol) * 2);
            #pragma unroll
            for (int nt = 0; nt < 8; ++nt)
                mma16816(s[nt], qf[ch],
                         kf[nt >> 1][(nt & 1) * 2 + 0],
                         kf[nt >> 1][(nt & 1) * 2 + 1]);
        }

        if (k0 + 63 > r0g + 8) {
            #pragma unroll
            for (int nt = 0; nt < 8; ++nt) {
                int c0 = k0 + nt * 8 + 2 * tig;
                if (c0     > r0g)     s[nt][0] = -1e30f;
                if (c0 + 1 > r0g)     s[nt][1] = -1e30f;
                if (c0     > r0g + 8) s[nt][2] = -1e30f;
                if (c0 + 1 > r0g + 8) s[nt][3] = -1e30f;
            }
        }

        float mx0 = -1e30f, mx1 = -1e30f;
        #pragma unroll
        for (int nt = 0; nt < 8; ++nt) {
            mx0 = fmaxf(mx0, fmaxf(s[nt][0], s[nt][1]));
            mx1 = fmaxf(mx1, fmaxf(s[nt][2], s[nt][3]));
        }
        mx0 = fmaxf(mx0, __shfl_xor_sync(0xffffffffu, mx0, 1));
        mx0 = fmaxf(mx0, __shfl_xor_sync(0xffffffffu, mx0, 2));
        mx1 = fmaxf(mx1, __shfl_xor_sync(0xffffffffu, mx1, 1));
        mx1 = fmaxf(mx1, __shfl_xor_sync(0xffffffffu, mx1, 2));

        float mn0 = fmaxf(m0, mx0), mn1 = fmaxf(m1, mx1);

        // skip rescale when corr==1 for all lanes (exact identity)
        if (!__all_sync(0xffffffffu, (mn0 == m0) && (mn1 == m1))) {
            float cr0 = exp2f(m0 - mn0), cr1 = exp2f(m1 - mn1);
            #pragma unroll
            for (int nt = 0; nt < 8; ++nt) {
                o[nt][0] *= cr0; o[nt][1] *= cr0;
                o[nt][2] *= cr1; o[nt][3] *= cr1;
            }
            lacc[0] *= cr0; lacc[1] *= cr0;
            lacc[2] *= cr1; lacc[3] *= cr1;
        }
        m0 = mn0; m1 = mn1;

        int vrow = (lane & 7) + (((lane >> 3) & 1) << 3);
        int vcol = (lane >> 4) << 3;
        #pragma unroll
        for (int c = 0; c < 4; ++c) {
            unsigned pa[4];
            pa[0] = h2exp2_u(f22h2(s[2 * c][0] - mn0, s[2 * c][1] - mn0));
            pa[1] = h2exp2_u(f22h2(s[2 * c][2] - mn1, s[2 * c][3] - mn1));
            pa[2] = h2exp2_u(f22h2(s[2 * c + 1][0] - mn0, s[2 * c + 1][1] - mn0));
            pa[3] = h2exp2_u(f22h2(s[2 * c + 1][2] - mn1, s[2 * c + 1][3] - mn1));

            unsigned vf[4][4];
            #pragma unroll
            for (int p = 0; p < 4; ++p)
                ldsm4t(vf[p], Vsb + (unsigned)((c * 16 + vrow) * KVP + p * 16 + vcol) * 2);

            #pragma unroll
            for (int dt = 0; dt < 8; ++dt)
                mma16816(o[dt], pa,
                         vf[dt >> 1][(dt & 1) * 2 + 0],
                         vf[dt >> 1][(dt & 1) * 2 + 1]);

            mma16816(lacc, pa, w0c, w1c);
        }
    }

    float l0 = __shfl_sync(0xffffffffu, lacc[0], lane & ~3);
    float l1 = __shfl_sync(0xffffffffu, lacc[2], lane & ~3);
    float i0 = 1.f / l0, i1 = 1.f / l1;
    __half* y0 = y + (bT + r0g) * CDIM + h * HDIM;
    __half* y1 = y0 + 8 * CDIM;
    #pragma unroll
    for (int dt = 0; dt < 8; ++dt) {
        __half2 a, bb;
        a.x  = __float2half_rn(o[dt][0] * i0);
        a.y  = __float2half_rn(o[dt][1] * i0);
        bb.x = __float2half_rn(o[dt][2] * i1);
        bb.y = __float2half_rn(o[dt][3] * i1);
        *(__half2*)(y0 + dt * 8 + 2 * tig) = a;
        *(__half2*)(y1 + dt * 8 + 2 * tig) = bb;
    }
}

// ---------------- launch --------------------------------------------------
extern "C" void kernel_launch(void* const* d_in, const int* in_sizes, int n_in,
                              void* d_out, int out_size) {
    const float* x      = (const float*)d_in[0];
    const float* ln1_g  = (const float*)d_in[1];
    const float* ln1_b  = (const float*)d_in[2];
    const float* w_qkv  = (const float*)d_in[3];
    const float* w_o    = (const float*)d_in[4];
    const float* ln2_g  = (const float*)d_in[5];
    const float* ln2_b  = (const float*)d_in[6];
    const float* w_fc   = (const float*)d_in[7];
    const float* b_fc   = (const float*)d_in[8];
    const float* w_proj = (const float*)d_in[9];
    const float* b_proj = (const float*)d_in[10];
    float* out = (float*)d_out;

    __half *lnh, *qkvh, *atth, *hh, *wqkv_h, *wo_h, *wfc_h, *wproj_h;
    float *x1;
    cudaGetSymbolAddress((void**)&lnh,  g_lnh);
    cudaGetSymbolAddress((void**)&qkvh, g_qkvh);
    cudaGetSymbolAddress((void**)&atth, g_atth);
    cudaGetSymbolAddress((void**)&x1,   g_x1);
    cudaGetSymbolAddress((void**)&hh,   g_hh);
    cudaGetSymbolAddress((void**)&wqkv_h,  g_wqkv_h);
    cudaGetSymbolAddress((void**)&wo_h,    g_wo_h);
    cudaGetSymbolAddress((void**)&wfc_h,   g_wfc_h);
    cudaGetSymbolAddress((void**)&wproj_h, g_wproj_h);

    static int smem_set = 0;
    if (!smem_set) {
        cudaFuncSetAttribute(attn_k, cudaFuncAttributeMaxDynamicSharedMemorySize, ATT_SMEM);
        cudaFuncSetAttribute(gemm_k<2>, cudaFuncAttributeMaxDynamicSharedMemorySize, GEMM_SMEM128);
        cudaFuncSetAttribute(gemm_k<4>, cudaFuncAttributeMaxDynamicSharedMemorySize, GEMM_SMEM128);
        cudaFuncSetAttribute(gemm64_k<1>, cudaFuncAttributeMaxDynamicSharedMemorySize, GEMM_SMEM64);
        cudaFuncSetAttribute(gemm64_k<3>, cudaFuncAttributeMaxDynamicSharedMemorySize, GEMM_SMEM64);
        smem_set = 1;
    }

    roundall_k<<<(NCHUNK + 255) / 256, 256>>>(w_qkv, w_o, w_fc, w_proj,
                                              wqkv_h, wo_h, wfc_h, wproj_h);

    ln_k<<<ROWS / 8, 256>>>(x, ln1_g, ln1_b, lnh);
    gemm_k<4><<<dim3(3 * CDIM / BN, ROWS / 128), 128, GEMM_SMEM128>>>(lnh, wqkv_h, nullptr, nullptr,
                                                                      qkvh, ROWS, 3 * CDIM, CDIM);
    attn_k<<<dim3(TSEQ / 128, NB * NH), 256, ATT_SMEM>>>(qkvh, atth);
    gemm64_k<1><<<dim3(CDIM / BN, ROWS / 64), 128, GEMM_SMEM64>>>(atth, wo_h, nullptr, x,
                                                                  x1, ROWS, CDIM, CDIM);
    ln_k<<<ROWS / 8, 256>>>(x1, ln2_g, ln2_b, lnh);
    gemm_k<2><<<dim3(DFF / BN, ROWS / 128), 128, GEMM_SMEM128>>>(lnh, wfc_h, b_fc, nullptr,
                                                                 hh, ROWS, DFF, CDIM);
    gemm64_k<3><<<dim3(CDIM / BN, ROWS / 64), 128, GEMM_SMEM64>>>(hh, wproj_h, b_proj, x1,
                                                                  out, ROWS, CDIM, DFF);
}